// round 8
// baseline (speedup 1.0000x reference)
#include <cuda_runtime.h>
#include <cuda_bf16.h>
#include <cstdint>

#define B_ 4
#define N_ 2048
#define E_ 1024
#define H_ 16
#define D_ 64
#define SCALE_ 0.125f            // 1/sqrt(64)
#define SCALE_LOG2E 0.18033688f  // 0.125 * log2(e)
#define MTOT (B_ * N_)           // 8192

// ---------------------------------------------------------------------------
// Scratch (allocation-free rule: __device__ globals)
// ---------------------------------------------------------------------------
__device__ __nv_bfloat16 g_xqh[(size_t)MTOT * E_];
__device__ __nv_bfloat16 g_xql[(size_t)MTOT * E_];
__device__ __nv_bfloat16 g_xkh[(size_t)MTOT * E_];
__device__ __nv_bfloat16 g_xkl[(size_t)MTOT * E_];
__device__ __nv_bfloat16 g_xvh[(size_t)MTOT * E_];
__device__ __nv_bfloat16 g_xvl[(size_t)MTOT * E_];

__device__ __nv_bfloat16 g_Qh[(size_t)MTOT * E_];
__device__ __nv_bfloat16 g_Ql[(size_t)MTOT * E_];
__device__ __nv_bfloat16 g_Kh[(size_t)MTOT * E_];
__device__ __nv_bfloat16 g_Kl[(size_t)MTOT * E_];
__device__ __nv_bfloat16 g_Vh[(size_t)MTOT * E_];
__device__ __nv_bfloat16 g_Vl[(size_t)MTOT * E_];
__device__ __nv_bfloat16 g_Ah[(size_t)MTOT * E_];
__device__ __nv_bfloat16 g_Al[(size_t)MTOT * E_];

__device__ __nv_bfloat16 g_Wqh[(size_t)E_ * E_];
__device__ __nv_bfloat16 g_Wql[(size_t)E_ * E_];
__device__ __nv_bfloat16 g_Wkh[(size_t)E_ * E_];
__device__ __nv_bfloat16 g_Wkl[(size_t)E_ * E_];
__device__ __nv_bfloat16 g_Wvh[(size_t)E_ * E_];
__device__ __nv_bfloat16 g_Wvl[(size_t)E_ * E_];
__device__ __nv_bfloat16 g_Woh[(size_t)E_ * E_];
__device__ __nv_bfloat16 g_Wol[(size_t)E_ * E_];

// ---------------------------------------------------------------------------
// helpers
// ---------------------------------------------------------------------------
__device__ __forceinline__ uint32_t smem_u32(const void* p) {
    uint32_t a;
    asm("{ .reg .u64 t; cvta.to.shared.u64 t, %1; cvt.u32.u64 %0, t; }"
        : "=r"(a) : "l"(p));
    return a;
}
__device__ __forceinline__ void cp16(uint32_t sa, const void* ga) {
    asm volatile("cp.async.cg.shared.global [%0], [%1], 16;"
                 :: "r"(sa), "l"(ga));
}
__device__ __forceinline__ void cp_commit() {
    asm volatile("cp.async.commit_group;");
}
__device__ __forceinline__ void cp_wait1() {
    asm volatile("cp.async.wait_group 1;");
}
__device__ __forceinline__ void cp_wait0() {
    asm volatile("cp.async.wait_group 0;");
}
__device__ __forceinline__ void ldmx4(uint32_t& r0, uint32_t& r1,
                                      uint32_t& r2, uint32_t& r3, uint32_t a) {
    asm volatile("ldmatrix.sync.aligned.m8n8.x4.shared.b16 {%0,%1,%2,%3}, [%4];"
                 : "=r"(r0), "=r"(r1), "=r"(r2), "=r"(r3) : "r"(a));
}
__device__ __forceinline__ void ldmx4t(uint32_t& r0, uint32_t& r1,
                                       uint32_t& r2, uint32_t& r3, uint32_t a) {
    asm volatile("ldmatrix.sync.aligned.m8n8.x4.trans.shared.b16 {%0,%1,%2,%3}, [%4];"
                 : "=r"(r0), "=r"(r1), "=r"(r2), "=r"(r3) : "r"(a));
}
__device__ __forceinline__ void mma16816(float* d, const uint32_t* a,
                                         const uint32_t* b) {
    asm volatile(
        "mma.sync.aligned.m16n8k16.row.col.f32.bf16.bf16.f32 "
        "{%0,%1,%2,%3}, {%4,%5,%6,%7}, {%8,%9}, {%0,%1,%2,%3};"
        : "+f"(d[0]), "+f"(d[1]), "+f"(d[2]), "+f"(d[3])
        : "r"(a[0]), "r"(a[1]), "r"(a[2]), "r"(a[3]), "r"(b[0]), "r"(b[1]));
}
__device__ __forceinline__ void split2(float a, float b, uint32_t& hi, uint32_t& lo) {
    __nv_bfloat162 h = __floats2bfloat162_rn(a, b);
    __nv_bfloat162 l = __floats2bfloat162_rn(
        a - __bfloat162float(h.x), b - __bfloat162float(h.y));
    hi = *(uint32_t*)&h;
    lo = *(uint32_t*)&l;
}

// ---------------------------------------------------------------------------
// Prepass: fp32 -> (hi, lo) bf16 split.
// ---------------------------------------------------------------------------
__global__ __launch_bounds__(256) void convert_split(
    const float* __restrict__ src, __nv_bfloat16* __restrict__ h,
    __nv_bfloat16* __restrict__ l, int n4)
{
    int i = blockIdx.x * 256 + threadIdx.x;
    if (i >= n4) return;
    float4 v = ((const float4*)src)[i];
    uint32_t h01, l01, h23, l23;
    split2(v.x, v.y, h01, l01);
    split2(v.z, v.w, h23, l23);
    ((uint2*)h)[i] = make_uint2(h01, h23);
    ((uint2*)l)[i] = make_uint2(l01, l23);
}

// ===========================================================================
// HMMA GEMM: C = (Xh+Xl) @ (Wh+Wl)^T, fp32 accum, 3 split products.
// CTA 128x128, BKC=32, 3-stage cp.async pipeline (single barrier per chunk).
// ===========================================================================
#define BM 128
#define BN 128
#define BKC 32
#define KTOT 1024
#define NCHUNK (KTOT / BKC)
#define LDT 40
#define TILE_B (128 * LDT * 2)
#define STAGE_B (4 * TILE_B)       // 40960
#define GSMEM_SZ (3 * STAGE_B)     // 122880

__device__ __forceinline__ uint32_t lm_addr(uint32_t base_b, int row0, int kseg0) {
    int L = threadIdx.x & 31;
    int mat = L >> 3;
    int r = (L & 7) + ((mat & 1) << 3);
    int ks = kseg0 + (mat >> 1);
    return base_b + (uint32_t)(row0 + r) * (LDT * 2) + ks * 16;
}

__global__ __launch_bounds__(256) void gemm_tc(
    const __nv_bfloat16* __restrict__ Xh, const __nv_bfloat16* __restrict__ Xl,
    const __nv_bfloat16* __restrict__ Wh, const __nv_bfloat16* __restrict__ Wl,
    const float* __restrict__ bias, float* __restrict__ Cf,
    __nv_bfloat16* __restrict__ Oh, __nv_bfloat16* __restrict__ Ol,
    float scale, int Nn)
{
    extern __shared__ char dynsm[];
    const uint32_t smb = smem_u32(dynsm);
    const int tid = threadIdx.x;
    const int bm = blockIdx.y * BM;
    const int bn = blockIdx.x * BN;
    const int w = tid >> 5;
    const int wm = w >> 2;
    const int wn = w & 3;

    const char* tb[4];
    tb[0] = (const char*)(Xh + (size_t)bm * KTOT);
    tb[1] = (const char*)(Xl + (size_t)bm * KTOT);
    tb[2] = (const char*)(Wh + (size_t)bn * KTOT);
    tb[3] = (const char*)(Wl + (size_t)bn * KTOT);

    float acc[4][4][4];
#pragma unroll
    for (int i = 0; i < 4; i++)
#pragma unroll
        for (int j = 0; j < 4; j++)
#pragma unroll
            for (int t = 0; t < 4; t++) acc[i][j][t] = 0.f;

    auto issue = [&](int c, int s) {
#pragma unroll
        for (int i = 0; i < 8; i++) {
            int sid = tid + 256 * i;
            int tile = sid >> 9;
            int r = (sid >> 2) & 127;
            int seg = sid & 3;
            const char* base = (tile == 0) ? tb[0] : (tile == 1) ? tb[1]
                             : (tile == 2) ? tb[2] : tb[3];
            uint32_t sa = smb + (uint32_t)s * STAGE_B + (uint32_t)tile * TILE_B
                        + (uint32_t)r * (LDT * 2) + seg * 16;
            const char* ga = base + (size_t)r * (KTOT * 2) + c * (BKC * 2) + seg * 16;
            cp16(sa, ga);
        }
        cp_commit();
    };

    issue(0, 0);
    issue(1, 1);

    for (int c = 0; c < NCHUNK; c++) {
        if (c + 1 < NCHUNK) cp_wait1(); else cp_wait0();
        __syncthreads();
        // safe: barrier above proves all warps finished reading stage (c+2)%3
        if (c + 2 < NCHUNK) issue(c + 2, (c + 2) % 3);

        const uint32_t bXh = smb + (uint32_t)(c % 3) * STAGE_B;
        const uint32_t bXl = bXh + TILE_B;
        const uint32_t bWh = bXh + 2 * TILE_B;
        const uint32_t bWl = bXh + 3 * TILE_B;

#pragma unroll
        for (int ks = 0; ks < 2; ks++) {
            const int kseg0 = ks * 2;
            uint32_t ah[4][4], al[4][4], bh[4][2], bl[4][2];
#pragma unroll
            for (int mt = 0; mt < 4; mt++) {
                ldmx4(ah[mt][0], ah[mt][1], ah[mt][2], ah[mt][3],
                      lm_addr(bXh, wm * 64 + mt * 16, kseg0));
                ldmx4(al[mt][0], al[mt][1], al[mt][2], al[mt][3],
                      lm_addr(bXl, wm * 64 + mt * 16, kseg0));
            }
#pragma unroll
            for (int np = 0; np < 2; np++) {
                uint32_t r0, r1, r2, r3;
                ldmx4(r0, r1, r2, r3, lm_addr(bWh, wn * 32 + np * 16, kseg0));
                bh[np * 2 + 0][0] = r0; bh[np * 2 + 0][1] = r2;
                bh[np * 2 + 1][0] = r1; bh[np * 2 + 1][1] = r3;
                ldmx4(r0, r1, r2, r3, lm_addr(bWl, wn * 32 + np * 16, kseg0));
                bl[np * 2 + 0][0] = r0; bl[np * 2 + 0][1] = r2;
                bl[np * 2 + 1][0] = r1; bl[np * 2 + 1][1] = r3;
            }
#pragma unroll
            for (int mt = 0; mt < 4; mt++)
#pragma unroll
                for (int nt = 0; nt < 4; nt++) {
                    mma16816(acc[mt][nt], ah[mt], bh[nt]);
                    mma16816(acc[mt][nt], ah[mt], bl[nt]);
                    mma16816(acc[mt][nt], al[mt], bh[nt]);
                }
        }
    }

    const int lid = tid & 31;
    const int grp = lid >> 2;
    const int tig = lid & 3;
#pragma unroll
    for (int mt = 0; mt < 4; mt++) {
#pragma unroll
        for (int nt = 0; nt < 4; nt++) {
            int row = bm + wm * 64 + mt * 16 + grp;
            int col = bn + wn * 32 + nt * 8 + tig * 2;
            float a0 = acc[mt][nt][0] * scale, a1 = acc[mt][nt][1] * scale;
            float a2 = acc[mt][nt][2] * scale, a3 = acc[mt][nt][3] * scale;
            if (Cf != nullptr) {
                if (bias != nullptr) {
                    float b0 = bias[col], b1 = bias[col + 1];
                    a0 += b0; a1 += b1; a2 += b0; a3 += b1;
                }
                *(float2*)(Cf + (size_t)row * Nn + col) = make_float2(a0, a1);
                *(float2*)(Cf + (size_t)(row + 8) * Nn + col) = make_float2(a2, a3);
            } else {
                uint32_t hi, lo;
                split2(a0, a1, hi, lo);
                *(uint32_t*)(Oh + (size_t)row * Nn + col) = hi;
                *(uint32_t*)(Ol + (size_t)row * Nn + col) = lo;
                split2(a2, a3, hi, lo);
                *(uint32_t*)(Oh + (size_t)(row + 8) * Nn + col) = hi;
                *(uint32_t*)(Ol + (size_t)(row + 8) * Nn + col) = lo;
            }
        }
    }
}

// ===========================================================================
// Tensor-core causal flash attention, bf16 hi/lo, q-tile 128 rows (8 warps).
// K/V tiles (64 rows) double-buffered; exp2 softmax (log2e folded into Q).
// ===========================================================================
#define ALDT 144                   // smem row stride bytes
#define AQ_TILE (128 * ALDT)       // 18432
#define AKV_TILE (64 * ALDT)       // 9216
#define AOFF_QH 0
#define AOFF_QL AQ_TILE
#define AOFF_ST (2 * AQ_TILE)      // 36864
#define ASTAGE (4 * AKV_TILE)      // 36864
#define ASMEM (AOFF_ST + 2 * ASTAGE)  // 110592

__device__ __forceinline__ uint32_t lda(uint32_t base, int r0, int c0) {
    int L = threadIdx.x & 31;
    int mat = L >> 3;
    int r = r0 + (L & 7) + ((mat & 1) << 3);
    int c = c0 + ((mat >> 1) << 3);
    return base + (uint32_t)r * ALDT + c * 2;
}

__global__ __launch_bounds__(256) void attn_mma(
    const __nv_bfloat16* __restrict__ Qh, const __nv_bfloat16* __restrict__ Ql,
    const __nv_bfloat16* __restrict__ Kh, const __nv_bfloat16* __restrict__ Kl,
    const __nv_bfloat16* __restrict__ Vh, const __nv_bfloat16* __restrict__ Vl,
    __nv_bfloat16* __restrict__ Oh, __nv_bfloat16* __restrict__ Ol)
{
    extern __shared__ char dynsm[];
    const uint32_t smb = smem_u32(dynsm);
    const int tid = threadIdx.x;
    const int w = tid >> 5;
    const int lid = tid & 31;
    const int grp = lid >> 2;
    const int tig = lid & 3;
    const int iblk = (gridDim.x - 1) - blockIdx.x;   // heavy blocks first
    const int h = blockIdx.y;
    const int b = blockIdx.z;
    const int qbase = iblk * 128;
    const int jmax = 2 * iblk + 1;
    const size_t bN = (size_t)b * N_;

    auto issue_stage = [&](int s, int kbase) {
#pragma unroll
        for (int i = 0; i < 8; i++) {
            int sid = tid + 256 * i;          // 0..2047
            int tile = sid >> 9;              // 0 Kh,1 Kl,2 Vh,3 Vl
            int r = (sid >> 3) & 63;
            int seg = sid & 7;
            const __nv_bfloat16* gp = (tile == 0) ? Kh : (tile == 1) ? Kl
                                    : (tile == 2) ? Vh : Vl;
            const char* ga = (const char*)(gp + (bN + kbase + r) * E_ + h * 64)
                           + seg * 16;
            cp16(smb + AOFF_ST + (uint32_t)s * ASTAGE + (uint32_t)tile * AKV_TILE
                 + (uint32_t)r * ALDT + seg * 16, ga);
        }
        cp_commit();
    };

    // prologue: Q tiles (128 rows x 64 cols, hi+lo) + KV stage 0, one group
    {
#pragma unroll
        for (int i = 0; i < 8; i++) {
            int sid = tid + 256 * i;          // 0..2047
            int tile = sid >> 10;             // 0 Qh, 1 Ql
            int r = (sid >> 3) & 127;
            int seg = sid & 7;
            const __nv_bfloat16* gp = tile ? Ql : Qh;
            const char* ga = (const char*)(gp + (bN + qbase + r) * E_ + h * 64)
                           + seg * 16;
            cp16(smb + (tile ? AOFF_QL : AOFF_QH) + (uint32_t)r * ALDT + seg * 16, ga);
        }
    }
    issue_stage(0, 0);

    uint32_t qh[4][4], ql[4][4];
    float o[8][4];
#pragma unroll
    for (int t = 0; t < 8; t++)
#pragma unroll
        for (int c = 0; c < 4; c++) o[t][c] = 0.f;
    float mr0 = -1e30f, mr1 = -1e30f, lr0 = 0.f, lr1 = 0.f;

    for (int j = 0; j <= jmax; j++) {
        cp_wait0();
        __syncthreads();
        if (j == 0) {
#pragma unroll
            for (int kc = 0; kc < 4; kc++) {
                ldmx4(qh[kc][0], qh[kc][1], qh[kc][2], qh[kc][3],
                      lda(smb + AOFF_QH, w * 16, kc * 16));
                ldmx4(ql[kc][0], ql[kc][1], ql[kc][2], ql[kc][3],
                      lda(smb + AOFF_QL, w * 16, kc * 16));
            }
        }
        if (j < jmax) issue_stage((j + 1) & 1, (j + 1) * 64);

        const uint32_t bKH = smb + AOFF_ST + (uint32_t)(j & 1) * ASTAGE;
        const uint32_t bKL = bKH + AKV_TILE;
        const uint32_t bVH = bKH + 2 * AKV_TILE;
        const uint32_t bVL = bKH + 3 * AKV_TILE;

        // ---- S = Q K^T (3 split products); scale*log2e folded into Q ----
        float s[8][4];
#pragma unroll
        for (int t = 0; t < 8; t++)
#pragma unroll
            for (int c = 0; c < 4; c++) s[t][c] = 0.f;
#pragma unroll
        for (int kc = 0; kc < 4; kc++) {
#pragma unroll
            for (int np = 0; np < 4; np++) {
                uint32_t r0, r1, r2, r3, t0, t1, t2, t3;
                ldmx4(r0, r1, r2, r3, lda(bKH, np * 16, kc * 16));
                ldmx4(t0, t1, t2, t3, lda(bKL, np * 16, kc * 16));
                uint32_t bh0[2] = {r0, r2}, bh1[2] = {r1, r3};
                uint32_t bl0[2] = {t0, t2}, bl1[2] = {t1, t3};
                mma16816(s[np * 2 + 0], qh[kc], bh0);
                mma16816(s[np * 2 + 0], qh[kc], bl0);
                mma16816(s[np * 2 + 0], ql[kc], bh0);
                mma16816(s[np * 2 + 1], qh[kc], bh1);
                mma16816(s[np * 2 + 1], qh[kc], bl1);
                mma16816(s[np * 2 + 1], ql[kc], bh1);
            }
        }

        // ---- causal mask (only the last two kv-blocks can cross diag) ----
        if (j >= 2 * iblk) {
            const int row0 = qbase + w * 16 + grp;
            const int row1 = row0 + 8;
            const int cb = j * 64;
#pragma unroll
            for (int t = 0; t < 8; t++) {
                int col = cb + t * 8 + 2 * tig;
                if (col > row0) s[t][0] = -1e30f;
                if (col + 1 > row0) s[t][1] = -1e30f;
                if (col > row1) s[t][2] = -1e30f;
                if (col + 1 > row1) s[t][3] = -1e30f;
            }
        }

        // ---- online softmax (base-2) ----
        float m0 = -1e30f, m1 = -1e30f;
#pragma unroll
        for (int t = 0; t < 8; t++) {
            m0 = fmaxf(m0, fmaxf(s[t][0], s[t][1]));
            m1 = fmaxf(m1, fmaxf(s[t][2], s[t][3]));
        }
        m0 = fmaxf(m0, __shfl_xor_sync(0xffffffffu, m0, 1));
        m0 = fmaxf(m0, __shfl_xor_sync(0xffffffffu, m0, 2));
        m1 = fmaxf(m1, __shfl_xor_sync(0xffffffffu, m1, 1));
        m1 = fmaxf(m1, __shfl_xor_sync(0xffffffffu, m1, 2));
        float mn0 = fmaxf(mr0, m0), mn1 = fmaxf(mr1, m1);
        float a0 = exp2f(mr0 - mn0), a1 = exp2f(mr1 - mn1);
        mr0 = mn0; mr1 = mn1;
        float sum0 = 0.f, sum1 = 0.f;
#pragma unroll
        for (int t = 0; t < 8; t++) {
            s[t][0] = exp2f(s[t][0] - mn0);
            s[t][1] = exp2f(s[t][1] - mn0);
            s[t][2] = exp2f(s[t][2] - mn1);
            s[t][3] = exp2f(s[t][3] - mn1);
            sum0 += s[t][0] + s[t][1];
            sum1 += s[t][2] + s[t][3];
        }
        sum0 += __shfl_xor_sync(0xffffffffu, sum0, 1);
        sum0 += __shfl_xor_sync(0xffffffffu, sum0, 2);
        sum1 += __shfl_xor_sync(0xffffffffu, sum1, 1);
        sum1 += __shfl_xor_sync(0xffffffffu, sum1, 2);
        lr0 = lr0 * a0 + sum0;
        lr1 = lr1 * a1 + sum1;
#pragma unroll
        for (int t = 0; t < 8; t++) {
            o[t][0] *= a0; o[t][1] *= a0;
            o[t][2] *= a1; o[t][3] *= a1;
        }

        // ---- P: C-frag -> A-frag, hi/lo split ----
        uint32_t ph[4][4], pl[4][4];
#pragma unroll
        for (int kc = 0; kc < 4; kc++) {
            split2(s[2 * kc][0], s[2 * kc][1], ph[kc][0], pl[kc][0]);
            split2(s[2 * kc][2], s[2 * kc][3], ph[kc][1], pl[kc][1]);
            split2(s[2 * kc + 1][0], s[2 * kc + 1][1], ph[kc][2], pl[kc][2]);
            split2(s[2 * kc + 1][2], s[2 * kc + 1][3], ph[kc][3], pl[kc][3]);
        }

        // ---- O += P V (3 split products), V via ldmatrix.trans ----
#pragma unroll
        for (int kc = 0; kc < 4; kc++) {
#pragma unroll
            for (int nd = 0; nd < 4; nd++) {
                uint32_t r0, r1, r2, r3, t0, t1, t2, t3;
                ldmx4t(r0, r1, r2, r3, lda(bVH, kc * 16, nd * 16));
                ldmx4t(t0, t1, t2, t3, lda(bVL, kc * 16, nd * 16));
                uint32_t vh0[2] = {r0, r1}, vh1[2] = {r2, r3};
                uint32_t vl0[2] = {t0, t1}, vl1[2] = {t2, t3};
                mma16816(o[nd * 2 + 0], ph[kc], vh0);
                mma16816(o[nd * 2 + 0], ph[kc], vl0);
                mma16816(o[nd * 2 + 0], pl[kc], vh0);
                mma16816(o[nd * 2 + 1], ph[kc], vh1);
                mma16816(o[nd * 2 + 1], ph[kc], vl1);
                mma16816(o[nd * 2 + 1], pl[kc], vh1);
            }
        }
    }

    // ---- epilogue: normalize, hi/lo split, store [B,N,E] ----
    const float i0 = 1.f / lr0, i1 = 1.f / lr1;
    const int qr0 = qbase + w * 16 + grp;
    const size_t ro0 = (bN + qr0) * E_;
    const size_t ro1 = (bN + qr0 + 8) * E_;
#pragma unroll
    for (int t = 0; t < 8; t++) {
        int col = h * 64 + t * 8 + 2 * tig;
        uint32_t hi, lo;
        split2(o[t][0] * i0, o[t][1] * i0, hi, lo);
        *(uint32_t*)(Oh + ro0 + col) = hi;
        *(uint32_t*)(Ol + ro0 + col) = lo;
        split2(o[t][2] * i1, o[t][3] * i1, hi, lo);
        *(uint32_t*)(Oh + ro1 + col) = hi;
        *(uint32_t*)(Ol + ro1 + col) = lo;
    }
}

// ---------------------------------------------------------------------------
extern "C" void kernel_launch(void* const* d_in, const int* in_sizes, int n_in,
                              void* d_out, int out_size)
{
    const float* xq = (const float*)d_in[0];
    const float* xk = (const float*)d_in[1];
    const float* xv = (const float*)d_in[2];
    // d_in[3] = attn_mask (causal, recomputed analytically) — unused
    const float* Wq = (const float*)d_in[4];
    const float* Wk = (const float*)d_in[5];
    const float* Wv = (const float*)d_in[6];
    const float* Wo = (const float*)d_in[7];
    const float* bo = (const float*)d_in[8];
    float* out = (float*)d_out;

    __nv_bfloat16 *xqh, *xql, *xkh, *xkl, *xvh, *xvl;
    __nv_bfloat16 *Qh, *Ql, *Kh, *Kl, *Vh, *Vl, *Ah, *Al;
    __nv_bfloat16 *Wqh, *Wql, *Wkh, *Wkl, *Wvh, *Wvl, *Woh, *Wol;
    cudaGetSymbolAddress((void**)&xqh, g_xqh);
    cudaGetSymbolAddress((void**)&xql, g_xql);
    cudaGetSymbolAddress((void**)&xkh, g_xkh);
    cudaGetSymbolAddress((void**)&xkl, g_xkl);
    cudaGetSymbolAddress((void**)&xvh, g_xvh);
    cudaGetSymbolAddress((void**)&xvl, g_xvl);
    cudaGetSymbolAddress((void**)&Qh, g_Qh);
    cudaGetSymbolAddress((void**)&Ql, g_Ql);
    cudaGetSymbolAddress((void**)&Kh, g_Kh);
    cudaGetSymbolAddress((void**)&Kl, g_Kl);
    cudaGetSymbolAddress((void**)&Vh, g_Vh);
    cudaGetSymbolAddress((void**)&Vl, g_Vl);
    cudaGetSymbolAddress((void**)&Ah, g_Ah);
    cudaGetSymbolAddress((void**)&Al, g_Al);
    cudaGetSymbolAddress((void**)&Wqh, g_Wqh);
    cudaGetSymbolAddress((void**)&Wql, g_Wql);
    cudaGetSymbolAddress((void**)&Wkh, g_Wkh);
    cudaGetSymbolAddress((void**)&Wkl, g_Wkl);
    cudaGetSymbolAddress((void**)&Wvh, g_Wvh);
    cudaGetSymbolAddress((void**)&Wvl, g_Wvl);
    cudaGetSymbolAddress((void**)&Woh, g_Woh);
    cudaGetSymbolAddress((void**)&Wol, g_Wol);

    cudaFuncSetAttribute(gemm_tc, cudaFuncAttributeMaxDynamicSharedMemorySize,
                         GSMEM_SZ);
    cudaFuncSetAttribute(attn_mma, cudaFuncAttributeMaxDynamicSharedMemorySize,
                         ASMEM);

    // Prepass conversions
    const int nx4 = MTOT * E_ / 4;
    const int nw4 = E_ * E_ / 4;
    convert_split<<<nx4 / 256, 256>>>(xq, xqh, xql, nx4);
    convert_split<<<nx4 / 256, 256>>>(xk, xkh, xkl, nx4);
    convert_split<<<nx4 / 256, 256>>>(xv, xvh, xvl, nx4);
    convert_split<<<nw4 / 256, 256>>>(Wq, Wqh, Wql, nw4);
    convert_split<<<nw4 / 256, 256>>>(Wk, Wkh, Wkl, nw4);
    convert_split<<<nw4 / 256, 256>>>(Wv, Wvh, Wvl, nw4);
    convert_split<<<nw4 / 256, 256>>>(Wo, Woh, Wol, nw4);

    dim3 gblock(256);
    dim3 ggrid(E_ / BN, MTOT / BM);        // (8, 64)

    // Projections -> bf16 hi/lo (Q pre-scaled by log2e/sqrt(D))
    gemm_tc<<<ggrid, gblock, GSMEM_SZ>>>(xqh, xql, Wqh, Wql, nullptr, nullptr,
                                         Qh, Ql, SCALE_LOG2E, E_);
    gemm_tc<<<ggrid, gblock, GSMEM_SZ>>>(xkh, xkl, Wkh, Wkl, nullptr, nullptr,
                                         Kh, Kl, 1.0f, E_);
    gemm_tc<<<ggrid, gblock, GSMEM_SZ>>>(xvh, xvl, Wvh, Wvl, nullptr, nullptr,
                                         Vh, Vl, 1.0f, E_);

    dim3 agrid(N_ / 128, H_, B_);          // (16, 16, 4)
    attn_mma<<<agrid, 256, ASMEM>>>(Qh, Ql, Kh, Kl, Vh, Vl, Ah, Al);

    // Output projection -> fp32 + bias
    gemm_tc<<<ggrid, gblock, GSMEM_SZ>>>(Ah, Al, Woh, Wol, bo, out,
                                         nullptr, nullptr, 1.0f, E_);
}

// round 9
// speedup vs baseline: 1.0921x; 1.0921x over previous
#include <cuda_runtime.h>
#include <cuda_bf16.h>
#include <cstdint>

#define B_ 4
#define N_ 2048
#define E_ 1024
#define H_ 16
#define D_ 64
#define SCALE_ 0.125f            // 1/sqrt(64)
#define SCALE_LOG2E 0.18033688f  // 0.125 * log2(e)
#define MTOT (B_ * N_)           // 8192

// ---------------------------------------------------------------------------
// Scratch (allocation-free rule: __device__ globals)
// ---------------------------------------------------------------------------
__device__ __nv_bfloat16 g_xqh[(size_t)MTOT * E_];
__device__ __nv_bfloat16 g_xql[(size_t)MTOT * E_];
__device__ __nv_bfloat16 g_xkh[(size_t)MTOT * E_];
__device__ __nv_bfloat16 g_xkl[(size_t)MTOT * E_];
__device__ __nv_bfloat16 g_xvh[(size_t)MTOT * E_];
__device__ __nv_bfloat16 g_xvl[(size_t)MTOT * E_];

__device__ __nv_bfloat16 g_Qh[(size_t)MTOT * E_];
__device__ __nv_bfloat16 g_Ql[(size_t)MTOT * E_];
__device__ __nv_bfloat16 g_Kh[(size_t)MTOT * E_];
__device__ __nv_bfloat16 g_Kl[(size_t)MTOT * E_];
__device__ __nv_bfloat16 g_Vh[(size_t)MTOT * E_];
__device__ __nv_bfloat16 g_Vl[(size_t)MTOT * E_];
__device__ __nv_bfloat16 g_Ah[(size_t)MTOT * E_];
__device__ __nv_bfloat16 g_Al[(size_t)MTOT * E_];

__device__ __nv_bfloat16 g_Wqh[(size_t)E_ * E_];
__device__ __nv_bfloat16 g_Wql[(size_t)E_ * E_];
__device__ __nv_bfloat16 g_Wkh[(size_t)E_ * E_];
__device__ __nv_bfloat16 g_Wkl[(size_t)E_ * E_];
__device__ __nv_bfloat16 g_Wvh[(size_t)E_ * E_];
__device__ __nv_bfloat16 g_Wvl[(size_t)E_ * E_];
__device__ __nv_bfloat16 g_Woh[(size_t)E_ * E_];
__device__ __nv_bfloat16 g_Wol[(size_t)E_ * E_];

// ---------------------------------------------------------------------------
// helpers
// ---------------------------------------------------------------------------
__device__ __forceinline__ uint32_t smem_u32(const void* p) {
    uint32_t a;
    asm("{ .reg .u64 t; cvta.to.shared.u64 t, %1; cvt.u32.u64 %0, t; }"
        : "=r"(a) : "l"(p));
    return a;
}
__device__ __forceinline__ void cp16(uint32_t sa, const void* ga) {
    asm volatile("cp.async.cg.shared.global [%0], [%1], 16;"
                 :: "r"(sa), "l"(ga));
}
__device__ __forceinline__ void cp_commit() {
    asm volatile("cp.async.commit_group;");
}
__device__ __forceinline__ void cp_wait1() {
    asm volatile("cp.async.wait_group 1;");
}
__device__ __forceinline__ void cp_wait0() {
    asm volatile("cp.async.wait_group 0;");
}
__device__ __forceinline__ void ldmx4(uint32_t& r0, uint32_t& r1,
                                      uint32_t& r2, uint32_t& r3, uint32_t a) {
    asm volatile("ldmatrix.sync.aligned.m8n8.x4.shared.b16 {%0,%1,%2,%3}, [%4];"
                 : "=r"(r0), "=r"(r1), "=r"(r2), "=r"(r3) : "r"(a));
}
__device__ __forceinline__ void ldmx4t(uint32_t& r0, uint32_t& r1,
                                       uint32_t& r2, uint32_t& r3, uint32_t a) {
    asm volatile("ldmatrix.sync.aligned.m8n8.x4.trans.shared.b16 {%0,%1,%2,%3}, [%4];"
                 : "=r"(r0), "=r"(r1), "=r"(r2), "=r"(r3) : "r"(a));
}
__device__ __forceinline__ void mma16816(float* d, const uint32_t* a,
                                         const uint32_t* b) {
    asm volatile(
        "mma.sync.aligned.m16n8k16.row.col.f32.bf16.bf16.f32 "
        "{%0,%1,%2,%3}, {%4,%5,%6,%7}, {%8,%9}, {%0,%1,%2,%3};"
        : "+f"(d[0]), "+f"(d[1]), "+f"(d[2]), "+f"(d[3])
        : "r"(a[0]), "r"(a[1]), "r"(a[2]), "r"(a[3]), "r"(b[0]), "r"(b[1]));
}
__device__ __forceinline__ void split2(float a, float b, uint32_t& hi, uint32_t& lo) {
    __nv_bfloat162 h = __floats2bfloat162_rn(a, b);
    __nv_bfloat162 l = __floats2bfloat162_rn(
        a - __bfloat162float(h.x), b - __bfloat162float(h.y));
    hi = *(uint32_t*)&h;
    lo = *(uint32_t*)&l;
}

// ---------------------------------------------------------------------------
// Prepass: fp32 -> (hi, lo) bf16 split.
// ---------------------------------------------------------------------------
__global__ __launch_bounds__(256) void convert_split(
    const float* __restrict__ src, __nv_bfloat16* __restrict__ h,
    __nv_bfloat16* __restrict__ l, int n4)
{
    int i = blockIdx.x * 256 + threadIdx.x;
    if (i >= n4) return;
    float4 v = ((const float4*)src)[i];
    uint32_t h01, l01, h23, l23;
    split2(v.x, v.y, h01, l01);
    split2(v.z, v.w, h23, l23);
    ((uint2*)h)[i] = make_uint2(h01, h23);
    ((uint2*)l)[i] = make_uint2(l01, l23);
}

// ===========================================================================
// HMMA GEMM: C = (Xh+Xl) @ (Wh+Wl)^T, fp32 accum, 3 split products.
// CTA 128x128, BKC=32, 2-stage cp.async pipeline (80KB smem -> 2 CTAs/SM).
// ===========================================================================
#define BM 128
#define BN 128
#define BKC 32
#define KTOT 1024
#define NCHUNK (KTOT / BKC)
#define LDT 40
#define TILE_B (128 * LDT * 2)
#define STAGE_B (4 * TILE_B)       // 40960
#define GSMEM_SZ (2 * STAGE_B)     // 81920 -> 2 CTAs/SM

__device__ __forceinline__ uint32_t lm_addr(uint32_t base_b, int row0, int kseg0) {
    int L = threadIdx.x & 31;
    int mat = L >> 3;
    int r = (L & 7) + ((mat & 1) << 3);
    int ks = kseg0 + (mat >> 1);
    return base_b + (uint32_t)(row0 + r) * (LDT * 2) + ks * 16;
}

__global__ __launch_bounds__(256) void gemm_tc(
    const __nv_bfloat16* __restrict__ Xh, const __nv_bfloat16* __restrict__ Xl,
    const __nv_bfloat16* __restrict__ Wh, const __nv_bfloat16* __restrict__ Wl,
    const float* __restrict__ bias, float* __restrict__ Cf,
    __nv_bfloat16* __restrict__ Oh, __nv_bfloat16* __restrict__ Ol,
    float scale, int Nn)
{
    extern __shared__ char dynsm[];
    const uint32_t smb = smem_u32(dynsm);
    const int tid = threadIdx.x;
    const int bm = blockIdx.y * BM;
    const int bn = blockIdx.x * BN;
    const int w = tid >> 5;
    const int wm = w >> 2;
    const int wn = w & 3;

    const char* tb[4];
    tb[0] = (const char*)(Xh + (size_t)bm * KTOT);
    tb[1] = (const char*)(Xl + (size_t)bm * KTOT);
    tb[2] = (const char*)(Wh + (size_t)bn * KTOT);
    tb[3] = (const char*)(Wl + (size_t)bn * KTOT);

    float acc[4][4][4];
#pragma unroll
    for (int i = 0; i < 4; i++)
#pragma unroll
        for (int j = 0; j < 4; j++)
#pragma unroll
            for (int t = 0; t < 4; t++) acc[i][j][t] = 0.f;

    auto issue = [&](int c, int s) {
#pragma unroll
        for (int i = 0; i < 8; i++) {
            int sid = tid + 256 * i;
            int tile = sid >> 9;
            int r = (sid >> 2) & 127;
            int seg = sid & 3;
            const char* base = (tile == 0) ? tb[0] : (tile == 1) ? tb[1]
                             : (tile == 2) ? tb[2] : tb[3];
            uint32_t sa = smb + (uint32_t)s * STAGE_B + (uint32_t)tile * TILE_B
                        + (uint32_t)r * (LDT * 2) + seg * 16;
            const char* ga = base + (size_t)r * (KTOT * 2) + c * (BKC * 2) + seg * 16;
            cp16(sa, ga);
        }
        cp_commit();
    };

    issue(0, 0);

    for (int c = 0; c < NCHUNK; c++) {
        const int st = c & 1;
        if (c + 1 < NCHUNK) {
            issue(c + 1, st ^ 1);
            cp_wait1();
        } else {
            cp_wait0();
        }
        __syncthreads();

        const uint32_t bXh = smb + (uint32_t)st * STAGE_B;
        const uint32_t bXl = bXh + TILE_B;
        const uint32_t bWh = bXh + 2 * TILE_B;
        const uint32_t bWl = bXh + 3 * TILE_B;

#pragma unroll
        for (int ks = 0; ks < 2; ks++) {
            const int kseg0 = ks * 2;
            uint32_t ah[4][4], al[4][4], bh[4][2], bl[4][2];
#pragma unroll
            for (int mt = 0; mt < 4; mt++) {
                ldmx4(ah[mt][0], ah[mt][1], ah[mt][2], ah[mt][3],
                      lm_addr(bXh, wm * 64 + mt * 16, kseg0));
                ldmx4(al[mt][0], al[mt][1], al[mt][2], al[mt][3],
                      lm_addr(bXl, wm * 64 + mt * 16, kseg0));
            }
#pragma unroll
            for (int np = 0; np < 2; np++) {
                uint32_t r0, r1, r2, r3;
                ldmx4(r0, r1, r2, r3, lm_addr(bWh, wn * 32 + np * 16, kseg0));
                bh[np * 2 + 0][0] = r0; bh[np * 2 + 0][1] = r2;
                bh[np * 2 + 1][0] = r1; bh[np * 2 + 1][1] = r3;
                ldmx4(r0, r1, r2, r3, lm_addr(bWl, wn * 32 + np * 16, kseg0));
                bl[np * 2 + 0][0] = r0; bl[np * 2 + 0][1] = r2;
                bl[np * 2 + 1][0] = r1; bl[np * 2 + 1][1] = r3;
            }
#pragma unroll
            for (int mt = 0; mt < 4; mt++)
#pragma unroll
                for (int nt = 0; nt < 4; nt++) {
                    mma16816(acc[mt][nt], ah[mt], bh[nt]);
                    mma16816(acc[mt][nt], ah[mt], bl[nt]);
                    mma16816(acc[mt][nt], al[mt], bh[nt]);
                }
        }
        __syncthreads();
    }

    const int lid = tid & 31;
    const int grp = lid >> 2;
    const int tig = lid & 3;
#pragma unroll
    for (int mt = 0; mt < 4; mt++) {
#pragma unroll
        for (int nt = 0; nt < 4; nt++) {
            int row = bm + wm * 64 + mt * 16 + grp;
            int col = bn + wn * 32 + nt * 8 + tig * 2;
            float a0 = acc[mt][nt][0] * scale, a1 = acc[mt][nt][1] * scale;
            float a2 = acc[mt][nt][2] * scale, a3 = acc[mt][nt][3] * scale;
            if (Cf != nullptr) {
                if (bias != nullptr) {
                    float b0 = bias[col], b1 = bias[col + 1];
                    a0 += b0; a1 += b1; a2 += b0; a3 += b1;
                }
                *(float2*)(Cf + (size_t)row * Nn + col) = make_float2(a0, a1);
                *(float2*)(Cf + (size_t)(row + 8) * Nn + col) = make_float2(a2, a3);
            } else {
                uint32_t hi, lo;
                split2(a0, a1, hi, lo);
                *(uint32_t*)(Oh + (size_t)row * Nn + col) = hi;
                *(uint32_t*)(Ol + (size_t)row * Nn + col) = lo;
                split2(a2, a3, hi, lo);
                *(uint32_t*)(Oh + (size_t)(row + 8) * Nn + col) = hi;
                *(uint32_t*)(Ol + (size_t)(row + 8) * Nn + col) = lo;
            }
        }
    }
}

// ===========================================================================
// Tensor-core causal flash attention, bf16 hi/lo, q-tile 128 rows (8 warps).
// K/V tiles (64 rows) double-buffered; exp2 softmax (log2e folded into Q).
// ===========================================================================
#define ALDT 144                   // smem row stride bytes
#define AQ_TILE (128 * ALDT)       // 18432
#define AKV_TILE (64 * ALDT)       // 9216
#define AOFF_QH 0
#define AOFF_QL AQ_TILE
#define AOFF_ST (2 * AQ_TILE)      // 36864
#define ASTAGE (4 * AKV_TILE)      // 36864
#define ASMEM (AOFF_ST + 2 * ASTAGE)  // 110592

__device__ __forceinline__ uint32_t lda(uint32_t base, int r0, int c0) {
    int L = threadIdx.x & 31;
    int mat = L >> 3;
    int r = r0 + (L & 7) + ((mat & 1) << 3);
    int c = c0 + ((mat >> 1) << 3);
    return base + (uint32_t)r * ALDT + c * 2;
}

__global__ __launch_bounds__(256) void attn_mma(
    const __nv_bfloat16* __restrict__ Qh, const __nv_bfloat16* __restrict__ Ql,
    const __nv_bfloat16* __restrict__ Kh, const __nv_bfloat16* __restrict__ Kl,
    const __nv_bfloat16* __restrict__ Vh, const __nv_bfloat16* __restrict__ Vl,
    __nv_bfloat16* __restrict__ Oh, __nv_bfloat16* __restrict__ Ol)
{
    extern __shared__ char dynsm[];
    const uint32_t smb = smem_u32(dynsm);
    const int tid = threadIdx.x;
    const int w = tid >> 5;
    const int lid = tid & 31;
    const int grp = lid >> 2;
    const int tig = lid & 3;
    const int iblk = (gridDim.x - 1) - blockIdx.x;   // heavy blocks first
    const int h = blockIdx.y;
    const int b = blockIdx.z;
    const int qbase = iblk * 128;
    const int jmax = 2 * iblk + 1;
    const size_t bN = (size_t)b * N_;

    auto issue_stage = [&](int s, int kbase) {
#pragma unroll
        for (int i = 0; i < 8; i++) {
            int sid = tid + 256 * i;          // 0..2047
            int tile = sid >> 9;              // 0 Kh,1 Kl,2 Vh,3 Vl
            int r = (sid >> 3) & 63;
            int seg = sid & 7;
            const __nv_bfloat16* gp = (tile == 0) ? Kh : (tile == 1) ? Kl
                                    : (tile == 2) ? Vh : Vl;
            const char* ga = (const char*)(gp + (bN + kbase + r) * E_ + h * 64)
                           + seg * 16;
            cp16(smb + AOFF_ST + (uint32_t)s * ASTAGE + (uint32_t)tile * AKV_TILE
                 + (uint32_t)r * ALDT + seg * 16, ga);
        }
        cp_commit();
    };

    // prologue: Q tiles (128 rows x 64 cols, hi+lo) + KV stage 0
    {
#pragma unroll
        for (int i = 0; i < 8; i++) {
            int sid = tid + 256 * i;          // 0..2047
            int tile = sid >> 10;             // 0 Qh, 1 Ql
            int r = (sid >> 3) & 127;
            int seg = sid & 7;
            const __nv_bfloat16* gp = tile ? Ql : Qh;
            const char* ga = (const char*)(gp + (bN + qbase + r) * E_ + h * 64)
                           + seg * 16;
            cp16(smb + (tile ? AOFF_QL : AOFF_QH) + (uint32_t)r * ALDT + seg * 16, ga);
        }
    }
    issue_stage(0, 0);

    uint32_t qh[4][4], ql[4][4];
    float o[8][4];
#pragma unroll
    for (int t = 0; t < 8; t++)
#pragma unroll
        for (int c = 0; c < 4; c++) o[t][c] = 0.f;
    float mr0 = -1e30f, mr1 = -1e30f, lr0 = 0.f, lr1 = 0.f;

    for (int j = 0; j <= jmax; j++) {
        cp_wait0();
        __syncthreads();
        if (j == 0) {
#pragma unroll
            for (int kc = 0; kc < 4; kc++) {
                ldmx4(qh[kc][0], qh[kc][1], qh[kc][2], qh[kc][3],
                      lda(smb + AOFF_QH, w * 16, kc * 16));
                ldmx4(ql[kc][0], ql[kc][1], ql[kc][2], ql[kc][3],
                      lda(smb + AOFF_QL, w * 16, kc * 16));
            }
        }
        if (j < jmax) issue_stage((j + 1) & 1, (j + 1) * 64);

        const uint32_t bKH = smb + AOFF_ST + (uint32_t)(j & 1) * ASTAGE;
        const uint32_t bKL = bKH + AKV_TILE;
        const uint32_t bVH = bKH + 2 * AKV_TILE;
        const uint32_t bVL = bKH + 3 * AKV_TILE;

        // ---- S = Q K^T (3 split products); scale*log2e folded into Q ----
        float s[8][4];
#pragma unroll
        for (int t = 0; t < 8; t++)
#pragma unroll
            for (int c = 0; c < 4; c++) s[t][c] = 0.f;
#pragma unroll
        for (int kc = 0; kc < 4; kc++) {
#pragma unroll
            for (int np = 0; np < 4; np++) {
                uint32_t r0, r1, r2, r3, t0, t1, t2, t3;
                ldmx4(r0, r1, r2, r3, lda(bKH, np * 16, kc * 16));
                ldmx4(t0, t1, t2, t3, lda(bKL, np * 16, kc * 16));
                uint32_t bh0[2] = {r0, r2}, bh1[2] = {r1, r3};
                uint32_t bl0[2] = {t0, t2}, bl1[2] = {t1, t3};
                mma16816(s[np * 2 + 0], qh[kc], bh0);
                mma16816(s[np * 2 + 0], qh[kc], bl0);
                mma16816(s[np * 2 + 0], ql[kc], bh0);
                mma16816(s[np * 2 + 1], qh[kc], bh1);
                mma16816(s[np * 2 + 1], qh[kc], bl1);
                mma16816(s[np * 2 + 1], ql[kc], bh1);
            }
        }

        // ---- causal mask (only kv-blocks crossing the diagonal) ----
        if (j >= 2 * iblk) {
            const int row0 = qbase + w * 16 + grp;
            const int row1 = row0 + 8;
            const int cb = j * 64;
#pragma unroll
            for (int t = 0; t < 8; t++) {
                int col = cb + t * 8 + 2 * tig;
                if (col > row0) s[t][0] = -1e30f;
                if (col + 1 > row0) s[t][1] = -1e30f;
                if (col > row1) s[t][2] = -1e30f;
                if (col + 1 > row1) s[t][3] = -1e30f;
            }
        }

        // ---- online softmax (base-2) ----
        float m0 = -1e30f, m1 = -1e30f;
#pragma unroll
        for (int t = 0; t < 8; t++) {
            m0 = fmaxf(m0, fmaxf(s[t][0], s[t][1]));
            m1 = fmaxf(m1, fmaxf(s[t][2], s[t][3]));
        }
        m0 = fmaxf(m0, __shfl_xor_sync(0xffffffffu, m0, 1));
        m0 = fmaxf(m0, __shfl_xor_sync(0xffffffffu, m0, 2));
        m1 = fmaxf(m1, __shfl_xor_sync(0xffffffffu, m1, 1));
        m1 = fmaxf(m1, __shfl_xor_sync(0xffffffffu, m1, 2));
        float mn0 = fmaxf(mr0, m0), mn1 = fmaxf(mr1, m1);
        float a0 = exp2f(mr0 - mn0), a1 = exp2f(mr1 - mn1);
        mr0 = mn0; mr1 = mn1;
        float sum0 = 0.f, sum1 = 0.f;
#pragma unroll
        for (int t = 0; t < 8; t++) {
            s[t][0] = exp2f(s[t][0] - mn0);
            s[t][1] = exp2f(s[t][1] - mn0);
            s[t][2] = exp2f(s[t][2] - mn1);
            s[t][3] = exp2f(s[t][3] - mn1);
            sum0 += s[t][0] + s[t][1];
            sum1 += s[t][2] + s[t][3];
        }
        sum0 += __shfl_xor_sync(0xffffffffu, sum0, 1);
        sum0 += __shfl_xor_sync(0xffffffffu, sum0, 2);
        sum1 += __shfl_xor_sync(0xffffffffu, sum1, 1);
        sum1 += __shfl_xor_sync(0xffffffffu, sum1, 2);
        lr0 = lr0 * a0 + sum0;
        lr1 = lr1 * a1 + sum1;
#pragma unroll
        for (int t = 0; t < 8; t++) {
            o[t][0] *= a0; o[t][1] *= a0;
            o[t][2] *= a1; o[t][3] *= a1;
        }

        // ---- P: C-frag -> A-frag, hi/lo split ----
        uint32_t ph[4][4], pl[4][4];
#pragma unroll
        for (int kc = 0; kc < 4; kc++) {
            split2(s[2 * kc][0], s[2 * kc][1], ph[kc][0], pl[kc][0]);
            split2(s[2 * kc][2], s[2 * kc][3], ph[kc][1], pl[kc][1]);
            split2(s[2 * kc + 1][0], s[2 * kc + 1][1], ph[kc][2], pl[kc][2]);
            split2(s[2 * kc + 1][2], s[2 * kc + 1][3], ph[kc][3], pl[kc][3]);
        }

        // ---- O += P V (3 split products), V via ldmatrix.trans ----
#pragma unroll
        for (int kc = 0; kc < 4; kc++) {
#pragma unroll
            for (int nd = 0; nd < 4; nd++) {
                uint32_t r0, r1, r2, r3, t0, t1, t2, t3;
                ldmx4t(r0, r1, r2, r3, lda(bVH, kc * 16, nd * 16));
                ldmx4t(t0, t1, t2, t3, lda(bVL, kc * 16, nd * 16));
                uint32_t vh0[2] = {r0, r1}, vh1[2] = {r2, r3};
                uint32_t vl0[2] = {t0, t1}, vl1[2] = {t2, t3};
                mma16816(o[nd * 2 + 0], ph[kc], vh0);
                mma16816(o[nd * 2 + 0], ph[kc], vl0);
                mma16816(o[nd * 2 + 0], pl[kc], vh0);
                mma16816(o[nd * 2 + 1], ph[kc], vh1);
                mma16816(o[nd * 2 + 1], ph[kc], vl1);
                mma16816(o[nd * 2 + 1], pl[kc], vh1);
            }
        }
    }

    // ---- epilogue: normalize, hi/lo split, store [B,N,E] ----
    const float i0 = 1.f / lr0, i1 = 1.f / lr1;
    const int qr0 = qbase + w * 16 + grp;
    const size_t ro0 = (bN + qr0) * E_;
    const size_t ro1 = (bN + qr0 + 8) * E_;
#pragma unroll
    for (int t = 0; t < 8; t++) {
        int col = h * 64 + t * 8 + 2 * tig;
        uint32_t hi, lo;
        split2(o[t][0] * i0, o[t][1] * i0, hi, lo);
        *(uint32_t*)(Oh + ro0 + col) = hi;
        *(uint32_t*)(Ol + ro0 + col) = lo;
        split2(o[t][2] * i1, o[t][3] * i1, hi, lo);
        *(uint32_t*)(Oh + ro1 + col) = hi;
        *(uint32_t*)(Ol + ro1 + col) = lo;
    }
}

// ---------------------------------------------------------------------------
extern "C" void kernel_launch(void* const* d_in, const int* in_sizes, int n_in,
                              void* d_out, int out_size)
{
    const float* xq = (const float*)d_in[0];
    const float* xk = (const float*)d_in[1];
    const float* xv = (const float*)d_in[2];
    // d_in[3] = attn_mask (causal, recomputed analytically) — unused
    const float* Wq = (const float*)d_in[4];
    const float* Wk = (const float*)d_in[5];
    const float* Wv = (const float*)d_in[6];
    const float* Wo = (const float*)d_in[7];
    const float* bo = (const float*)d_in[8];
    float* out = (float*)d_out;

    __nv_bfloat16 *xqh, *xql, *xkh, *xkl, *xvh, *xvl;
    __nv_bfloat16 *Qh, *Ql, *Kh, *Kl, *Vh, *Vl, *Ah, *Al;
    __nv_bfloat16 *Wqh, *Wql, *Wkh, *Wkl, *Wvh, *Wvl, *Woh, *Wol;
    cudaGetSymbolAddress((void**)&xqh, g_xqh);
    cudaGetSymbolAddress((void**)&xql, g_xql);
    cudaGetSymbolAddress((void**)&xkh, g_xkh);
    cudaGetSymbolAddress((void**)&xkl, g_xkl);
    cudaGetSymbolAddress((void**)&xvh, g_xvh);
    cudaGetSymbolAddress((void**)&xvl, g_xvl);
    cudaGetSymbolAddress((void**)&Qh, g_Qh);
    cudaGetSymbolAddress((void**)&Ql, g_Ql);
    cudaGetSymbolAddress((void**)&Kh, g_Kh);
    cudaGetSymbolAddress((void**)&Kl, g_Kl);
    cudaGetSymbolAddress((void**)&Vh, g_Vh);
    cudaGetSymbolAddress((void**)&Vl, g_Vl);
    cudaGetSymbolAddress((void**)&Ah, g_Ah);
    cudaGetSymbolAddress((void**)&Al, g_Al);
    cudaGetSymbolAddress((void**)&Wqh, g_Wqh);
    cudaGetSymbolAddress((void**)&Wql, g_Wql);
    cudaGetSymbolAddress((void**)&Wkh, g_Wkh);
    cudaGetSymbolAddress((void**)&Wkl, g_Wkl);
    cudaGetSymbolAddress((void**)&Wvh, g_Wvh);
    cudaGetSymbolAddress((void**)&Wvl, g_Wvl);
    cudaGetSymbolAddress((void**)&Woh, g_Woh);
    cudaGetSymbolAddress((void**)&Wol, g_Wol);

    cudaFuncSetAttribute(gemm_tc, cudaFuncAttributeMaxDynamicSharedMemorySize,
                         GSMEM_SZ);
    cudaFuncSetAttribute(attn_mma, cudaFuncAttributeMaxDynamicSharedMemorySize,
                         ASMEM);

    // Prepass conversions
    const int nx4 = MTOT * E_ / 4;
    const int nw4 = E_ * E_ / 4;
    convert_split<<<nx4 / 256, 256>>>(xq, xqh, xql, nx4);
    convert_split<<<nx4 / 256, 256>>>(xk, xkh, xkl, nx4);
    convert_split<<<nx4 / 256, 256>>>(xv, xvh, xvl, nx4);
    convert_split<<<nw4 / 256, 256>>>(Wq, Wqh, Wql, nw4);
    convert_split<<<nw4 / 256, 256>>>(Wk, Wkh, Wkl, nw4);
    convert_split<<<nw4 / 256, 256>>>(Wv, Wvh, Wvl, nw4);
    convert_split<<<nw4 / 256, 256>>>(Wo, Woh, Wol, nw4);

    dim3 gblock(256);
    dim3 ggrid(E_ / BN, MTOT / BM);        // (8, 64)

    // Projections -> bf16 hi/lo (Q pre-scaled by log2e/sqrt(D))
    gemm_tc<<<ggrid, gblock, GSMEM_SZ>>>(xqh, xql, Wqh, Wql, nullptr, nullptr,
                                         Qh, Ql, SCALE_LOG2E, E_);
    gemm_tc<<<ggrid, gblock, GSMEM_SZ>>>(xkh, xkl, Wkh, Wkl, nullptr, nullptr,
                                         Kh, Kl, 1.0f, E_);
    gemm_tc<<<ggrid, gblock, GSMEM_SZ>>>(xvh, xvl, Wvh, Wvl, nullptr, nullptr,
                                         Vh, Vl, 1.0f, E_);

    dim3 agrid(N_ / 128, H_, B_);          // (16, 16, 4)
    attn_mma<<<agrid, 256, ASMEM>>>(Qh, Ql, Kh, Kl, Vh, Vl, Ah, Al);

    // Output projection -> fp32 + bias
    gemm_tc<<<ggrid, gblock, GSMEM_SZ>>>(Ah, Al, Woh, Wol, bo, out,
                                         nullptr, nullptr, 1.0f, E_);
}

// round 10
// speedup vs baseline: 1.1236x; 1.0288x over previous
#include <cuda_runtime.h>
#include <cuda_bf16.h>
#include <cstdint>

#define B_ 4
#define N_ 2048
#define E_ 1024
#define H_ 16
#define D_ 64
#define SCALE_ 0.125f            // 1/sqrt(64)
#define SCALE_LOG2E 0.18033688f  // 0.125 * log2(e)
#define MTOT (B_ * N_)           // 8192

// ---------------------------------------------------------------------------
// Scratch (allocation-free rule: __device__ globals)
// ---------------------------------------------------------------------------
__device__ __nv_bfloat16 g_xqh[(size_t)MTOT * E_];
__device__ __nv_bfloat16 g_xql[(size_t)MTOT * E_];
__device__ __nv_bfloat16 g_xkh[(size_t)MTOT * E_];
__device__ __nv_bfloat16 g_xkl[(size_t)MTOT * E_];
__device__ __nv_bfloat16 g_xvh[(size_t)MTOT * E_];
__device__ __nv_bfloat16 g_xvl[(size_t)MTOT * E_];

__device__ __nv_bfloat16 g_Qh[(size_t)MTOT * E_];
__device__ __nv_bfloat16 g_Ql[(size_t)MTOT * E_];
__device__ __nv_bfloat16 g_Kh[(size_t)MTOT * E_];
__device__ __nv_bfloat16 g_Kl[(size_t)MTOT * E_];
__device__ __nv_bfloat16 g_Vh[(size_t)MTOT * E_];
__device__ __nv_bfloat16 g_Vl[(size_t)MTOT * E_];
__device__ __nv_bfloat16 g_Ah[(size_t)MTOT * E_];
__device__ __nv_bfloat16 g_Al[(size_t)MTOT * E_];

__device__ __nv_bfloat16 g_Wqh[(size_t)E_ * E_];
__device__ __nv_bfloat16 g_Wql[(size_t)E_ * E_];
__device__ __nv_bfloat16 g_Wkh[(size_t)E_ * E_];
__device__ __nv_bfloat16 g_Wkl[(size_t)E_ * E_];
__device__ __nv_bfloat16 g_Wvh[(size_t)E_ * E_];
__device__ __nv_bfloat16 g_Wvl[(size_t)E_ * E_];
__device__ __nv_bfloat16 g_Woh[(size_t)E_ * E_];
__device__ __nv_bfloat16 g_Wol[(size_t)E_ * E_];

// ---------------------------------------------------------------------------
// helpers
// ---------------------------------------------------------------------------
__device__ __forceinline__ uint32_t smem_u32(const void* p) {
    uint32_t a;
    asm("{ .reg .u64 t; cvta.to.shared.u64 t, %1; cvt.u32.u64 %0, t; }"
        : "=r"(a) : "l"(p));
    return a;
}
__device__ __forceinline__ void cp16(uint32_t sa, const void* ga) {
    asm volatile("cp.async.cg.shared.global [%0], [%1], 16;"
                 :: "r"(sa), "l"(ga));
}
__device__ __forceinline__ void cp_commit() {
    asm volatile("cp.async.commit_group;");
}
__device__ __forceinline__ void cp_wait1() {
    asm volatile("cp.async.wait_group 1;");
}
__device__ __forceinline__ void cp_wait0() {
    asm volatile("cp.async.wait_group 0;");
}
__device__ __forceinline__ void ldmx4(uint32_t& r0, uint32_t& r1,
                                      uint32_t& r2, uint32_t& r3, uint32_t a) {
    asm volatile("ldmatrix.sync.aligned.m8n8.x4.shared.b16 {%0,%1,%2,%3}, [%4];"
                 : "=r"(r0), "=r"(r1), "=r"(r2), "=r"(r3) : "r"(a));
}
__device__ __forceinline__ void ldmx4t(uint32_t& r0, uint32_t& r1,
                                       uint32_t& r2, uint32_t& r3, uint32_t a) {
    asm volatile("ldmatrix.sync.aligned.m8n8.x4.trans.shared.b16 {%0,%1,%2,%3}, [%4];"
                 : "=r"(r0), "=r"(r1), "=r"(r2), "=r"(r3) : "r"(a));
}
__device__ __forceinline__ void mma16816(float* d, const uint32_t* a,
                                         const uint32_t* b) {
    asm volatile(
        "mma.sync.aligned.m16n8k16.row.col.f32.bf16.bf16.f32 "
        "{%0,%1,%2,%3}, {%4,%5,%6,%7}, {%8,%9}, {%0,%1,%2,%3};"
        : "+f"(d[0]), "+f"(d[1]), "+f"(d[2]), "+f"(d[3])
        : "r"(a[0]), "r"(a[1]), "r"(a[2]), "r"(a[3]), "r"(b[0]), "r"(b[1]));
}
__device__ __forceinline__ void split2(float a, float b, uint32_t& hi, uint32_t& lo) {
    __nv_bfloat162 h = __floats2bfloat162_rn(a, b);
    __nv_bfloat162 l = __floats2bfloat162_rn(
        a - __bfloat162float(h.x), b - __bfloat162float(h.y));
    hi = *(uint32_t*)&h;
    lo = *(uint32_t*)&l;
}

// ---------------------------------------------------------------------------
// Prepass: fp32 -> (hi, lo) bf16 split.
// ---------------------------------------------------------------------------
__global__ __launch_bounds__(256) void convert_split(
    const float* __restrict__ src, __nv_bfloat16* __restrict__ h,
    __nv_bfloat16* __restrict__ l, int n4)
{
    int i = blockIdx.x * 256 + threadIdx.x;
    if (i >= n4) return;
    float4 v = ((const float4*)src)[i];
    uint32_t h01, l01, h23, l23;
    split2(v.x, v.y, h01, l01);
    split2(v.z, v.w, h23, l23);
    ((uint2*)h)[i] = make_uint2(h01, h23);
    ((uint2*)l)[i] = make_uint2(l01, l23);
}

// ===========================================================================
// HMMA GEMM: C = (Xh+Xl) @ (Wh+Wl)^T, fp32 accum, 3 split products.
// CTA 128x128, BKC=32, 2-stage cp.async pipeline (80KB smem, 2 CTAs/SM).
// MMA issue is product-major: 16 independent tiles between same-acc repeats.
// ===========================================================================
#define BM 128
#define BN 128
#define BKC 32
#define KTOT 1024
#define NCHUNK (KTOT / BKC)
#define LDT 40
#define TILE_B (128 * LDT * 2)
#define STAGE_B (4 * TILE_B)       // 40960
#define GSMEM_SZ (2 * STAGE_B)     // 81920 -> 2 CTAs/SM

__device__ __forceinline__ uint32_t lm_addr(uint32_t base_b, int row0, int kseg0) {
    int L = threadIdx.x & 31;
    int mat = L >> 3;
    int r = (L & 7) + ((mat & 1) << 3);
    int ks = kseg0 + (mat >> 1);
    return base_b + (uint32_t)(row0 + r) * (LDT * 2) + ks * 16;
}

__global__ __launch_bounds__(256, 2) void gemm_tc(
    const __nv_bfloat16* __restrict__ Xh, const __nv_bfloat16* __restrict__ Xl,
    const __nv_bfloat16* __restrict__ Wh, const __nv_bfloat16* __restrict__ Wl,
    const float* __restrict__ bias, float* __restrict__ Cf,
    __nv_bfloat16* __restrict__ Oh, __nv_bfloat16* __restrict__ Ol,
    float scale, int Nn)
{
    extern __shared__ char dynsm[];
    const uint32_t smb = smem_u32(dynsm);
    const int tid = threadIdx.x;
    const int bm = blockIdx.y * BM;
    const int bn = blockIdx.x * BN;
    const int w = tid >> 5;
    const int wm = w >> 2;
    const int wn = w & 3;

    const char* tb[4];
    tb[0] = (const char*)(Xh + (size_t)bm * KTOT);
    tb[1] = (const char*)(Xl + (size_t)bm * KTOT);
    tb[2] = (const char*)(Wh + (size_t)bn * KTOT);
    tb[3] = (const char*)(Wl + (size_t)bn * KTOT);

    float acc[4][4][4];
#pragma unroll
    for (int i = 0; i < 4; i++)
#pragma unroll
        for (int j = 0; j < 4; j++)
#pragma unroll
            for (int t = 0; t < 4; t++) acc[i][j][t] = 0.f;

    auto issue = [&](int c, int s) {
#pragma unroll
        for (int i = 0; i < 8; i++) {
            int sid = tid + 256 * i;
            int tile = sid >> 9;
            int r = (sid >> 2) & 127;
            int seg = sid & 3;
            const char* base = (tile == 0) ? tb[0] : (tile == 1) ? tb[1]
                             : (tile == 2) ? tb[2] : tb[3];
            uint32_t sa = smb + (uint32_t)s * STAGE_B + (uint32_t)tile * TILE_B
                        + (uint32_t)r * (LDT * 2) + seg * 16;
            const char* ga = base + (size_t)r * (KTOT * 2) + c * (BKC * 2) + seg * 16;
            cp16(sa, ga);
        }
        cp_commit();
    };

    issue(0, 0);

    for (int c = 0; c < NCHUNK; c++) {
        const int st = c & 1;
        if (c + 1 < NCHUNK) {
            issue(c + 1, st ^ 1);
            cp_wait1();
        } else {
            cp_wait0();
        }
        __syncthreads();

        const uint32_t bXh = smb + (uint32_t)st * STAGE_B;
        const uint32_t bXl = bXh + TILE_B;
        const uint32_t bWh = bXh + 2 * TILE_B;
        const uint32_t bWl = bXh + 3 * TILE_B;

#pragma unroll
        for (int ks = 0; ks < 2; ks++) {
            const int kseg0 = ks * 2;
            uint32_t ah[4][4], al[4][4], bh[4][2], bl[4][2];
#pragma unroll
            for (int mt = 0; mt < 4; mt++) {
                ldmx4(ah[mt][0], ah[mt][1], ah[mt][2], ah[mt][3],
                      lm_addr(bXh, wm * 64 + mt * 16, kseg0));
                ldmx4(al[mt][0], al[mt][1], al[mt][2], al[mt][3],
                      lm_addr(bXl, wm * 64 + mt * 16, kseg0));
            }
#pragma unroll
            for (int np = 0; np < 2; np++) {
                uint32_t r0, r1, r2, r3;
                ldmx4(r0, r1, r2, r3, lm_addr(bWh, wn * 32 + np * 16, kseg0));
                bh[np * 2 + 0][0] = r0; bh[np * 2 + 0][1] = r2;
                bh[np * 2 + 1][0] = r1; bh[np * 2 + 1][1] = r3;
                ldmx4(r0, r1, r2, r3, lm_addr(bWl, wn * 32 + np * 16, kseg0));
                bl[np * 2 + 0][0] = r0; bl[np * 2 + 0][1] = r2;
                bl[np * 2 + 1][0] = r1; bl[np * 2 + 1][1] = r3;
            }
            // product-major: 16 independent MMAs between same-acc repeats
#pragma unroll
            for (int mt = 0; mt < 4; mt++)
#pragma unroll
                for (int nt = 0; nt < 4; nt++)
                    mma16816(acc[mt][nt], ah[mt], bh[nt]);
#pragma unroll
            for (int mt = 0; mt < 4; mt++)
#pragma unroll
                for (int nt = 0; nt < 4; nt++)
                    mma16816(acc[mt][nt], ah[mt], bl[nt]);
#pragma unroll
            for (int mt = 0; mt < 4; mt++)
#pragma unroll
                for (int nt = 0; nt < 4; nt++)
                    mma16816(acc[mt][nt], al[mt], bh[nt]);
        }
        __syncthreads();
    }

    const int lid = tid & 31;
    const int grp = lid >> 2;
    const int tig = lid & 3;
#pragma unroll
    for (int mt = 0; mt < 4; mt++) {
#pragma unroll
        for (int nt = 0; nt < 4; nt++) {
            int row = bm + wm * 64 + mt * 16 + grp;
            int col = bn + wn * 32 + nt * 8 + tig * 2;
            float a0 = acc[mt][nt][0] * scale, a1 = acc[mt][nt][1] * scale;
            float a2 = acc[mt][nt][2] * scale, a3 = acc[mt][nt][3] * scale;
            if (Cf != nullptr) {
                if (bias != nullptr) {
                    float b0 = bias[col], b1 = bias[col + 1];
                    a0 += b0; a1 += b1; a2 += b0; a3 += b1;
                }
                *(float2*)(Cf + (size_t)row * Nn + col) = make_float2(a0, a1);
                *(float2*)(Cf + (size_t)(row + 8) * Nn + col) = make_float2(a2, a3);
            } else {
                uint32_t hi, lo;
                split2(a0, a1, hi, lo);
                *(uint32_t*)(Oh + (size_t)row * Nn + col) = hi;
                *(uint32_t*)(Ol + (size_t)row * Nn + col) = lo;
                split2(a2, a3, hi, lo);
                *(uint32_t*)(Oh + (size_t)(row + 8) * Nn + col) = hi;
                *(uint32_t*)(Ol + (size_t)(row + 8) * Nn + col) = lo;
            }
        }
    }
}

// ===========================================================================
// Tensor-core causal flash attention, bf16 hi/lo, q-tile 128 rows (8 warps).
// Product-major MMA issue (8 independent tiles between same-acc repeats).
// ===========================================================================
#define ALDT 144                   // smem row stride bytes
#define AQ_TILE (128 * ALDT)       // 18432
#define AKV_TILE (64 * ALDT)       // 9216
#define AOFF_QH 0
#define AOFF_QL AQ_TILE
#define AOFF_ST (2 * AQ_TILE)      // 36864
#define ASTAGE (4 * AKV_TILE)      // 36864
#define ASMEM (AOFF_ST + 2 * ASTAGE)  // 110592

__device__ __forceinline__ uint32_t lda(uint32_t base, int r0, int c0) {
    int L = threadIdx.x & 31;
    int mat = L >> 3;
    int r = r0 + (L & 7) + ((mat & 1) << 3);
    int c = c0 + ((mat >> 1) << 3);
    return base + (uint32_t)r * ALDT + c * 2;
}

__global__ __launch_bounds__(256) void attn_mma(
    const __nv_bfloat16* __restrict__ Qh, const __nv_bfloat16* __restrict__ Ql,
    const __nv_bfloat16* __restrict__ Kh, const __nv_bfloat16* __restrict__ Kl,
    const __nv_bfloat16* __restrict__ Vh, const __nv_bfloat16* __restrict__ Vl,
    __nv_bfloat16* __restrict__ Oh, __nv_bfloat16* __restrict__ Ol)
{
    extern __shared__ char dynsm[];
    const uint32_t smb = smem_u32(dynsm);
    const int tid = threadIdx.x;
    const int w = tid >> 5;
    const int lid = tid & 31;
    const int grp = lid >> 2;
    const int tig = lid & 3;
    const int iblk = (gridDim.x - 1) - blockIdx.x;   // heavy blocks first
    const int h = blockIdx.y;
    const int b = blockIdx.z;
    const int qbase = iblk * 128;
    const int jmax = 2 * iblk + 1;
    const size_t bN = (size_t)b * N_;

    auto issue_stage = [&](int s, int kbase) {
#pragma unroll
        for (int i = 0; i < 8; i++) {
            int sid = tid + 256 * i;          // 0..2047
            int tile = sid >> 9;              // 0 Kh,1 Kl,2 Vh,3 Vl
            int r = (sid >> 3) & 63;
            int seg = sid & 7;
            const __nv_bfloat16* gp = (tile == 0) ? Kh : (tile == 1) ? Kl
                                    : (tile == 2) ? Vh : Vl;
            const char* ga = (const char*)(gp + (bN + kbase + r) * E_ + h * 64)
                           + seg * 16;
            cp16(smb + AOFF_ST + (uint32_t)s * ASTAGE + (uint32_t)tile * AKV_TILE
                 + (uint32_t)r * ALDT + seg * 16, ga);
        }
        cp_commit();
    };

    // prologue: Q tiles (128 rows x 64 cols, hi+lo) + KV stage 0
    {
#pragma unroll
        for (int i = 0; i < 8; i++) {
            int sid = tid + 256 * i;          // 0..2047
            int tile = sid >> 10;             // 0 Qh, 1 Ql
            int r = (sid >> 3) & 127;
            int seg = sid & 7;
            const __nv_bfloat16* gp = tile ? Ql : Qh;
            const char* ga = (const char*)(gp + (bN + qbase + r) * E_ + h * 64)
                           + seg * 16;
            cp16(smb + (tile ? AOFF_QL : AOFF_QH) + (uint32_t)r * ALDT + seg * 16, ga);
        }
    }
    issue_stage(0, 0);

    uint32_t qh[4][4], ql[4][4];
    float o[8][4];
#pragma unroll
    for (int t = 0; t < 8; t++)
#pragma unroll
        for (int c = 0; c < 4; c++) o[t][c] = 0.f;
    float mr0 = -1e30f, mr1 = -1e30f, lr0 = 0.f, lr1 = 0.f;

    for (int j = 0; j <= jmax; j++) {
        cp_wait0();
        __syncthreads();
        if (j == 0) {
#pragma unroll
            for (int kc = 0; kc < 4; kc++) {
                ldmx4(qh[kc][0], qh[kc][1], qh[kc][2], qh[kc][3],
                      lda(smb + AOFF_QH, w * 16, kc * 16));
                ldmx4(ql[kc][0], ql[kc][1], ql[kc][2], ql[kc][3],
                      lda(smb + AOFF_QL, w * 16, kc * 16));
            }
        }
        if (j < jmax) issue_stage((j + 1) & 1, (j + 1) * 64);

        const uint32_t bKH = smb + AOFF_ST + (uint32_t)(j & 1) * ASTAGE;
        const uint32_t bKL = bKH + AKV_TILE;
        const uint32_t bVH = bKH + 2 * AKV_TILE;
        const uint32_t bVL = bKH + 3 * AKV_TILE;

        // ---- S = Q K^T, product-major over hoisted K fragments ----
        float s[8][4];
#pragma unroll
        for (int t = 0; t < 8; t++)
#pragma unroll
            for (int c = 0; c < 4; c++) s[t][c] = 0.f;
#pragma unroll
        for (int kc = 0; kc < 4; kc++) {
            uint32_t bh[8][2], bl[8][2];
#pragma unroll
            for (int np = 0; np < 4; np++) {
                uint32_t r0, r1, r2, r3;
                ldmx4(r0, r1, r2, r3, lda(bKH, np * 16, kc * 16));
                bh[np * 2 + 0][0] = r0; bh[np * 2 + 0][1] = r2;
                bh[np * 2 + 1][0] = r1; bh[np * 2 + 1][1] = r3;
                ldmx4(r0, r1, r2, r3, lda(bKL, np * 16, kc * 16));
                bl[np * 2 + 0][0] = r0; bl[np * 2 + 0][1] = r2;
                bl[np * 2 + 1][0] = r1; bl[np * 2 + 1][1] = r3;
            }
#pragma unroll
            for (int t = 0; t < 8; t++) mma16816(s[t], qh[kc], bh[t]);
#pragma unroll
            for (int t = 0; t < 8; t++) mma16816(s[t], qh[kc], bl[t]);
#pragma unroll
            for (int t = 0; t < 8; t++) mma16816(s[t], ql[kc], bh[t]);
        }

        // ---- causal mask (only kv-blocks crossing the diagonal) ----
        if (j >= 2 * iblk) {
            const int row0 = qbase + w * 16 + grp;
            const int row1 = row0 + 8;
            const int cb = j * 64;
#pragma unroll
            for (int t = 0; t < 8; t++) {
                int col = cb + t * 8 + 2 * tig;
                if (col > row0) s[t][0] = -1e30f;
                if (col + 1 > row0) s[t][1] = -1e30f;
                if (col > row1) s[t][2] = -1e30f;
                if (col + 1 > row1) s[t][3] = -1e30f;
            }
        }

        // ---- online softmax (base-2) ----
        float m0 = -1e30f, m1 = -1e30f;
#pragma unroll
        for (int t = 0; t < 8; t++) {
            m0 = fmaxf(m0, fmaxf(s[t][0], s[t][1]));
            m1 = fmaxf(m1, fmaxf(s[t][2], s[t][3]));
        }
        m0 = fmaxf(m0, __shfl_xor_sync(0xffffffffu, m0, 1));
        m0 = fmaxf(m0, __shfl_xor_sync(0xffffffffu, m0, 2));
        m1 = fmaxf(m1, __shfl_xor_sync(0xffffffffu, m1, 1));
        m1 = fmaxf(m1, __shfl_xor_sync(0xffffffffu, m1, 2));
        float mn0 = fmaxf(mr0, m0), mn1 = fmaxf(mr1, m1);
        float a0 = exp2f(mr0 - mn0), a1 = exp2f(mr1 - mn1);
        mr0 = mn0; mr1 = mn1;
        float sum0 = 0.f, sum1 = 0.f;
#pragma unroll
        for (int t = 0; t < 8; t++) {
            s[t][0] = exp2f(s[t][0] - mn0);
            s[t][1] = exp2f(s[t][1] - mn0);
            s[t][2] = exp2f(s[t][2] - mn1);
            s[t][3] = exp2f(s[t][3] - mn1);
            sum0 += s[t][0] + s[t][1];
            sum1 += s[t][2] + s[t][3];
        }
        sum0 += __shfl_xor_sync(0xffffffffu, sum0, 1);
        sum0 += __shfl_xor_sync(0xffffffffu, sum0, 2);
        sum1 += __shfl_xor_sync(0xffffffffu, sum1, 1);
        sum1 += __shfl_xor_sync(0xffffffffu, sum1, 2);
        lr0 = lr0 * a0 + sum0;
        lr1 = lr1 * a1 + sum1;
#pragma unroll
        for (int t = 0; t < 8; t++) {
            o[t][0] *= a0; o[t][1] *= a0;
            o[t][2] *= a1; o[t][3] *= a1;
        }

        // ---- P: C-frag -> A-frag, hi/lo split ----
        uint32_t ph[4][4], pl[4][4];
#pragma unroll
        for (int kc = 0; kc < 4; kc++) {
            split2(s[2 * kc][0], s[2 * kc][1], ph[kc][0], pl[kc][0]);
            split2(s[2 * kc][2], s[2 * kc][3], ph[kc][1], pl[kc][1]);
            split2(s[2 * kc + 1][0], s[2 * kc + 1][1], ph[kc][2], pl[kc][2]);
            split2(s[2 * kc + 1][2], s[2 * kc + 1][3], ph[kc][3], pl[kc][3]);
        }

        // ---- O += P V, product-major over hoisted V fragments ----
#pragma unroll
        for (int kc = 0; kc < 4; kc++) {
            uint32_t vh[8][2], vl[8][2];
#pragma unroll
            for (int nd = 0; nd < 4; nd++) {
                uint32_t r0, r1, r2, r3;
                ldmx4t(r0, r1, r2, r3, lda(bVH, kc * 16, nd * 16));
                vh[nd * 2 + 0][0] = r0; vh[nd * 2 + 0][1] = r1;
                vh[nd * 2 + 1][0] = r2; vh[nd * 2 + 1][1] = r3;
                ldmx4t(r0, r1, r2, r3, lda(bVL, kc * 16, nd * 16));
                vl[nd * 2 + 0][0] = r0; vl[nd * 2 + 0][1] = r1;
                vl[nd * 2 + 1][0] = r2; vl[nd * 2 + 1][1] = r3;
            }
#pragma unroll
            for (int t = 0; t < 8; t++) mma16816(o[t], ph[kc], vh[t]);
#pragma unroll
            for (int t = 0; t < 8; t++) mma16816(o[t], ph[kc], vl[t]);
#pragma unroll
            for (int t = 0; t < 8; t++) mma16816(o[t], pl[kc], vh[t]);
        }
    }

    // ---- epilogue: normalize, hi/lo split, store [B,N,E] ----
    const float i0 = 1.f / lr0, i1 = 1.f / lr1;
    const int qr0 = qbase + w * 16 + grp;
    const size_t ro0 = (bN + qr0) * E_;
    const size_t ro1 = (bN + qr0 + 8) * E_;
#pragma unroll
    for (int t = 0; t < 8; t++) {
        int col = h * 64 + t * 8 + 2 * tig;
        uint32_t hi, lo;
        split2(o[t][0] * i0, o[t][1] * i0, hi, lo);
        *(uint32_t*)(Oh + ro0 + col) = hi;
        *(uint32_t*)(Ol + ro0 + col) = lo;
        split2(o[t][2] * i1, o[t][3] * i1, hi, lo);
        *(uint32_t*)(Oh + ro1 + col) = hi;
        *(uint32_t*)(Ol + ro1 + col) = lo;
    }
}

// ---------------------------------------------------------------------------
extern "C" void kernel_launch(void* const* d_in, const int* in_sizes, int n_in,
                              void* d_out, int out_size)
{
    const float* xq = (const float*)d_in[0];
    const float* xk = (const float*)d_in[1];
    const float* xv = (const float*)d_in[2];
    // d_in[3] = attn_mask (causal, recomputed analytically) — unused
    const float* Wq = (const float*)d_in[4];
    const float* Wk = (const float*)d_in[5];
    const float* Wv = (const float*)d_in[6];
    const float* Wo = (const float*)d_in[7];
    const float* bo = (const float*)d_in[8];
    float* out = (float*)d_out;

    __nv_bfloat16 *xqh, *xql, *xkh, *xkl, *xvh, *xvl;
    __nv_bfloat16 *Qh, *Ql, *Kh, *Kl, *Vh, *Vl, *Ah, *Al;
    __nv_bfloat16 *Wqh, *Wql, *Wkh, *Wkl, *Wvh, *Wvl, *Woh, *Wol;
    cudaGetSymbolAddress((void**)&xqh, g_xqh);
    cudaGetSymbolAddress((void**)&xql, g_xql);
    cudaGetSymbolAddress((void**)&xkh, g_xkh);
    cudaGetSymbolAddress((void**)&xkl, g_xkl);
    cudaGetSymbolAddress((void**)&xvh, g_xvh);
    cudaGetSymbolAddress((void**)&xvl, g_xvl);
    cudaGetSymbolAddress((void**)&Qh, g_Qh);
    cudaGetSymbolAddress((void**)&Ql, g_Ql);
    cudaGetSymbolAddress((void**)&Kh, g_Kh);
    cudaGetSymbolAddress((void**)&Kl, g_Kl);
    cudaGetSymbolAddress((void**)&Vh, g_Vh);
    cudaGetSymbolAddress((void**)&Vl, g_Vl);
    cudaGetSymbolAddress((void**)&Ah, g_Ah);
    cudaGetSymbolAddress((void**)&Al, g_Al);
    cudaGetSymbolAddress((void**)&Wqh, g_Wqh);
    cudaGetSymbolAddress((void**)&Wql, g_Wql);
    cudaGetSymbolAddress((void**)&Wkh, g_Wkh);
    cudaGetSymbolAddress((void**)&Wkl, g_Wkl);
    cudaGetSymbolAddress((void**)&Wvh, g_Wvh);
    cudaGetSymbolAddress((void**)&Wvl, g_Wvl);
    cudaGetSymbolAddress((void**)&Woh, g_Woh);
    cudaGetSymbolAddress((void**)&Wol, g_Wol);

    cudaFuncSetAttribute(gemm_tc, cudaFuncAttributeMaxDynamicSharedMemorySize,
                         GSMEM_SZ);
    cudaFuncSetAttribute(attn_mma, cudaFuncAttributeMaxDynamicSharedMemorySize,
                         ASMEM);

    // Prepass conversions
    const int nx4 = MTOT * E_ / 4;
    const int nw4 = E_ * E_ / 4;
    convert_split<<<nx4 / 256, 256>>>(xq, xqh, xql, nx4);
    convert_split<<<nx4 / 256, 256>>>(xk, xkh, xkl, nx4);
    convert_split<<<nx4 / 256, 256>>>(xv, xvh, xvl, nx4);
    convert_split<<<nw4 / 256, 256>>>(Wq, Wqh, Wql, nw4);
    convert_split<<<nw4 / 256, 256>>>(Wk, Wkh, Wkl, nw4);
    convert_split<<<nw4 / 256, 256>>>(Wv, Wvh, Wvl, nw4);
    convert_split<<<nw4 / 256, 256>>>(Wo, Woh, Wol, nw4);

    dim3 gblock(256);
    dim3 ggrid(E_ / BN, MTOT / BM);        // (8, 64)

    // Projections -> bf16 hi/lo (Q pre-scaled by log2e/sqrt(D))
    gemm_tc<<<ggrid, gblock, GSMEM_SZ>>>(xqh, xql, Wqh, Wql, nullptr, nullptr,
                                         Qh, Ql, SCALE_LOG2E, E_);
    gemm_tc<<<ggrid, gblock, GSMEM_SZ>>>(xkh, xkl, Wkh, Wkl, nullptr, nullptr,
                                         Kh, Kl, 1.0f, E_);
    gemm_tc<<<ggrid, gblock, GSMEM_SZ>>>(xvh, xvl, Wvh, Wvl, nullptr, nullptr,
                                         Vh, Vl, 1.0f, E_);

    dim3 agrid(N_ / 128, H_, B_);          // (16, 16, 4)
    attn_mma<<<agrid, 256, ASMEM>>>(Qh, Ql, Kh, Kl, Vh, Vl, Ah, Al);

    // Output projection -> fp32 + bias
    gemm_tc<<<ggrid, gblock, GSMEM_SZ>>>(Ah, Al, Woh, Wol, bo, out,
                                         nullptr, nullptr, 1.0f, E_);
}

// round 11
// speedup vs baseline: 1.5031x; 1.3378x over previous
#include <cuda_runtime.h>
#include <cuda_fp16.h>
#include <cstdint>

#define B_ 4
#define N_ 2048
#define E_ 1024
#define H_ 16
#define D_ 64
#define SCALE_ 0.125f            // 1/sqrt(64)
#define SCALE_LOG2E 0.18033688f  // 0.125 * log2(e)
#define MTOT (B_ * N_)           // 8192

// ---------------------------------------------------------------------------
// Scratch (allocation-free rule: __device__ globals)
// ---------------------------------------------------------------------------
__device__ __half g_xqh[(size_t)MTOT * E_];
__device__ __half g_xql[(size_t)MTOT * E_];
__device__ __half g_xkh[(size_t)MTOT * E_];
__device__ __half g_xkl[(size_t)MTOT * E_];
__device__ __half g_xvh[(size_t)MTOT * E_];
__device__ __half g_xvl[(size_t)MTOT * E_];

__device__ __half g_Qh[(size_t)MTOT * E_];
__device__ __half g_Ql[(size_t)MTOT * E_];
__device__ __half g_K[(size_t)MTOT * E_];
__device__ __half g_V[(size_t)MTOT * E_];
__device__ __half g_Ah[(size_t)MTOT * E_];
__device__ __half g_Al[(size_t)MTOT * E_];

__device__ __half g_Wq[(size_t)E_ * E_];
__device__ __half g_Wk[(size_t)E_ * E_];
__device__ __half g_Wv[(size_t)E_ * E_];
__device__ __half g_Wo[(size_t)E_ * E_];

// ---------------------------------------------------------------------------
// helpers
// ---------------------------------------------------------------------------
__device__ __forceinline__ uint32_t smem_u32(const void* p) {
    uint32_t a;
    asm("{ .reg .u64 t; cvta.to.shared.u64 t, %1; cvt.u32.u64 %0, t; }"
        : "=r"(a) : "l"(p));
    return a;
}
__device__ __forceinline__ void cp16(uint32_t sa, const void* ga) {
    asm volatile("cp.async.cg.shared.global [%0], [%1], 16;"
                 :: "r"(sa), "l"(ga));
}
__device__ __forceinline__ void cp_commit() {
    asm volatile("cp.async.commit_group;");
}
__device__ __forceinline__ void cp_wait1() {
    asm volatile("cp.async.wait_group 1;");
}
__device__ __forceinline__ void cp_wait0() {
    asm volatile("cp.async.wait_group 0;");
}
__device__ __forceinline__ void ldmx4(uint32_t& r0, uint32_t& r1,
                                      uint32_t& r2, uint32_t& r3, uint32_t a) {
    asm volatile("ldmatrix.sync.aligned.m8n8.x4.shared.b16 {%0,%1,%2,%3}, [%4];"
                 : "=r"(r0), "=r"(r1), "=r"(r2), "=r"(r3) : "r"(a));
}
__device__ __forceinline__ void ldmx4t(uint32_t& r0, uint32_t& r1,
                                       uint32_t& r2, uint32_t& r3, uint32_t a) {
    asm volatile("ldmatrix.sync.aligned.m8n8.x4.trans.shared.b16 {%0,%1,%2,%3}, [%4];"
                 : "=r"(r0), "=r"(r1), "=r"(r2), "=r"(r3) : "r"(a));
}
__device__ __forceinline__ void mma16816(float* d, const uint32_t* a,
                                         const uint32_t* b) {
    asm volatile(
        "mma.sync.aligned.m16n8k16.row.col.f32.f16.f16.f32 "
        "{%0,%1,%2,%3}, {%4,%5,%6,%7}, {%8,%9}, {%0,%1,%2,%3};"
        : "+f"(d[0]), "+f"(d[1]), "+f"(d[2]), "+f"(d[3])
        : "r"(a[0]), "r"(a[1]), "r"(a[2]), "r"(a[3]), "r"(b[0]), "r"(b[1]));
}
// split (a,b) into fp16x2 hi + lo words
__device__ __forceinline__ void split2h(float a, float b, uint32_t& hi, uint32_t& lo) {
    __half2 h = __floats2half2_rn(a, b);
    __half2 l = __floats2half2_rn(a - __half2float(h.x), b - __half2float(h.y));
    hi = *(uint32_t*)&h;
    lo = *(uint32_t*)&l;
}
__device__ __forceinline__ uint32_t pack2h(float a, float b) {
    __half2 h = __floats2half2_rn(a, b);
    return *(uint32_t*)&h;
}

// ---------------------------------------------------------------------------
// Prepass: fp32 -> (hi, lo) fp16 split, and fp32 -> fp16 single.
// ---------------------------------------------------------------------------
__global__ __launch_bounds__(256) void convert_split_h(
    const float* __restrict__ src, __half* __restrict__ h,
    __half* __restrict__ l, int n4)
{
    int i = blockIdx.x * 256 + threadIdx.x;
    if (i >= n4) return;
    float4 v = ((const float4*)src)[i];
    uint32_t h01, l01, h23, l23;
    split2h(v.x, v.y, h01, l01);
    split2h(v.z, v.w, h23, l23);
    ((uint2*)h)[i] = make_uint2(h01, h23);
    ((uint2*)l)[i] = make_uint2(l01, l23);
}
__global__ __launch_bounds__(256) void convert_h(
    const float* __restrict__ src, __half* __restrict__ h, int n4)
{
    int i = blockIdx.x * 256 + threadIdx.x;
    if (i >= n4) return;
    float4 v = ((const float4*)src)[i];
    ((uint2*)h)[i] = make_uint2(pack2h(v.x, v.y), pack2h(v.z, v.w));
}

// ===========================================================================
// HMMA GEMM: C = (Xh+Xl) @ W^T, fp32 accum, 2 products (Xh*W + Xl*W).
// CTA 128x128, BKC=32, 2-stage cp.async pipeline, 3 tiles/stage (60KB smem).
// Epilogue: fp32+bias (Cf), fp16 hi/lo (Oh+Ol), or fp16 single (Oh only).
// ===========================================================================
#define BM 128
#define BN 128
#define BKC 32
#define KTOT 1024
#define NCHUNK (KTOT / BKC)
#define LDT 40
#define TILE_B (128 * LDT * 2)
#define STAGE_B (3 * TILE_B)       // 30720
#define GSMEM_SZ (2 * STAGE_B)     // 61440 -> 2 CTAs/SM

__device__ __forceinline__ uint32_t lm_addr(uint32_t base_b, int row0, int kseg0) {
    int L = threadIdx.x & 31;
    int mat = L >> 3;
    int r = (L & 7) + ((mat & 1) << 3);
    int ks = kseg0 + (mat >> 1);
    return base_b + (uint32_t)(row0 + r) * (LDT * 2) + ks * 16;
}

__global__ __launch_bounds__(256, 2) void gemm_tc(
    const __half* __restrict__ Xh, const __half* __restrict__ Xl,
    const __half* __restrict__ W,
    const float* __restrict__ bias, float* __restrict__ Cf,
    __half* __restrict__ Oh, __half* __restrict__ Ol,
    float scale, int Nn)
{
    extern __shared__ char dynsm[];
    const uint32_t smb = smem_u32(dynsm);
    const int tid = threadIdx.x;
    const int bm = blockIdx.y * BM;
    const int bn = blockIdx.x * BN;
    const int w = tid >> 5;
    const int wm = w >> 2;
    const int wn = w & 3;

    const char* tb[3];
    tb[0] = (const char*)(Xh + (size_t)bm * KTOT);
    tb[1] = (const char*)(Xl + (size_t)bm * KTOT);
    tb[2] = (const char*)(W + (size_t)bn * KTOT);

    float acc[4][4][4];
#pragma unroll
    for (int i = 0; i < 4; i++)
#pragma unroll
        for (int j = 0; j < 4; j++)
#pragma unroll
            for (int t = 0; t < 4; t++) acc[i][j][t] = 0.f;

    auto issue = [&](int c, int s) {
#pragma unroll
        for (int i = 0; i < 6; i++) {
            int sid = tid + 256 * i;          // 0..1535
            int tile = sid >> 9;              // 0 Xh, 1 Xl, 2 W
            int r = (sid >> 2) & 127;
            int seg = sid & 3;
            const char* base = (tile == 0) ? tb[0] : (tile == 1) ? tb[1] : tb[2];
            uint32_t sa = smb + (uint32_t)s * STAGE_B + (uint32_t)tile * TILE_B
                        + (uint32_t)r * (LDT * 2) + seg * 16;
            const char* ga = base + (size_t)r * (KTOT * 2) + c * (BKC * 2) + seg * 16;
            cp16(sa, ga);
        }
        cp_commit();
    };

    issue(0, 0);

    for (int c = 0; c < NCHUNK; c++) {
        const int st = c & 1;
        if (c + 1 < NCHUNK) {
            issue(c + 1, st ^ 1);
            cp_wait1();
        } else {
            cp_wait0();
        }
        __syncthreads();

        const uint32_t bXh = smb + (uint32_t)st * STAGE_B;
        const uint32_t bXl = bXh + TILE_B;
        const uint32_t bW  = bXh + 2 * TILE_B;

#pragma unroll
        for (int ks = 0; ks < 2; ks++) {
            const int kseg0 = ks * 2;
            uint32_t ah[4][4], al[4][4], bw[4][2];
#pragma unroll
            for (int mt = 0; mt < 4; mt++) {
                ldmx4(ah[mt][0], ah[mt][1], ah[mt][2], ah[mt][3],
                      lm_addr(bXh, wm * 64 + mt * 16, kseg0));
                ldmx4(al[mt][0], al[mt][1], al[mt][2], al[mt][3],
                      lm_addr(bXl, wm * 64 + mt * 16, kseg0));
            }
#pragma unroll
            for (int np = 0; np < 2; np++) {
                uint32_t r0, r1, r2, r3;
                ldmx4(r0, r1, r2, r3, lm_addr(bW, wn * 32 + np * 16, kseg0));
                bw[np * 2 + 0][0] = r0; bw[np * 2 + 0][1] = r2;
                bw[np * 2 + 1][0] = r1; bw[np * 2 + 1][1] = r3;
            }
#pragma unroll
            for (int mt = 0; mt < 4; mt++)
#pragma unroll
                for (int nt = 0; nt < 4; nt++)
                    mma16816(acc[mt][nt], ah[mt], bw[nt]);
#pragma unroll
            for (int mt = 0; mt < 4; mt++)
#pragma unroll
                for (int nt = 0; nt < 4; nt++)
                    mma16816(acc[mt][nt], al[mt], bw[nt]);
        }
        __syncthreads();
    }

    const int lid = tid & 31;
    const int grp = lid >> 2;
    const int tig = lid & 3;
#pragma unroll
    for (int mt = 0; mt < 4; mt++) {
#pragma unroll
        for (int nt = 0; nt < 4; nt++) {
            int row = bm + wm * 64 + mt * 16 + grp;
            int col = bn + wn * 32 + nt * 8 + tig * 2;
            float a0 = acc[mt][nt][0] * scale, a1 = acc[mt][nt][1] * scale;
            float a2 = acc[mt][nt][2] * scale, a3 = acc[mt][nt][3] * scale;
            if (Cf != nullptr) {
                if (bias != nullptr) {
                    float b0 = bias[col], b1 = bias[col + 1];
                    a0 += b0; a1 += b1; a2 += b0; a3 += b1;
                }
                *(float2*)(Cf + (size_t)row * Nn + col) = make_float2(a0, a1);
                *(float2*)(Cf + (size_t)(row + 8) * Nn + col) = make_float2(a2, a3);
            } else if (Ol != nullptr) {
                uint32_t hi, lo;
                split2h(a0, a1, hi, lo);
                *(uint32_t*)(Oh + (size_t)row * Nn + col) = hi;
                *(uint32_t*)(Ol + (size_t)row * Nn + col) = lo;
                split2h(a2, a3, hi, lo);
                *(uint32_t*)(Oh + (size_t)(row + 8) * Nn + col) = hi;
                *(uint32_t*)(Ol + (size_t)(row + 8) * Nn + col) = lo;
            } else {
                *(uint32_t*)(Oh + (size_t)row * Nn + col) = pack2h(a0, a1);
                *(uint32_t*)(Oh + (size_t)(row + 8) * Nn + col) = pack2h(a2, a3);
            }
        }
    }
}

// ===========================================================================
// Tensor-core causal flash attention, fp16. q-tile 128 rows (8 warps).
// S = (Qh+Ql)K^T (2 products, K single fp16); O = (Ph+Pl)V (2 products).
// K/V stages = 2 tiles, double-buffered cp.async. exp2 softmax.
// ===========================================================================
#define ALDT 144                   // smem row stride bytes
#define AQ_TILE (128 * ALDT)       // 18432
#define AKV_TILE (64 * ALDT)       // 9216
#define AOFF_QH 0
#define AOFF_QL AQ_TILE
#define AOFF_ST (2 * AQ_TILE)      // 36864
#define ASTAGE (2 * AKV_TILE)      // 18432
#define ASMEM (AOFF_ST + 2 * ASTAGE)  // 73728

__device__ __forceinline__ uint32_t lda(uint32_t base, int r0, int c0) {
    int L = threadIdx.x & 31;
    int mat = L >> 3;
    int r = r0 + (L & 7) + ((mat & 1) << 3);
    int c = c0 + ((mat >> 1) << 3);
    return base + (uint32_t)r * ALDT + c * 2;
}

__global__ __launch_bounds__(256) void attn_mma(
    const __half* __restrict__ Qh, const __half* __restrict__ Ql,
    const __half* __restrict__ K, const __half* __restrict__ V,
    __half* __restrict__ Oh, __half* __restrict__ Ol)
{
    extern __shared__ char dynsm[];
    const uint32_t smb = smem_u32(dynsm);
    const int tid = threadIdx.x;
    const int w = tid >> 5;
    const int lid = tid & 31;
    const int grp = lid >> 2;
    const int tig = lid & 3;
    const int iblk = (gridDim.x - 1) - blockIdx.x;   // heavy blocks first
    const int h = blockIdx.y;
    const int b = blockIdx.z;
    const int qbase = iblk * 128;
    const int jmax = 2 * iblk + 1;
    const size_t bN = (size_t)b * N_;

    auto issue_stage = [&](int s, int kbase) {
#pragma unroll
        for (int i = 0; i < 4; i++) {
            int sid = tid + 256 * i;          // 0..1023
            int tile = sid >> 9;              // 0 K, 1 V
            int r = (sid >> 3) & 63;
            int seg = sid & 7;
            const __half* gp = tile ? V : K;
            const char* ga = (const char*)(gp + (bN + kbase + r) * E_ + h * 64)
                           + seg * 16;
            cp16(smb + AOFF_ST + (uint32_t)s * ASTAGE + (uint32_t)tile * AKV_TILE
                 + (uint32_t)r * ALDT + seg * 16, ga);
        }
        cp_commit();
    };

    // prologue: Q tiles (128 rows x 64 cols, hi+lo) + KV stage 0
    {
#pragma unroll
        for (int i = 0; i < 8; i++) {
            int sid = tid + 256 * i;          // 0..2047
            int tile = sid >> 10;             // 0 Qh, 1 Ql
            int r = (sid >> 3) & 127;
            int seg = sid & 7;
            const __half* gp = tile ? Ql : Qh;
            const char* ga = (const char*)(gp + (bN + qbase + r) * E_ + h * 64)
                           + seg * 16;
            cp16(smb + (tile ? AOFF_QL : AOFF_QH) + (uint32_t)r * ALDT + seg * 16, ga);
        }
    }
    issue_stage(0, 0);

    uint32_t qh[4][4], ql[4][4];
    float o[8][4];
#pragma unroll
    for (int t = 0; t < 8; t++)
#pragma unroll
        for (int c = 0; c < 4; c++) o[t][c] = 0.f;
    float mr0 = -1e30f, mr1 = -1e30f, lr0 = 0.f, lr1 = 0.f;

    for (int j = 0; j <= jmax; j++) {
        cp_wait0();
        __syncthreads();
        if (j == 0) {
#pragma unroll
            for (int kc = 0; kc < 4; kc++) {
                ldmx4(qh[kc][0], qh[kc][1], qh[kc][2], qh[kc][3],
                      lda(smb + AOFF_QH, w * 16, kc * 16));
                ldmx4(ql[kc][0], ql[kc][1], ql[kc][2], ql[kc][3],
                      lda(smb + AOFF_QL, w * 16, kc * 16));
            }
        }
        if (j < jmax) issue_stage((j + 1) & 1, (j + 1) * 64);

        const uint32_t bK = smb + AOFF_ST + (uint32_t)(j & 1) * ASTAGE;
        const uint32_t bV = bK + AKV_TILE;

        // ---- S = Q K^T (2 products, hoisted K fragments) ----
        float s[8][4];
#pragma unroll
        for (int t = 0; t < 8; t++)
#pragma unroll
            for (int c = 0; c < 4; c++) s[t][c] = 0.f;
#pragma unroll
        for (int kc = 0; kc < 4; kc++) {
            uint32_t bk[8][2];
#pragma unroll
            for (int np = 0; np < 4; np++) {
                uint32_t r0, r1, r2, r3;
                ldmx4(r0, r1, r2, r3, lda(bK, np * 16, kc * 16));
                bk[np * 2 + 0][0] = r0; bk[np * 2 + 0][1] = r2;
                bk[np * 2 + 1][0] = r1; bk[np * 2 + 1][1] = r3;
            }
#pragma unroll
            for (int t = 0; t < 8; t++) mma16816(s[t], qh[kc], bk[t]);
#pragma unroll
            for (int t = 0; t < 8; t++) mma16816(s[t], ql[kc], bk[t]);
        }

        // ---- causal mask (only kv-blocks crossing the diagonal) ----
        if (j >= 2 * iblk) {
            const int row0 = qbase + w * 16 + grp;
            const int row1 = row0 + 8;
            const int cb = j * 64;
#pragma unroll
            for (int t = 0; t < 8; t++) {
                int col = cb + t * 8 + 2 * tig;
                if (col > row0) s[t][0] = -1e30f;
                if (col + 1 > row0) s[t][1] = -1e30f;
                if (col > row1) s[t][2] = -1e30f;
                if (col + 1 > row1) s[t][3] = -1e30f;
            }
        }

        // ---- online softmax (base-2) ----
        float m0 = -1e30f, m1 = -1e30f;
#pragma unroll
        for (int t = 0; t < 8; t++) {
            m0 = fmaxf(m0, fmaxf(s[t][0], s[t][1]));
            m1 = fmaxf(m1, fmaxf(s[t][2], s[t][3]));
        }
        m0 = fmaxf(m0, __shfl_xor_sync(0xffffffffu, m0, 1));
        m0 = fmaxf(m0, __shfl_xor_sync(0xffffffffu, m0, 2));
        m1 = fmaxf(m1, __shfl_xor_sync(0xffffffffu, m1, 1));
        m1 = fmaxf(m1, __shfl_xor_sync(0xffffffffu, m1, 2));
        float mn0 = fmaxf(mr0, m0), mn1 = fmaxf(mr1, m1);
        float a0 = exp2f(mr0 - mn0), a1 = exp2f(mr1 - mn1);
        mr0 = mn0; mr1 = mn1;
        float sum0 = 0.f, sum1 = 0.f;
#pragma unroll
        for (int t = 0; t < 8; t++) {
            s[t][0] = exp2f(s[t][0] - mn0);
            s[t][1] = exp2f(s[t][1] - mn0);
            s[t][2] = exp2f(s[t][2] - mn1);
            s[t][3] = exp2f(s[t][3] - mn1);
            sum0 += s[t][0] + s[t][1];
            sum1 += s[t][2] + s[t][3];
        }
        sum0 += __shfl_xor_sync(0xffffffffu, sum0, 1);
        sum0 += __shfl_xor_sync(0xffffffffu, sum0, 2);
        sum1 += __shfl_xor_sync(0xffffffffu, sum1, 1);
        sum1 += __shfl_xor_sync(0xffffffffu, sum1, 2);
        lr0 = lr0 * a0 + sum0;
        lr1 = lr1 * a1 + sum1;
#pragma unroll
        for (int t = 0; t < 8; t++) {
            o[t][0] *= a0; o[t][1] *= a0;
            o[t][2] *= a1; o[t][3] *= a1;
        }

        // ---- P: C-frag -> A-frag, fp16 hi/lo split ----
        uint32_t ph[4][4], pl[4][4];
#pragma unroll
        for (int kc = 0; kc < 4; kc++) {
            split2h(s[2 * kc][0], s[2 * kc][1], ph[kc][0], pl[kc][0]);
            split2h(s[2 * kc][2], s[2 * kc][3], ph[kc][1], pl[kc][1]);
            split2h(s[2 * kc + 1][0], s[2 * kc + 1][1], ph[kc][2], pl[kc][2]);
            split2h(s[2 * kc + 1][2], s[2 * kc + 1][3], ph[kc][3], pl[kc][3]);
        }

        // ---- O += P V (2 products, hoisted V fragments) ----
#pragma unroll
        for (int kc = 0; kc < 4; kc++) {
            uint32_t vv[8][2];
#pragma unroll
            for (int nd = 0; nd < 4; nd++) {
                uint32_t r0, r1, r2, r3;
                ldmx4t(r0, r1, r2, r3, lda(bV, kc * 16, nd * 16));
                vv[nd * 2 + 0][0] = r0; vv[nd * 2 + 0][1] = r1;
                vv[nd * 2 + 1][0] = r2; vv[nd * 2 + 1][1] = r3;
            }
#pragma unroll
            for (int t = 0; t < 8; t++) mma16816(o[t], ph[kc], vv[t]);
#pragma unroll
            for (int t = 0; t < 8; t++) mma16816(o[t], pl[kc], vv[t]);
        }
    }

    // ---- epilogue: normalize, fp16 hi/lo split, store [B,N,E] ----
    const float i0 = 1.f / lr0, i1 = 1.f / lr1;
    const int qr0 = qbase + w * 16 + grp;
    const size_t ro0 = (bN + qr0) * E_;
    const size_t ro1 = (bN + qr0 + 8) * E_;
#pragma unroll
    for (int t = 0; t < 8; t++) {
        int col = h * 64 + t * 8 + 2 * tig;
        uint32_t hi, lo;
        split2h(o[t][0] * i0, o[t][1] * i0, hi, lo);
        *(uint32_t*)(Oh + ro0 + col) = hi;
        *(uint32_t*)(Ol + ro0 + col) = lo;
        split2h(o[t][2] * i1, o[t][3] * i1, hi, lo);
        *(uint32_t*)(Oh + ro1 + col) = hi;
        *(uint32_t*)(Ol + ro1 + col) = lo;
    }
}

// ---------------------------------------------------------------------------
extern "C" void kernel_launch(void* const* d_in, const int* in_sizes, int n_in,
                              void* d_out, int out_size)
{
    const float* xq = (const float*)d_in[0];
    const float* xk = (const float*)d_in[1];
    const float* xv = (const float*)d_in[2];
    // d_in[3] = attn_mask (causal, recomputed analytically) — unused
    const float* Wq = (const float*)d_in[4];
    const float* Wk = (const float*)d_in[5];
    const float* Wv = (const float*)d_in[6];
    const float* Wo = (const float*)d_in[7];
    const float* bo = (const float*)d_in[8];
    float* out = (float*)d_out;

    __half *xqh, *xql, *xkh, *xkl, *xvh, *xvl;
    __half *Qh, *Ql, *Kb, *Vb, *Ah, *Al;
    __half *Wqh, *Wkh, *Wvh, *Woh;
    cudaGetSymbolAddress((void**)&xqh, g_xqh);
    cudaGetSymbolAddress((void**)&xql, g_xql);
    cudaGetSymbolAddress((void**)&xkh, g_xkh);
    cudaGetSymbolAddress((void**)&xkl, g_xkl);
    cudaGetSymbolAddress((void**)&xvh, g_xvh);
    cudaGetSymbolAddress((void**)&xvl, g_xvl);
    cudaGetSymbolAddress((void**)&Qh, g_Qh);
    cudaGetSymbolAddress((void**)&Ql, g_Ql);
    cudaGetSymbolAddress((void**)&Kb, g_K);
    cudaGetSymbolAddress((void**)&Vb, g_V);
    cudaGetSymbolAddress((void**)&Ah, g_Ah);
    cudaGetSymbolAddress((void**)&Al, g_Al);
    cudaGetSymbolAddress((void**)&Wqh, g_Wq);
    cudaGetSymbolAddress((void**)&Wkh, g_Wk);
    cudaGetSymbolAddress((void**)&Wvh, g_Wv);
    cudaGetSymbolAddress((void**)&Woh, g_Wo);

    cudaFuncSetAttribute(gemm_tc, cudaFuncAttributeMaxDynamicSharedMemorySize,
                         GSMEM_SZ);
    cudaFuncSetAttribute(attn_mma, cudaFuncAttributeMaxDynamicSharedMemorySize,
                         ASMEM);

    // Prepass conversions
    const int nx4 = MTOT * E_ / 4;
    const int nw4 = E_ * E_ / 4;
    convert_split_h<<<nx4 / 256, 256>>>(xq, xqh, xql, nx4);
    convert_split_h<<<nx4 / 256, 256>>>(xk, xkh, xkl, nx4);
    convert_split_h<<<nx4 / 256, 256>>>(xv, xvh, xvl, nx4);
    convert_h<<<nw4 / 256, 256>>>(Wq, Wqh, nw4);
    convert_h<<<nw4 / 256, 256>>>(Wk, Wkh, nw4);
    convert_h<<<nw4 / 256, 256>>>(Wv, Wvh, nw4);
    convert_h<<<nw4 / 256, 256>>>(Wo, Woh, nw4);

    dim3 gblock(256);
    dim3 ggrid(E_ / BN, MTOT / BM);        // (8, 64)

    // Projections: Q -> fp16 hi/lo (pre-scaled by log2e/sqrt(D)); K,V -> fp16
    gemm_tc<<<ggrid, gblock, GSMEM_SZ>>>(xqh, xql, Wqh, nullptr, nullptr,
                                         Qh, Ql, SCALE_LOG2E, E_);
    gemm_tc<<<ggrid, gblock, GSMEM_SZ>>>(xkh, xkl, Wkh, nullptr, nullptr,
                                         Kb, nullptr, 1.0f, E_);
    gemm_tc<<<ggrid, gblock, GSMEM_SZ>>>(xvh, xvl, Wvh, nullptr, nullptr,
                                         Vb, nullptr, 1.0f, E_);

    dim3 agrid(N_ / 128, H_, B_);          // (16, 16, 4)
    attn_mma<<<agrid, 256, ASMEM>>>(Qh, Ql, Kb, Vb, Ah, Al);

    // Output projection -> fp32 + bias
    gemm_tc<<<ggrid, gblock, GSMEM_SZ>>>(Ah, Al, Woh, bo, out,
                                         nullptr, nullptr, 1.0f, E_);
}

// round 12
// speedup vs baseline: 1.7780x; 1.1829x over previous
#include <cuda_runtime.h>
#include <cuda_fp16.h>
#include <cstdint>

#define B_ 4
#define N_ 2048
#define E_ 1024
#define H_ 16
#define D_ 64
#define SCALE_ 0.125f            // 1/sqrt(64)
#define SCALE_LOG2E 0.18033688f  // 0.125 * log2(e)
#define MTOT (B_ * N_)           // 8192

// ---------------------------------------------------------------------------
// Scratch (allocation-free rule: __device__ globals)
// ---------------------------------------------------------------------------
__device__ __half g_xqh[(size_t)MTOT * E_];
__device__ __half g_xql[(size_t)MTOT * E_];
__device__ __half g_xkh[(size_t)MTOT * E_];
__device__ __half g_xkl[(size_t)MTOT * E_];
__device__ __half g_xvh[(size_t)MTOT * E_];
__device__ __half g_xvl[(size_t)MTOT * E_];

__device__ __half g_Qh[(size_t)MTOT * E_];
__device__ __half g_Ql[(size_t)MTOT * E_];
__device__ __half g_K[(size_t)MTOT * E_];
__device__ __half g_V[(size_t)MTOT * E_];
__device__ __half g_A[(size_t)MTOT * E_];

__device__ __half g_Wq[(size_t)E_ * E_];
__device__ __half g_Wk[(size_t)E_ * E_];
__device__ __half g_Wv[(size_t)E_ * E_];
__device__ __half g_Wo[(size_t)E_ * E_];

// ---------------------------------------------------------------------------
// helpers
// ---------------------------------------------------------------------------
__device__ __forceinline__ uint32_t smem_u32(const void* p) {
    uint32_t a;
    asm("{ .reg .u64 t; cvta.to.shared.u64 t, %1; cvt.u32.u64 %0, t; }"
        : "=r"(a) : "l"(p));
    return a;
}
__device__ __forceinline__ void cp16(uint32_t sa, const void* ga) {
    asm volatile("cp.async.cg.shared.global [%0], [%1], 16;"
                 :: "r"(sa), "l"(ga));
}
__device__ __forceinline__ void cp_commit() {
    asm volatile("cp.async.commit_group;");
}
__device__ __forceinline__ void cp_wait1() {
    asm volatile("cp.async.wait_group 1;");
}
__device__ __forceinline__ void cp_wait0() {
    asm volatile("cp.async.wait_group 0;");
}
__device__ __forceinline__ void ldmx4(uint32_t& r0, uint32_t& r1,
                                      uint32_t& r2, uint32_t& r3, uint32_t a) {
    asm volatile("ldmatrix.sync.aligned.m8n8.x4.shared.b16 {%0,%1,%2,%3}, [%4];"
                 : "=r"(r0), "=r"(r1), "=r"(r2), "=r"(r3) : "r"(a));
}
__device__ __forceinline__ void ldmx4t(uint32_t& r0, uint32_t& r1,
                                       uint32_t& r2, uint32_t& r3, uint32_t a) {
    asm volatile("ldmatrix.sync.aligned.m8n8.x4.trans.shared.b16 {%0,%1,%2,%3}, [%4];"
                 : "=r"(r0), "=r"(r1), "=r"(r2), "=r"(r3) : "r"(a));
}
__device__ __forceinline__ void mma16816(float* d, const uint32_t* a,
                                         const uint32_t* b) {
    asm volatile(
        "mma.sync.aligned.m16n8k16.row.col.f32.f16.f16.f32 "
        "{%0,%1,%2,%3}, {%4,%5,%6,%7}, {%8,%9}, {%0,%1,%2,%3};"
        : "+f"(d[0]), "+f"(d[1]), "+f"(d[2]), "+f"(d[3])
        : "r"(a[0]), "r"(a[1]), "r"(a[2]), "r"(a[3]), "r"(b[0]), "r"(b[1]));
}
// split (a,b) into fp16x2 hi + lo words
__device__ __forceinline__ void split2h(float a, float b, uint32_t& hi, uint32_t& lo) {
    __half2 h = __floats2half2_rn(a, b);
    __half2 l = __floats2half2_rn(a - __half2float(h.x), b - __half2float(h.y));
    hi = *(uint32_t*)&h;
    lo = *(uint32_t*)&l;
}
__device__ __forceinline__ uint32_t pack2h(float a, float b) {
    __half2 h = __floats2half2_rn(a, b);
    return *(uint32_t*)&h;
}

// ---------------------------------------------------------------------------
// Prepass: fp32 -> (hi, lo) fp16 split, and fp32 -> fp16 single.
// ---------------------------------------------------------------------------
__global__ __launch_bounds__(256) void convert_split_h(
    const float* __restrict__ src, __half* __restrict__ h,
    __half* __restrict__ l, int n4)
{
    int i = blockIdx.x * 256 + threadIdx.x;
    if (i >= n4) return;
    float4 v = ((const float4*)src)[i];
    uint32_t h01, l01, h23, l23;
    split2h(v.x, v.y, h01, l01);
    split2h(v.z, v.w, h23, l23);
    ((uint2*)h)[i] = make_uint2(h01, h23);
    ((uint2*)l)[i] = make_uint2(l01, l23);
}
__global__ __launch_bounds__(256) void convert_h(
    const float* __restrict__ src, __half* __restrict__ h, int n4)
{
    int i = blockIdx.x * 256 + threadIdx.x;
    if (i >= n4) return;
    float4 v = ((const float4*)src)[i];
    ((uint2*)h)[i] = make_uint2(pack2h(v.x, v.y), pack2h(v.z, v.w));
}

// ===========================================================================
// Shared GEMM tiling constants
// ===========================================================================
#define BM 128
#define BN 128
#define BKC 32
#define KTOT 1024
#define NCHUNK (KTOT / BKC)
#define LDT 40
#define TILE_B (128 * LDT * 2)     // 10240

__device__ __forceinline__ uint32_t lm_addr(uint32_t base_b, int row0, int kseg0) {
    int L = threadIdx.x & 31;
    int mat = L >> 3;
    int r = (L & 7) + ((mat & 1) << 3);
    int ks = kseg0 + (mat >> 1);
    return base_b + (uint32_t)(row0 + r) * (LDT * 2) + ks * 16;
}

// ===========================================================================
// 2-product GEMM: C = (Xh+Xl) @ W^T. fp32 accum. 3 tiles/stage, 2 stages.
// Epilogue: fp16 hi/lo (Oh+Ol) or fp16 single (Oh only).
// ===========================================================================
#define STAGE2_B (3 * TILE_B)       // 30720
#define GSMEM2_SZ (2 * STAGE2_B)    // 61440

__global__ __launch_bounds__(256, 2) void gemm_tc2(
    const __half* __restrict__ Xh, const __half* __restrict__ Xl,
    const __half* __restrict__ W,
    __half* __restrict__ Oh, __half* __restrict__ Ol,
    float scale, int Nn)
{
    extern __shared__ char dynsm[];
    const uint32_t smb = smem_u32(dynsm);
    const int tid = threadIdx.x;
    const int bm = blockIdx.y * BM;
    const int bn = blockIdx.x * BN;
    const int w = tid >> 5;
    const int wm = w >> 2;
    const int wn = w & 3;

    const char* tb[3];
    tb[0] = (const char*)(Xh + (size_t)bm * KTOT);
    tb[1] = (const char*)(Xl + (size_t)bm * KTOT);
    tb[2] = (const char*)(W + (size_t)bn * KTOT);

    float acc[4][4][4];
#pragma unroll
    for (int i = 0; i < 4; i++)
#pragma unroll
        for (int j = 0; j < 4; j++)
#pragma unroll
            for (int t = 0; t < 4; t++) acc[i][j][t] = 0.f;

    auto issue = [&](int c, int s) {
#pragma unroll
        for (int i = 0; i < 6; i++) {
            int sid = tid + 256 * i;          // 0..1535
            int tile = sid >> 9;              // 0 Xh, 1 Xl, 2 W
            int r = (sid >> 2) & 127;
            int seg = sid & 3;
            const char* base = (tile == 0) ? tb[0] : (tile == 1) ? tb[1] : tb[2];
            uint32_t sa = smb + (uint32_t)s * STAGE2_B + (uint32_t)tile * TILE_B
                        + (uint32_t)r * (LDT * 2) + seg * 16;
            const char* ga = base + (size_t)r * (KTOT * 2) + c * (BKC * 2) + seg * 16;
            cp16(sa, ga);
        }
        cp_commit();
    };

    issue(0, 0);

    for (int c = 0; c < NCHUNK; c++) {
        const int st = c & 1;
        if (c + 1 < NCHUNK) {
            issue(c + 1, st ^ 1);
            cp_wait1();
        } else {
            cp_wait0();
        }
        __syncthreads();

        const uint32_t bXh = smb + (uint32_t)st * STAGE2_B;
        const uint32_t bXl = bXh + TILE_B;
        const uint32_t bW  = bXh + 2 * TILE_B;

#pragma unroll
        for (int ks = 0; ks < 2; ks++) {
            const int kseg0 = ks * 2;
            uint32_t ah[4][4], al[4][4], bw[4][2];
#pragma unroll
            for (int mt = 0; mt < 4; mt++) {
                ldmx4(ah[mt][0], ah[mt][1], ah[mt][2], ah[mt][3],
                      lm_addr(bXh, wm * 64 + mt * 16, kseg0));
                ldmx4(al[mt][0], al[mt][1], al[mt][2], al[mt][3],
                      lm_addr(bXl, wm * 64 + mt * 16, kseg0));
            }
#pragma unroll
            for (int np = 0; np < 2; np++) {
                uint32_t r0, r1, r2, r3;
                ldmx4(r0, r1, r2, r3, lm_addr(bW, wn * 32 + np * 16, kseg0));
                bw[np * 2 + 0][0] = r0; bw[np * 2 + 0][1] = r2;
                bw[np * 2 + 1][0] = r1; bw[np * 2 + 1][1] = r3;
            }
#pragma unroll
            for (int mt = 0; mt < 4; mt++)
#pragma unroll
                for (int nt = 0; nt < 4; nt++)
                    mma16816(acc[mt][nt], ah[mt], bw[nt]);
#pragma unroll
            for (int mt = 0; mt < 4; mt++)
#pragma unroll
                for (int nt = 0; nt < 4; nt++)
                    mma16816(acc[mt][nt], al[mt], bw[nt]);
        }
        __syncthreads();
    }

    const int lid = tid & 31;
    const int grp = lid >> 2;
    const int tig = lid & 3;
#pragma unroll
    for (int mt = 0; mt < 4; mt++) {
#pragma unroll
        for (int nt = 0; nt < 4; nt++) {
            int row = bm + wm * 64 + mt * 16 + grp;
            int col = bn + wn * 32 + nt * 8 + tig * 2;
            float a0 = acc[mt][nt][0] * scale, a1 = acc[mt][nt][1] * scale;
            float a2 = acc[mt][nt][2] * scale, a3 = acc[mt][nt][3] * scale;
            if (Ol != nullptr) {
                uint32_t hi, lo;
                split2h(a0, a1, hi, lo);
                *(uint32_t*)(Oh + (size_t)row * Nn + col) = hi;
                *(uint32_t*)(Ol + (size_t)row * Nn + col) = lo;
                split2h(a2, a3, hi, lo);
                *(uint32_t*)(Oh + (size_t)(row + 8) * Nn + col) = hi;
                *(uint32_t*)(Ol + (size_t)(row + 8) * Nn + col) = lo;
            } else {
                *(uint32_t*)(Oh + (size_t)row * Nn + col) = pack2h(a0, a1);
                *(uint32_t*)(Oh + (size_t)(row + 8) * Nn + col) = pack2h(a2, a3);
            }
        }
    }
}

// ===========================================================================
// 1-product GEMM: C = X @ W^T + bias (fp32 out). 2 tiles/stage, 2 stages.
// Used for the output projection (A and Wo both single fp16).
// ===========================================================================
#define STAGE1_B (2 * TILE_B)       // 20480
#define GSMEM1_SZ (2 * STAGE1_B)    // 40960

__global__ __launch_bounds__(256, 2) void gemm_tc1(
    const __half* __restrict__ X, const __half* __restrict__ W,
    const float* __restrict__ bias, float* __restrict__ Cf, int Nn)
{
    extern __shared__ char dynsm[];
    const uint32_t smb = smem_u32(dynsm);
    const int tid = threadIdx.x;
    const int bm = blockIdx.y * BM;
    const int bn = blockIdx.x * BN;
    const int w = tid >> 5;
    const int wm = w >> 2;
    const int wn = w & 3;

    const char* tbX = (const char*)(X + (size_t)bm * KTOT);
    const char* tbW = (const char*)(W + (size_t)bn * KTOT);

    float acc[4][4][4];
#pragma unroll
    for (int i = 0; i < 4; i++)
#pragma unroll
        for (int j = 0; j < 4; j++)
#pragma unroll
            for (int t = 0; t < 4; t++) acc[i][j][t] = 0.f;

    auto issue = [&](int c, int s) {
#pragma unroll
        for (int i = 0; i < 4; i++) {
            int sid = tid + 256 * i;          // 0..1023
            int tile = sid >> 9;              // 0 X, 1 W
            int r = (sid >> 2) & 127;
            int seg = sid & 3;
            const char* base = tile ? tbW : tbX;
            uint32_t sa = smb + (uint32_t)s * STAGE1_B + (uint32_t)tile * TILE_B
                        + (uint32_t)r * (LDT * 2) + seg * 16;
            const char* ga = base + (size_t)r * (KTOT * 2) + c * (BKC * 2) + seg * 16;
            cp16(sa, ga);
        }
        cp_commit();
    };

    issue(0, 0);

    for (int c = 0; c < NCHUNK; c++) {
        const int st = c & 1;
        if (c + 1 < NCHUNK) {
            issue(c + 1, st ^ 1);
            cp_wait1();
        } else {
            cp_wait0();
        }
        __syncthreads();

        const uint32_t bX = smb + (uint32_t)st * STAGE1_B;
        const uint32_t bW = bX + TILE_B;

#pragma unroll
        for (int ks = 0; ks < 2; ks++) {
            const int kseg0 = ks * 2;
            uint32_t ax[4][4], bw[4][2];
#pragma unroll
            for (int mt = 0; mt < 4; mt++)
                ldmx4(ax[mt][0], ax[mt][1], ax[mt][2], ax[mt][3],
                      lm_addr(bX, wm * 64 + mt * 16, kseg0));
#pragma unroll
            for (int np = 0; np < 2; np++) {
                uint32_t r0, r1, r2, r3;
                ldmx4(r0, r1, r2, r3, lm_addr(bW, wn * 32 + np * 16, kseg0));
                bw[np * 2 + 0][0] = r0; bw[np * 2 + 0][1] = r2;
                bw[np * 2 + 1][0] = r1; bw[np * 2 + 1][1] = r3;
            }
#pragma unroll
            for (int mt = 0; mt < 4; mt++)
#pragma unroll
                for (int nt = 0; nt < 4; nt++)
                    mma16816(acc[mt][nt], ax[mt], bw[nt]);
        }
        __syncthreads();
    }

    const int lid = tid & 31;
    const int grp = lid >> 2;
    const int tig = lid & 3;
#pragma unroll
    for (int mt = 0; mt < 4; mt++) {
#pragma unroll
        for (int nt = 0; nt < 4; nt++) {
            int row = bm + wm * 64 + mt * 16 + grp;
            int col = bn + wn * 32 + nt * 8 + tig * 2;
            float b0 = bias[col], b1 = bias[col + 1];
            *(float2*)(Cf + (size_t)row * Nn + col) =
                make_float2(acc[mt][nt][0] + b0, acc[mt][nt][1] + b1);
            *(float2*)(Cf + (size_t)(row + 8) * Nn + col) =
                make_float2(acc[mt][nt][2] + b0, acc[mt][nt][3] + b1);
        }
    }
}

// ===========================================================================
// Tensor-core causal flash attention, fp16. q-tile 128 rows (8 warps).
// S = (Qh+Ql)K^T (2 products); O = P V (1 product, P single fp16).
// Output A single fp16. K/V double-buffered cp.async; exp2 softmax.
// ===========================================================================
#define ALDT 144                   // smem row stride bytes
#define AQ_TILE (128 * ALDT)       // 18432
#define AKV_TILE (64 * ALDT)       // 9216
#define AOFF_QH 0
#define AOFF_QL AQ_TILE
#define AOFF_ST (2 * AQ_TILE)      // 36864
#define ASTAGE (2 * AKV_TILE)      // 18432
#define ASMEM (AOFF_ST + 2 * ASTAGE)  // 73728

__device__ __forceinline__ uint32_t lda(uint32_t base, int r0, int c0) {
    int L = threadIdx.x & 31;
    int mat = L >> 3;
    int r = r0 + (L & 7) + ((mat & 1) << 3);
    int c = c0 + ((mat >> 1) << 3);
    return base + (uint32_t)r * ALDT + c * 2;
}

__global__ __launch_bounds__(256) void attn_mma(
    const __half* __restrict__ Qh, const __half* __restrict__ Ql,
    const __half* __restrict__ K, const __half* __restrict__ V,
    __half* __restrict__ O)
{
    extern __shared__ char dynsm[];
    const uint32_t smb = smem_u32(dynsm);
    const int tid = threadIdx.x;
    const int w = tid >> 5;
    const int lid = tid & 31;
    const int grp = lid >> 2;
    const int tig = lid & 3;
    const int iblk = (gridDim.x - 1) - blockIdx.x;   // heavy blocks first
    const int h = blockIdx.y;
    const int b = blockIdx.z;
    const int qbase = iblk * 128;
    const int jmax = 2 * iblk + 1;
    const size_t bN = (size_t)b * N_;

    auto issue_stage = [&](int s, int kbase) {
#pragma unroll
        for (int i = 0; i < 4; i++) {
            int sid = tid + 256 * i;          // 0..1023
            int tile = sid >> 9;              // 0 K, 1 V
            int r = (sid >> 3) & 63;
            int seg = sid & 7;
            const __half* gp = tile ? V : K;
            const char* ga = (const char*)(gp + (bN + kbase + r) * E_ + h * 64)
                           + seg * 16;
            cp16(smb + AOFF_ST + (uint32_t)s * ASTAGE + (uint32_t)tile * AKV_TILE
                 + (uint32_t)r * ALDT + seg * 16, ga);
        }
        cp_commit();
    };

    // prologue: Q tiles (128 rows x 64 cols, hi+lo) + KV stage 0
    {
#pragma unroll
        for (int i = 0; i < 8; i++) {
            int sid = tid + 256 * i;          // 0..2047
            int tile = sid >> 10;             // 0 Qh, 1 Ql
            int r = (sid >> 3) & 127;
            int seg = sid & 7;
            const __half* gp = tile ? Ql : Qh;
            const char* ga = (const char*)(gp + (bN + qbase + r) * E_ + h * 64)
                           + seg * 16;
            cp16(smb + (tile ? AOFF_QL : AOFF_QH) + (uint32_t)r * ALDT + seg * 16, ga);
        }
    }
    issue_stage(0, 0);

    uint32_t qh[4][4], ql[4][4];
    float o[8][4];
#pragma unroll
    for (int t = 0; t < 8; t++)
#pragma unroll
        for (int c = 0; c < 4; c++) o[t][c] = 0.f;
    float mr0 = -1e30f, mr1 = -1e30f, lr0 = 0.f, lr1 = 0.f;

    for (int j = 0; j <= jmax; j++) {
        cp_wait0();
        __syncthreads();
        if (j == 0) {
#pragma unroll
            for (int kc = 0; kc < 4; kc++) {
                ldmx4(qh[kc][0], qh[kc][1], qh[kc][2], qh[kc][3],
                      lda(smb + AOFF_QH, w * 16, kc * 16));
                ldmx4(ql[kc][0], ql[kc][1], ql[kc][2], ql[kc][3],
                      lda(smb + AOFF_QL, w * 16, kc * 16));
            }
        }
        if (j < jmax) issue_stage((j + 1) & 1, (j + 1) * 64);

        const uint32_t bK = smb + AOFF_ST + (uint32_t)(j & 1) * ASTAGE;
        const uint32_t bV = bK + AKV_TILE;

        // ---- S = Q K^T (2 products, hoisted K fragments) ----
        float s[8][4];
#pragma unroll
        for (int t = 0; t < 8; t++)
#pragma unroll
            for (int c = 0; c < 4; c++) s[t][c] = 0.f;
#pragma unroll
        for (int kc = 0; kc < 4; kc++) {
            uint32_t bk[8][2];
#pragma unroll
            for (int np = 0; np < 4; np++) {
                uint32_t r0, r1, r2, r3;
                ldmx4(r0, r1, r2, r3, lda(bK, np * 16, kc * 16));
                bk[np * 2 + 0][0] = r0; bk[np * 2 + 0][1] = r2;
                bk[np * 2 + 1][0] = r1; bk[np * 2 + 1][1] = r3;
            }
#pragma unroll
            for (int t = 0; t < 8; t++) mma16816(s[t], qh[kc], bk[t]);
#pragma unroll
            for (int t = 0; t < 8; t++) mma16816(s[t], ql[kc], bk[t]);
        }

        // ---- causal mask (only kv-blocks crossing the diagonal) ----
        if (j >= 2 * iblk) {
            const int row0 = qbase + w * 16 + grp;
            const int row1 = row0 + 8;
            const int cb = j * 64;
#pragma unroll
            for (int t = 0; t < 8; t++) {
                int col = cb + t * 8 + 2 * tig;
                if (col > row0) s[t][0] = -1e30f;
                if (col + 1 > row0) s[t][1] = -1e30f;
                if (col > row1) s[t][2] = -1e30f;
                if (col + 1 > row1) s[t][3] = -1e30f;
            }
        }

        // ---- online softmax (base-2) ----
        float m0 = -1e30f, m1 = -1e30f;
#pragma unroll
        for (int t = 0; t < 8; t++) {
            m0 = fmaxf(m0, fmaxf(s[t][0], s[t][1]));
            m1 = fmaxf(m1, fmaxf(s[t][2], s[t][3]));
        }
        m0 = fmaxf(m0, __shfl_xor_sync(0xffffffffu, m0, 1));
        m0 = fmaxf(m0, __shfl_xor_sync(0xffffffffu, m0, 2));
        m1 = fmaxf(m1, __shfl_xor_sync(0xffffffffu, m1, 1));
        m1 = fmaxf(m1, __shfl_xor_sync(0xffffffffu, m1, 2));
        float mn0 = fmaxf(mr0, m0), mn1 = fmaxf(mr1, m1);
        float a0 = exp2f(mr0 - mn0), a1 = exp2f(mr1 - mn1);
        mr0 = mn0; mr1 = mn1;
        float sum0 = 0.f, sum1 = 0.f;
#pragma unroll
        for (int t = 0; t < 8; t++) {
            s[t][0] = exp2f(s[t][0] - mn0);
            s[t][1] = exp2f(s[t][1] - mn0);
            s[t][2] = exp2f(s[t][2] - mn1);
            s[t][3] = exp2f(s[t][3] - mn1);
            sum0 += s[t][0] + s[t][1];
            sum1 += s[t][2] + s[t][3];
        }
        sum0 += __shfl_xor_sync(0xffffffffu, sum0, 1);
        sum0 += __shfl_xor_sync(0xffffffffu, sum0, 2);
        sum1 += __shfl_xor_sync(0xffffffffu, sum1, 1);
        sum1 += __shfl_xor_sync(0xffffffffu, sum1, 2);
        lr0 = lr0 * a0 + sum0;
        lr1 = lr1 * a1 + sum1;
#pragma unroll
        for (int t = 0; t < 8; t++) {
            o[t][0] *= a0; o[t][1] *= a0;
            o[t][2] *= a1; o[t][3] *= a1;
        }

        // ---- P: C-frag -> A-frag, single fp16 ----
        uint32_t ph[4][4];
#pragma unroll
        for (int kc = 0; kc < 4; kc++) {
            ph[kc][0] = pack2h(s[2 * kc][0], s[2 * kc][1]);
            ph[kc][1] = pack2h(s[2 * kc][2], s[2 * kc][3]);
            ph[kc][2] = pack2h(s[2 * kc + 1][0], s[2 * kc + 1][1]);
            ph[kc][3] = pack2h(s[2 * kc + 1][2], s[2 * kc + 1][3]);
        }

        // ---- O += P V (1 product, hoisted V fragments) ----
#pragma unroll
        for (int kc = 0; kc < 4; kc++) {
            uint32_t vv[8][2];
#pragma unroll
            for (int nd = 0; nd < 4; nd++) {
                uint32_t r0, r1, r2, r3;
                ldmx4t(r0, r1, r2, r3, lda(bV, kc * 16, nd * 16));
                vv[nd * 2 + 0][0] = r0; vv[nd * 2 + 0][1] = r1;
                vv[nd * 2 + 1][0] = r2; vv[nd * 2 + 1][1] = r3;
            }
#pragma unroll
            for (int t = 0; t < 8; t++) mma16816(o[t], ph[kc], vv[t]);
        }
    }

    // ---- epilogue: normalize, single fp16, store [B,N,E] ----
    const float i0 = 1.f / lr0, i1 = 1.f / lr1;
    const int qr0 = qbase + w * 16 + grp;
    const size_t ro0 = (bN + qr0) * E_;
    const size_t ro1 = (bN + qr0 + 8) * E_;
#pragma unroll
    for (int t = 0; t < 8; t++) {
        int col = h * 64 + t * 8 + 2 * tig;
        *(uint32_t*)(O + ro0 + col) = pack2h(o[t][0] * i0, o[t][1] * i0);
        *(uint32_t*)(O + ro1 + col) = pack2h(o[t][2] * i1, o[t][3] * i1);
    }
}

// ---------------------------------------------------------------------------
extern "C" void kernel_launch(void* const* d_in, const int* in_sizes, int n_in,
                              void* d_out, int out_size)
{
    const float* xq = (const float*)d_in[0];
    const float* xk = (const float*)d_in[1];
    const float* xv = (const float*)d_in[2];
    // d_in[3] = attn_mask (causal, recomputed analytically) — unused
    const float* Wq = (const float*)d_in[4];
    const float* Wk = (const float*)d_in[5];
    const float* Wv = (const float*)d_in[6];
    const float* Wo = (const float*)d_in[7];
    const float* bo = (const float*)d_in[8];
    float* out = (float*)d_out;

    __half *xqh, *xql, *xkh, *xkl, *xvh, *xvl;
    __half *Qh, *Ql, *Kb, *Vb, *Ab;
    __half *Wqh, *Wkh, *Wvh, *Woh;
    cudaGetSymbolAddress((void**)&xqh, g_xqh);
    cudaGetSymbolAddress((void**)&xql, g_xql);
    cudaGetSymbolAddress((void**)&xkh, g_xkh);
    cudaGetSymbolAddress((void**)&xkl, g_xkl);
    cudaGetSymbolAddress((void**)&xvh, g_xvh);
    cudaGetSymbolAddress((void**)&xvl, g_xvl);
    cudaGetSymbolAddress((void**)&Qh, g_Qh);
    cudaGetSymbolAddress((void**)&Ql, g_Ql);
    cudaGetSymbolAddress((void**)&Kb, g_K);
    cudaGetSymbolAddress((void**)&Vb, g_V);
    cudaGetSymbolAddress((void**)&Ab, g_A);
    cudaGetSymbolAddress((void**)&Wqh, g_Wq);
    cudaGetSymbolAddress((void**)&Wkh, g_Wk);
    cudaGetSymbolAddress((void**)&Wvh, g_Wv);
    cudaGetSymbolAddress((void**)&Woh, g_Wo);

    cudaFuncSetAttribute(gemm_tc2, cudaFuncAttributeMaxDynamicSharedMemorySize,
                         GSMEM2_SZ);
    cudaFuncSetAttribute(gemm_tc1, cudaFuncAttributeMaxDynamicSharedMemorySize,
                         GSMEM1_SZ);
    cudaFuncSetAttribute(attn_mma, cudaFuncAttributeMaxDynamicSharedMemorySize,
                         ASMEM);

    // Prepass conversions
    const int nx4 = MTOT * E_ / 4;
    const int nw4 = E_ * E_ / 4;
    convert_split_h<<<nx4 / 256, 256>>>(xq, xqh, xql, nx4);
    convert_split_h<<<nx4 / 256, 256>>>(xk, xkh, xkl, nx4);
    convert_split_h<<<nx4 / 256, 256>>>(xv, xvh, xvl, nx4);
    convert_h<<<nw4 / 256, 256>>>(Wq, Wqh, nw4);
    convert_h<<<nw4 / 256, 256>>>(Wk, Wkh, nw4);
    convert_h<<<nw4 / 256, 256>>>(Wv, Wvh, nw4);
    convert_h<<<nw4 / 256, 256>>>(Wo, Woh, nw4);

    dim3 gblock(256);
    dim3 ggrid(E_ / BN, MTOT / BM);        // (8, 64)

    // Projections: Q -> fp16 hi/lo (pre-scaled by log2e/sqrt(D)); K,V -> fp16
    gemm_tc2<<<ggrid, gblock, GSMEM2_SZ>>>(xqh, xql, Wqh, Qh, Ql,
                                           SCALE_LOG2E, E_);
    gemm_tc2<<<ggrid, gblock, GSMEM2_SZ>>>(xkh, xkl, Wkh, Kb, nullptr,
                                           1.0f, E_);
    gemm_tc2<<<ggrid, gblock, GSMEM2_SZ>>>(xvh, xvl, Wvh, Vb, nullptr,
                                           1.0f, E_);

    dim3 agrid(N_ / 128, H_, B_);          // (16, 16, 4)
    attn_mma<<<agrid, 256, ASMEM>>>(Qh, Ql, Kb, Vb, Ab);

    // Output projection (single product) -> fp32 + bias
    gemm_tc1<<<ggrid, gblock, GSMEM1_SZ>>>(Ab, Woh, bo, out, E_);
}

// round 13
// speedup vs baseline: 2.1200x; 1.1923x over previous
#include <cuda_runtime.h>
#include <cuda_fp16.h>
#include <cstdint>

#define B_ 4
#define N_ 2048
#define E_ 1024
#define H_ 16
#define D_ 64
#define SCALE_ 0.125f            // 1/sqrt(64)
#define SCALE_LOG2E 0.18033688f  // 0.125 * log2(e)
#define MTOT (B_ * N_)           // 8192

// ---------------------------------------------------------------------------
// Scratch (allocation-free rule: __device__ globals)
// ---------------------------------------------------------------------------
__device__ __half g_xqh[(size_t)MTOT * E_];
__device__ __half g_xql[(size_t)MTOT * E_];
__device__ __half g_xk[(size_t)MTOT * E_];
__device__ __half g_xv[(size_t)MTOT * E_];

__device__ __half g_Qh[(size_t)MTOT * E_];
__device__ __half g_Ql[(size_t)MTOT * E_];
__device__ __half g_K[(size_t)MTOT * E_];
__device__ __half g_V[(size_t)MTOT * E_];
__device__ __half g_A[(size_t)MTOT * E_];

__device__ __half g_Wq[(size_t)E_ * E_];
__device__ __half g_Wk[(size_t)E_ * E_];
__device__ __half g_Wv[(size_t)E_ * E_];
__device__ __half g_Wo[(size_t)E_ * E_];

// ---------------------------------------------------------------------------
// helpers
// ---------------------------------------------------------------------------
__device__ __forceinline__ uint32_t smem_u32(const void* p) {
    uint32_t a;
    asm("{ .reg .u64 t; cvta.to.shared.u64 t, %1; cvt.u32.u64 %0, t; }"
        : "=r"(a) : "l"(p));
    return a;
}
__device__ __forceinline__ void cp16(uint32_t sa, const void* ga) {
    asm volatile("cp.async.cg.shared.global [%0], [%1], 16;"
                 :: "r"(sa), "l"(ga));
}
__device__ __forceinline__ void cp_commit() {
    asm volatile("cp.async.commit_group;");
}
__device__ __forceinline__ void cp_wait1() {
    asm volatile("cp.async.wait_group 1;");
}
__device__ __forceinline__ void cp_wait0() {
    asm volatile("cp.async.wait_group 0;");
}
__device__ __forceinline__ void ldmx4(uint32_t& r0, uint32_t& r1,
                                      uint32_t& r2, uint32_t& r3, uint32_t a) {
    asm volatile("ldmatrix.sync.aligned.m8n8.x4.shared.b16 {%0,%1,%2,%3}, [%4];"
                 : "=r"(r0), "=r"(r1), "=r"(r2), "=r"(r3) : "r"(a));
}
__device__ __forceinline__ void ldmx4t(uint32_t& r0, uint32_t& r1,
                                       uint32_t& r2, uint32_t& r3, uint32_t a) {
    asm volatile("ldmatrix.sync.aligned.m8n8.x4.trans.shared.b16 {%0,%1,%2,%3}, [%4];"
                 : "=r"(r0), "=r"(r1), "=r"(r2), "=r"(r3) : "r"(a));
}
__device__ __forceinline__ void mma16816(float* d, const uint32_t* a,
                                         const uint32_t* b) {
    asm volatile(
        "mma.sync.aligned.m16n8k16.row.col.f32.f16.f16.f32 "
        "{%0,%1,%2,%3}, {%4,%5,%6,%7}, {%8,%9}, {%0,%1,%2,%3};"
        : "+f"(d[0]), "+f"(d[1]), "+f"(d[2]), "+f"(d[3])
        : "r"(a[0]), "r"(a[1]), "r"(a[2]), "r"(a[3]), "r"(b[0]), "r"(b[1]));
}
// split (a,b) into fp16x2 hi + lo words
__device__ __forceinline__ void split2h(float a, float b, uint32_t& hi, uint32_t& lo) {
    __half2 h = __floats2half2_rn(a, b);
    __half2 l = __floats2half2_rn(a - __half2float(h.x), b - __half2float(h.y));
    hi = *(uint32_t*)&h;
    lo = *(uint32_t*)&l;
}
__device__ __forceinline__ uint32_t pack2h(float a, float b) {
    __half2 h = __floats2half2_rn(a, b);
    return *(uint32_t*)&h;
}

// ---------------------------------------------------------------------------
// Prepass: fp32 -> (hi, lo) fp16 split, and fp32 -> fp16 single.
// ---------------------------------------------------------------------------
__global__ __launch_bounds__(256) void convert_split_h(
    const float* __restrict__ src, __half* __restrict__ h,
    __half* __restrict__ l, int n4)
{
    int i = blockIdx.x * 256 + threadIdx.x;
    if (i >= n4) return;
    float4 v = ((const float4*)src)[i];
    uint32_t h01, l01, h23, l23;
    split2h(v.x, v.y, h01, l01);
    split2h(v.z, v.w, h23, l23);
    ((uint2*)h)[i] = make_uint2(h01, h23);
    ((uint2*)l)[i] = make_uint2(l01, l23);
}
__global__ __launch_bounds__(256) void convert_h(
    const float* __restrict__ src, __half* __restrict__ h, int n4)
{
    int i = blockIdx.x * 256 + threadIdx.x;
    if (i >= n4) return;
    float4 v = ((const float4*)src)[i];
    ((uint2*)h)[i] = make_uint2(pack2h(v.x, v.y), pack2h(v.z, v.w));
}

// ===========================================================================
// Shared GEMM tiling constants
// ===========================================================================
#define BM 128
#define BN 128
#define BKC 32
#define KTOT 1024
#define NCHUNK (KTOT / BKC)
#define LDT 40
#define TILE_B (128 * LDT * 2)     // 10240

__device__ __forceinline__ uint32_t lm_addr(uint32_t base_b, int row0, int kseg0) {
    int L = threadIdx.x & 31;
    int mat = L >> 3;
    int r = (L & 7) + ((mat & 1) << 3);
    int ks = kseg0 + (mat >> 1);
    return base_b + (uint32_t)(row0 + r) * (LDT * 2) + ks * 16;
}

// ===========================================================================
// 2-product GEMM: C = (Xh+Xl) @ W^T. fp32 accum. 3 tiles/stage, 2 stages.
// Epilogue: fp16 hi/lo (Oh+Ol).
// ===========================================================================
#define STAGE2_B (3 * TILE_B)       // 30720
#define GSMEM2_SZ (2 * STAGE2_B)    // 61440

__global__ __launch_bounds__(256, 2) void gemm_tc2(
    const __half* __restrict__ Xh, const __half* __restrict__ Xl,
    const __half* __restrict__ W,
    __half* __restrict__ Oh, __half* __restrict__ Ol,
    float scale, int Nn)
{
    extern __shared__ char dynsm[];
    const uint32_t smb = smem_u32(dynsm);
    const int tid = threadIdx.x;
    const int bm = blockIdx.y * BM;
    const int bn = blockIdx.x * BN;
    const int w = tid >> 5;
    const int wm = w >> 2;
    const int wn = w & 3;

    const char* tb[3];
    tb[0] = (const char*)(Xh + (size_t)bm * KTOT);
    tb[1] = (const char*)(Xl + (size_t)bm * KTOT);
    tb[2] = (const char*)(W + (size_t)bn * KTOT);

    float acc[4][4][4];
#pragma unroll
    for (int i = 0; i < 4; i++)
#pragma unroll
        for (int j = 0; j < 4; j++)
#pragma unroll
            for (int t = 0; t < 4; t++) acc[i][j][t] = 0.f;

    auto issue = [&](int c, int s) {
#pragma unroll
        for (int i = 0; i < 6; i++) {
            int sid = tid + 256 * i;          // 0..1535
            int tile = sid >> 9;              // 0 Xh, 1 Xl, 2 W
            int r = (sid >> 2) & 127;
            int seg = sid & 3;
            const char* base = (tile == 0) ? tb[0] : (tile == 1) ? tb[1] : tb[2];
            uint32_t sa = smb + (uint32_t)s * STAGE2_B + (uint32_t)tile * TILE_B
                        + (uint32_t)r * (LDT * 2) + seg * 16;
            const char* ga = base + (size_t)r * (KTOT * 2) + c * (BKC * 2) + seg * 16;
            cp16(sa, ga);
        }
        cp_commit();
    };

    issue(0, 0);

    for (int c = 0; c < NCHUNK; c++) {
        const int st = c & 1;
        if (c + 1 < NCHUNK) {
            issue(c + 1, st ^ 1);
            cp_wait1();
        } else {
            cp_wait0();
        }
        __syncthreads();

        const uint32_t bXh = smb + (uint32_t)st * STAGE2_B;
        const uint32_t bXl = bXh + TILE_B;
        const uint32_t bW  = bXh + 2 * TILE_B;

#pragma unroll
        for (int ks = 0; ks < 2; ks++) {
            const int kseg0 = ks * 2;
            uint32_t ah[4][4], al[4][4], bw[4][2];
#pragma unroll
            for (int mt = 0; mt < 4; mt++) {
                ldmx4(ah[mt][0], ah[mt][1], ah[mt][2], ah[mt][3],
                      lm_addr(bXh, wm * 64 + mt * 16, kseg0));
                ldmx4(al[mt][0], al[mt][1], al[mt][2], al[mt][3],
                      lm_addr(bXl, wm * 64 + mt * 16, kseg0));
            }
#pragma unroll
            for (int np = 0; np < 2; np++) {
                uint32_t r0, r1, r2, r3;
                ldmx4(r0, r1, r2, r3, lm_addr(bW, wn * 32 + np * 16, kseg0));
                bw[np * 2 + 0][0] = r0; bw[np * 2 + 0][1] = r2;
                bw[np * 2 + 1][0] = r1; bw[np * 2 + 1][1] = r3;
            }
#pragma unroll
            for (int mt = 0; mt < 4; mt++)
#pragma unroll
                for (int nt = 0; nt < 4; nt++)
                    mma16816(acc[mt][nt], ah[mt], bw[nt]);
#pragma unroll
            for (int mt = 0; mt < 4; mt++)
#pragma unroll
                for (int nt = 0; nt < 4; nt++)
                    mma16816(acc[mt][nt], al[mt], bw[nt]);
        }
        __syncthreads();
    }

    const int lid = tid & 31;
    const int grp = lid >> 2;
    const int tig = lid & 3;
#pragma unroll
    for (int mt = 0; mt < 4; mt++) {
#pragma unroll
        for (int nt = 0; nt < 4; nt++) {
            int row = bm + wm * 64 + mt * 16 + grp;
            int col = bn + wn * 32 + nt * 8 + tig * 2;
            float a0 = acc[mt][nt][0] * scale, a1 = acc[mt][nt][1] * scale;
            float a2 = acc[mt][nt][2] * scale, a3 = acc[mt][nt][3] * scale;
            uint32_t hi, lo;
            split2h(a0, a1, hi, lo);
            *(uint32_t*)(Oh + (size_t)row * Nn + col) = hi;
            *(uint32_t*)(Ol + (size_t)row * Nn + col) = lo;
            split2h(a2, a3, hi, lo);
            *(uint32_t*)(Oh + (size_t)(row + 8) * Nn + col) = hi;
            *(uint32_t*)(Ol + (size_t)(row + 8) * Nn + col) = lo;
        }
    }
}

// ===========================================================================
// 1-product GEMM: C = X @ W^T. 2 tiles/stage, 2 stages.
// Epilogue: fp32+bias (Cf) or single fp16 (Oh).
// ===========================================================================
#define STAGE1_B (2 * TILE_B)       // 20480
#define GSMEM1_SZ (2 * STAGE1_B)    // 40960

__global__ __launch_bounds__(256, 2) void gemm_tc1(
    const __half* __restrict__ X, const __half* __restrict__ W,
    const float* __restrict__ bias, float* __restrict__ Cf,
    __half* __restrict__ Oh, int Nn)
{
    extern __shared__ char dynsm[];
    const uint32_t smb = smem_u32(dynsm);
    const int tid = threadIdx.x;
    const int bm = blockIdx.y * BM;
    const int bn = blockIdx.x * BN;
    const int w = tid >> 5;
    const int wm = w >> 2;
    const int wn = w & 3;

    const char* tbX = (const char*)(X + (size_t)bm * KTOT);
    const char* tbW = (const char*)(W + (size_t)bn * KTOT);

    float acc[4][4][4];
#pragma unroll
    for (int i = 0; i < 4; i++)
#pragma unroll
        for (int j = 0; j < 4; j++)
#pragma unroll
            for (int t = 0; t < 4; t++) acc[i][j][t] = 0.f;

    auto issue = [&](int c, int s) {
#pragma unroll
        for (int i = 0; i < 4; i++) {
            int sid = tid + 256 * i;          // 0..1023
            int tile = sid >> 9;              // 0 X, 1 W
            int r = (sid >> 2) & 127;
            int seg = sid & 3;
            const char* base = tile ? tbW : tbX;
            uint32_t sa = smb + (uint32_t)s * STAGE1_B + (uint32_t)tile * TILE_B
                        + (uint32_t)r * (LDT * 2) + seg * 16;
            const char* ga = base + (size_t)r * (KTOT * 2) + c * (BKC * 2) + seg * 16;
            cp16(sa, ga);
        }
        cp_commit();
    };

    issue(0, 0);

    for (int c = 0; c < NCHUNK; c++) {
        const int st = c & 1;
        if (c + 1 < NCHUNK) {
            issue(c + 1, st ^ 1);
            cp_wait1();
        } else {
            cp_wait0();
        }
        __syncthreads();

        const uint32_t bX = smb + (uint32_t)st * STAGE1_B;
        const uint32_t bW = bX + TILE_B;

#pragma unroll
        for (int ks = 0; ks < 2; ks++) {
            const int kseg0 = ks * 2;
            uint32_t ax[4][4], bw[4][2];
#pragma unroll
            for (int mt = 0; mt < 4; mt++)
                ldmx4(ax[mt][0], ax[mt][1], ax[mt][2], ax[mt][3],
                      lm_addr(bX, wm * 64 + mt * 16, kseg0));
#pragma unroll
            for (int np = 0; np < 2; np++) {
                uint32_t r0, r1, r2, r3;
                ldmx4(r0, r1, r2, r3, lm_addr(bW, wn * 32 + np * 16, kseg0));
                bw[np * 2 + 0][0] = r0; bw[np * 2 + 0][1] = r2;
                bw[np * 2 + 1][0] = r1; bw[np * 2 + 1][1] = r3;
            }
#pragma unroll
            for (int mt = 0; mt < 4; mt++)
#pragma unroll
                for (int nt = 0; nt < 4; nt++)
                    mma16816(acc[mt][nt], ax[mt], bw[nt]);
        }
        __syncthreads();
    }

    const int lid = tid & 31;
    const int grp = lid >> 2;
    const int tig = lid & 3;
#pragma unroll
    for (int mt = 0; mt < 4; mt++) {
#pragma unroll
        for (int nt = 0; nt < 4; nt++) {
            int row = bm + wm * 64 + mt * 16 + grp;
            int col = bn + wn * 32 + nt * 8 + tig * 2;
            if (Cf != nullptr) {
                float b0 = bias[col], b1 = bias[col + 1];
                *(float2*)(Cf + (size_t)row * Nn + col) =
                    make_float2(acc[mt][nt][0] + b0, acc[mt][nt][1] + b1);
                *(float2*)(Cf + (size_t)(row + 8) * Nn + col) =
                    make_float2(acc[mt][nt][2] + b0, acc[mt][nt][3] + b1);
            } else {
                *(uint32_t*)(Oh + (size_t)row * Nn + col) =
                    pack2h(acc[mt][nt][0], acc[mt][nt][1]);
                *(uint32_t*)(Oh + (size_t)(row + 8) * Nn + col) =
                    pack2h(acc[mt][nt][2], acc[mt][nt][3]);
            }
        }
    }
}

// ===========================================================================
// Tensor-core causal flash attention, fp16. q-tile 128 rows (8 warps).
// S = (Qh+Ql)K^T (2 products); O = P V (1 product, P single fp16).
// Output A single fp16. K/V double-buffered cp.async; exp2 softmax.
// ===========================================================================
#define ALDT 144                   // smem row stride bytes
#define AQ_TILE (128 * ALDT)       // 18432
#define AKV_TILE (64 * ALDT)       // 9216
#define AOFF_QH 0
#define AOFF_QL AQ_TILE
#define AOFF_ST (2 * AQ_TILE)      // 36864
#define ASTAGE (2 * AKV_TILE)      // 18432
#define ASMEM (AOFF_ST + 2 * ASTAGE)  // 73728

__device__ __forceinline__ uint32_t lda(uint32_t base, int r0, int c0) {
    int L = threadIdx.x & 31;
    int mat = L >> 3;
    int r = r0 + (L & 7) + ((mat & 1) << 3);
    int c = c0 + ((mat >> 1) << 3);
    return base + (uint32_t)r * ALDT + c * 2;
}

__global__ __launch_bounds__(256) void attn_mma(
    const __half* __restrict__ Qh, const __half* __restrict__ Ql,
    const __half* __restrict__ K, const __half* __restrict__ V,
    __half* __restrict__ O)
{
    extern __shared__ char dynsm[];
    const uint32_t smb = smem_u32(dynsm);
    const int tid = threadIdx.x;
    const int w = tid >> 5;
    const int lid = tid & 31;
    const int grp = lid >> 2;
    const int tig = lid & 3;
    const int iblk = (gridDim.x - 1) - blockIdx.x;   // heavy blocks first
    const int h = blockIdx.y;
    const int b = blockIdx.z;
    const int qbase = iblk * 128;
    const int jmax = 2 * iblk + 1;
    const size_t bN = (size_t)b * N_;

    auto issue_stage = [&](int s, int kbase) {
#pragma unroll
        for (int i = 0; i < 4; i++) {
            int sid = tid + 256 * i;          // 0..1023
            int tile = sid >> 9;              // 0 K, 1 V
            int r = (sid >> 3) & 63;
            int seg = sid & 7;
            const __half* gp = tile ? V : K;
            const char* ga = (const char*)(gp + (bN + kbase + r) * E_ + h * 64)
                           + seg * 16;
            cp16(smb + AOFF_ST + (uint32_t)s * ASTAGE + (uint32_t)tile * AKV_TILE
                 + (uint32_t)r * ALDT + seg * 16, ga);
        }
        cp_commit();
    };

    // prologue: Q tiles (128 rows x 64 cols, hi+lo) + KV stage 0
    {
#pragma unroll
        for (int i = 0; i < 8; i++) {
            int sid = tid + 256 * i;          // 0..2047
            int tile = sid >> 10;             // 0 Qh, 1 Ql
            int r = (sid >> 3) & 127;
            int seg = sid & 7;
            const __half* gp = tile ? Ql : Qh;
            const char* ga = (const char*)(gp + (bN + qbase + r) * E_ + h * 64)
                           + seg * 16;
            cp16(smb + (tile ? AOFF_QL : AOFF_QH) + (uint32_t)r * ALDT + seg * 16, ga);
        }
    }
    issue_stage(0, 0);

    uint32_t qh[4][4], ql[4][4];
    float o[8][4];
#pragma unroll
    for (int t = 0; t < 8; t++)
#pragma unroll
        for (int c = 0; c < 4; c++) o[t][c] = 0.f;
    float mr0 = -1e30f, mr1 = -1e30f, lr0 = 0.f, lr1 = 0.f;

    for (int j = 0; j <= jmax; j++) {
        cp_wait0();
        __syncthreads();
        if (j == 0) {
#pragma unroll
            for (int kc = 0; kc < 4; kc++) {
                ldmx4(qh[kc][0], qh[kc][1], qh[kc][2], qh[kc][3],
                      lda(smb + AOFF_QH, w * 16, kc * 16));
                ldmx4(ql[kc][0], ql[kc][1], ql[kc][2], ql[kc][3],
                      lda(smb + AOFF_QL, w * 16, kc * 16));
            }
        }
        if (j < jmax) issue_stage((j + 1) & 1, (j + 1) * 64);

        const uint32_t bK = smb + AOFF_ST + (uint32_t)(j & 1) * ASTAGE;
        const uint32_t bV = bK + AKV_TILE;

        // ---- S = Q K^T (2 products, hoisted K fragments) ----
        float s[8][4];
#pragma unroll
        for (int t = 0; t < 8; t++)
#pragma unroll
            for (int c = 0; c < 4; c++) s[t][c] = 0.f;
#pragma unroll
        for (int kc = 0; kc < 4; kc++) {
            uint32_t bk[8][2];
#pragma unroll
            for (int np = 0; np < 4; np++) {
                uint32_t r0, r1, r2, r3;
                ldmx4(r0, r1, r2, r3, lda(bK, np * 16, kc * 16));
                bk[np * 2 + 0][0] = r0; bk[np * 2 + 0][1] = r2;
                bk[np * 2 + 1][0] = r1; bk[np * 2 + 1][1] = r3;
            }
#pragma unroll
            for (int t = 0; t < 8; t++) mma16816(s[t], qh[kc], bk[t]);
#pragma unroll
            for (int t = 0; t < 8; t++) mma16816(s[t], ql[kc], bk[t]);
        }

        // ---- causal mask (only kv-blocks crossing the diagonal) ----
        if (j >= 2 * iblk) {
            const int row0 = qbase + w * 16 + grp;
            const int row1 = row0 + 8;
            const int cb = j * 64;
#pragma unroll
            for (int t = 0; t < 8; t++) {
                int col = cb + t * 8 + 2 * tig;
                if (col > row0) s[t][0] = -1e30f;
                if (col + 1 > row0) s[t][1] = -1e30f;
                if (col > row1) s[t][2] = -1e30f;
                if (col + 1 > row1) s[t][3] = -1e30f;
            }
        }

        // ---- online softmax (base-2) ----
        float m0 = -1e30f, m1 = -1e30f;
#pragma unroll
        for (int t = 0; t < 8; t++) {
            m0 = fmaxf(m0, fmaxf(s[t][0], s[t][1]));
            m1 = fmaxf(m1, fmaxf(s[t][2], s[t][3]));
        }
        m0 = fmaxf(m0, __shfl_xor_sync(0xffffffffu, m0, 1));
        m0 = fmaxf(m0, __shfl_xor_sync(0xffffffffu, m0, 2));
        m1 = fmaxf(m1, __shfl_xor_sync(0xffffffffu, m1, 1));
        m1 = fmaxf(m1, __shfl_xor_sync(0xffffffffu, m1, 2));
        float mn0 = fmaxf(mr0, m0), mn1 = fmaxf(mr1, m1);
        float a0 = exp2f(mr0 - mn0), a1 = exp2f(mr1 - mn1);
        mr0 = mn0; mr1 = mn1;
        float sum0 = 0.f, sum1 = 0.f;
#pragma unroll
        for (int t = 0; t < 8; t++) {
            s[t][0] = exp2f(s[t][0] - mn0);
            s[t][1] = exp2f(s[t][1] - mn0);
            s[t][2] = exp2f(s[t][2] - mn1);
            s[t][3] = exp2f(s[t][3] - mn1);
            sum0 += s[t][0] + s[t][1];
            sum1 += s[t][2] + s[t][3];
        }
        sum0 += __shfl_xor_sync(0xffffffffu, sum0, 1);
        sum0 += __shfl_xor_sync(0xffffffffu, sum0, 2);
        sum1 += __shfl_xor_sync(0xffffffffu, sum1, 1);
        sum1 += __shfl_xor_sync(0xffffffffu, sum1, 2);
        lr0 = lr0 * a0 + sum0;
        lr1 = lr1 * a1 + sum1;
#pragma unroll
        for (int t = 0; t < 8; t++) {
            o[t][0] *= a0; o[t][1] *= a0;
            o[t][2] *= a1; o[t][3] *= a1;
        }

        // ---- P: C-frag -> A-frag, single fp16 ----
        uint32_t ph[4][4];
#pragma unroll
        for (int kc = 0; kc < 4; kc++) {
            ph[kc][0] = pack2h(s[2 * kc][0], s[2 * kc][1]);
            ph[kc][1] = pack2h(s[2 * kc][2], s[2 * kc][3]);
            ph[kc][2] = pack2h(s[2 * kc + 1][0], s[2 * kc + 1][1]);
            ph[kc][3] = pack2h(s[2 * kc + 1][2], s[2 * kc + 1][3]);
        }

        // ---- O += P V (1 product, hoisted V fragments) ----
#pragma unroll
        for (int kc = 0; kc < 4; kc++) {
            uint32_t vv[8][2];
#pragma unroll
            for (int nd = 0; nd < 4; nd++) {
                uint32_t r0, r1, r2, r3;
                ldmx4t(r0, r1, r2, r3, lda(bV, kc * 16, nd * 16));
                vv[nd * 2 + 0][0] = r0; vv[nd * 2 + 0][1] = r1;
                vv[nd * 2 + 1][0] = r2; vv[nd * 2 + 1][1] = r3;
            }
#pragma unroll
            for (int t = 0; t < 8; t++) mma16816(o[t], ph[kc], vv[t]);
        }
    }

    // ---- epilogue: normalize, single fp16, store [B,N,E] ----
    const float i0 = 1.f / lr0, i1 = 1.f / lr1;
    const int qr0 = qbase + w * 16 + grp;
    const size_t ro0 = (bN + qr0) * E_;
    const size_t ro1 = (bN + qr0 + 8) * E_;
#pragma unroll
    for (int t = 0; t < 8; t++) {
        int col = h * 64 + t * 8 + 2 * tig;
        *(uint32_t*)(O + ro0 + col) = pack2h(o[t][0] * i0, o[t][1] * i0);
        *(uint32_t*)(O + ro1 + col) = pack2h(o[t][2] * i1, o[t][3] * i1);
    }
}

// ---------------------------------------------------------------------------
extern "C" void kernel_launch(void* const* d_in, const int* in_sizes, int n_in,
                              void* d_out, int out_size)
{
    const float* xq = (const float*)d_in[0];
    const float* xk = (const float*)d_in[1];
    const float* xv = (const float*)d_in[2];
    // d_in[3] = attn_mask (causal, recomputed analytically) — unused
    const float* Wq = (const float*)d_in[4];
    const float* Wk = (const float*)d_in[5];
    const float* Wv = (const float*)d_in[6];
    const float* Wo = (const float*)d_in[7];
    const float* bo = (const float*)d_in[8];
    float* out = (float*)d_out;

    __half *xqh, *xql, *xkp, *xvp;
    __half *Qh, *Ql, *Kb, *Vb, *Ab;
    __half *Wqh, *Wkh, *Wvh, *Woh;
    cudaGetSymbolAddress((void**)&xqh, g_xqh);
    cudaGetSymbolAddress((void**)&xql, g_xql);
    cudaGetSymbolAddress((void**)&xkp, g_xk);
    cudaGetSymbolAddress((void**)&xvp, g_xv);
    cudaGetSymbolAddress((void**)&Qh, g_Qh);
    cudaGetSymbolAddress((void**)&Ql, g_Ql);
    cudaGetSymbolAddress((void**)&Kb, g_K);
    cudaGetSymbolAddress((void**)&Vb, g_V);
    cudaGetSymbolAddress((void**)&Ab, g_A);
    cudaGetSymbolAddress((void**)&Wqh, g_Wq);
    cudaGetSymbolAddress((void**)&Wkh, g_Wk);
    cudaGetSymbolAddress((void**)&Wvh, g_Wv);
    cudaGetSymbolAddress((void**)&Woh, g_Wo);

    cudaFuncSetAttribute(gemm_tc2, cudaFuncAttributeMaxDynamicSharedMemorySize,
                         GSMEM2_SZ);
    cudaFuncSetAttribute(gemm_tc1, cudaFuncAttributeMaxDynamicSharedMemorySize,
                         GSMEM1_SZ);
    cudaFuncSetAttribute(attn_mma, cudaFuncAttributeMaxDynamicSharedMemorySize,
                         ASMEM);

    // Prepass conversions
    const int nx4 = MTOT * E_ / 4;
    const int nw4 = E_ * E_ / 4;
    convert_split_h<<<nx4 / 256, 256>>>(xq, xqh, xql, nx4);
    convert_h<<<nx4 / 256, 256>>>(xk, xkp, nx4);
    convert_h<<<nx4 / 256, 256>>>(xv, xvp, nx4);
    convert_h<<<nw4 / 256, 256>>>(Wq, Wqh, nw4);
    convert_h<<<nw4 / 256, 256>>>(Wk, Wkh, nw4);
    convert_h<<<nw4 / 256, 256>>>(Wv, Wvh, nw4);
    convert_h<<<nw4 / 256, 256>>>(Wo, Woh, nw4);

    dim3 gblock(256);
    dim3 ggrid(E_ / BN, MTOT / BM);        // (8, 64)

    // Q projection: 2-product, fp16 hi/lo out (pre-scaled by log2e/sqrt(D))
    gemm_tc2<<<ggrid, gblock, GSMEM2_SZ>>>(xqh, xql, Wqh, Qh, Ql,
                                           SCALE_LOG2E, E_);
    // K, V projections: 1-product, single fp16 out
    gemm_tc1<<<ggrid, gblock, GSMEM1_SZ>>>(xkp, Wkh, nullptr, nullptr, Kb, E_);
    gemm_tc1<<<ggrid, gblock, GSMEM1_SZ>>>(xvp, Wvh, nullptr, nullptr, Vb, E_);

    dim3 agrid(N_ / 128, H_, B_);          // (16, 16, 4)
    attn_mma<<<agrid, 256, ASMEM>>>(Qh, Ql, Kb, Vb, Ab);

    // Output projection (single product) -> fp32 + bias
    gemm_tc1<<<ggrid, gblock, GSMEM1_SZ>>>(Ab, Woh, bo, out, nullptr, E_);
}

// round 14
// speedup vs baseline: 2.6347x; 1.2428x over previous
#include <cuda_runtime.h>
#include <cuda_fp16.h>
#include <cstdint>

#define B_ 4
#define N_ 2048
#define E_ 1024
#define H_ 16
#define D_ 64
#define SCALE_LOG2E 0.18033688f  // 0.125 * log2(e)
#define MTOT (B_ * N_)           // 8192

// ---------------------------------------------------------------------------
// Scratch (allocation-free rule: __device__ globals)
// ---------------------------------------------------------------------------
__device__ __half g_xq[(size_t)MTOT * E_];
__device__ __half g_xk[(size_t)MTOT * E_];
__device__ __half g_xv[(size_t)MTOT * E_];

__device__ __half g_Q[(size_t)MTOT * E_];
__device__ __half g_K[(size_t)MTOT * E_];
__device__ __half g_V[(size_t)MTOT * E_];
__device__ __half g_A[(size_t)MTOT * E_];

__device__ __half g_Wq[(size_t)E_ * E_];
__device__ __half g_Wk[(size_t)E_ * E_];
__device__ __half g_Wv[(size_t)E_ * E_];
__device__ __half g_Wo[(size_t)E_ * E_];

// ---------------------------------------------------------------------------
// helpers
// ---------------------------------------------------------------------------
__device__ __forceinline__ uint32_t smem_u32(const void* p) {
    uint32_t a;
    asm("{ .reg .u64 t; cvta.to.shared.u64 t, %1; cvt.u32.u64 %0, t; }"
        : "=r"(a) : "l"(p));
    return a;
}
__device__ __forceinline__ void cp16(uint32_t sa, const void* ga) {
    asm volatile("cp.async.cg.shared.global [%0], [%1], 16;"
                 :: "r"(sa), "l"(ga));
}
__device__ __forceinline__ void cp_commit() {
    asm volatile("cp.async.commit_group;");
}
__device__ __forceinline__ void cp_wait1() {
    asm volatile("cp.async.wait_group 1;");
}
__device__ __forceinline__ void cp_wait0() {
    asm volatile("cp.async.wait_group 0;");
}
__device__ __forceinline__ void ldmx4(uint32_t& r0, uint32_t& r1,
                                      uint32_t& r2, uint32_t& r3, uint32_t a) {
    asm volatile("ldmatrix.sync.aligned.m8n8.x4.shared.b16 {%0,%1,%2,%3}, [%4];"
                 : "=r"(r0), "=r"(r1), "=r"(r2), "=r"(r3) : "r"(a));
}
__device__ __forceinline__ void ldmx4t(uint32_t& r0, uint32_t& r1,
                                       uint32_t& r2, uint32_t& r3, uint32_t a) {
    asm volatile("ldmatrix.sync.aligned.m8n8.x4.trans.shared.b16 {%0,%1,%2,%3}, [%4];"
                 : "=r"(r0), "=r"(r1), "=r"(r2), "=r"(r3) : "r"(a));
}
__device__ __forceinline__ void mma16816(float* d, const uint32_t* a,
                                         const uint32_t* b) {
    asm volatile(
        "mma.sync.aligned.m16n8k16.row.col.f32.f16.f16.f32 "
        "{%0,%1,%2,%3}, {%4,%5,%6,%7}, {%8,%9}, {%0,%1,%2,%3};"
        : "+f"(d[0]), "+f"(d[1]), "+f"(d[2]), "+f"(d[3])
        : "r"(a[0]), "r"(a[1]), "r"(a[2]), "r"(a[3]), "r"(b[0]), "r"(b[1]));
}
__device__ __forceinline__ uint32_t pack2h(float a, float b) {
    __half2 h = __floats2half2_rn(a, b);
    return *(uint32_t*)&h;
}

// ---------------------------------------------------------------------------
// Prepass: fp32 -> fp16.
// ---------------------------------------------------------------------------
__global__ __launch_bounds__(256) void convert_h(
    const float* __restrict__ src, __half* __restrict__ h, int n4)
{
    int i = blockIdx.x * 256 + threadIdx.x;
    if (i >= n4) return;
    float4 v = ((const float4*)src)[i];
    ((uint2*)h)[i] = make_uint2(pack2h(v.x, v.y), pack2h(v.z, v.w));
}

// ===========================================================================
// Shared GEMM tiling constants
// ===========================================================================
#define BM 128
#define BN 128
#define BKC 32
#define KTOT 1024
#define NCHUNK (KTOT / BKC)
#define LDT 40
#define TILE_B (128 * LDT * 2)     // 10240

__device__ __forceinline__ uint32_t lm_addr(uint32_t base_b, int row0, int kseg0) {
    int L = threadIdx.x & 31;
    int mat = L >> 3;
    int r = (L & 7) + ((mat & 1) << 3);
    int ks = kseg0 + (mat >> 1);
    return base_b + (uint32_t)(row0 + r) * (LDT * 2) + ks * 16;
}

// ===========================================================================
// 1-product GEMM: C = X @ W^T (scaled). 2 tiles/stage, 2 stages.
// Epilogue: fp32+bias (Cf) or single fp16 (Oh).
// ===========================================================================
#define STAGE1_B (2 * TILE_B)       // 20480
#define GSMEM1_SZ (2 * STAGE1_B)    // 40960

__global__ __launch_bounds__(256, 2) void gemm_tc1(
    const __half* __restrict__ X, const __half* __restrict__ W,
    const float* __restrict__ bias, float* __restrict__ Cf,
    __half* __restrict__ Oh, float scale, int Nn)
{
    extern __shared__ char dynsm[];
    const uint32_t smb = smem_u32(dynsm);
    const int tid = threadIdx.x;
    const int bm = blockIdx.y * BM;
    const int bn = blockIdx.x * BN;
    const int w = tid >> 5;
    const int wm = w >> 2;
    const int wn = w & 3;

    const char* tbX = (const char*)(X + (size_t)bm * KTOT);
    const char* tbW = (const char*)(W + (size_t)bn * KTOT);

    float acc[4][4][4];
#pragma unroll
    for (int i = 0; i < 4; i++)
#pragma unroll
        for (int j = 0; j < 4; j++)
#pragma unroll
            for (int t = 0; t < 4; t++) acc[i][j][t] = 0.f;

    auto issue = [&](int c, int s) {
#pragma unroll
        for (int i = 0; i < 4; i++) {
            int sid = tid + 256 * i;          // 0..1023
            int tile = sid >> 9;              // 0 X, 1 W
            int r = (sid >> 2) & 127;
            int seg = sid & 3;
            const char* base = tile ? tbW : tbX;
            uint32_t sa = smb + (uint32_t)s * STAGE1_B + (uint32_t)tile * TILE_B
                        + (uint32_t)r * (LDT * 2) + seg * 16;
            const char* ga = base + (size_t)r * (KTOT * 2) + c * (BKC * 2) + seg * 16;
            cp16(sa, ga);
        }
        cp_commit();
    };

    issue(0, 0);

    for (int c = 0; c < NCHUNK; c++) {
        const int st = c & 1;
        if (c + 1 < NCHUNK) {
            issue(c + 1, st ^ 1);
            cp_wait1();
        } else {
            cp_wait0();
        }
        __syncthreads();

        const uint32_t bX = smb + (uint32_t)st * STAGE1_B;
        const uint32_t bW = bX + TILE_B;

#pragma unroll
        for (int ks = 0; ks < 2; ks++) {
            const int kseg0 = ks * 2;
            uint32_t ax[4][4], bw[4][2];
#pragma unroll
            for (int mt = 0; mt < 4; mt++)
                ldmx4(ax[mt][0], ax[mt][1], ax[mt][2], ax[mt][3],
                      lm_addr(bX, wm * 64 + mt * 16, kseg0));
#pragma unroll
            for (int np = 0; np < 2; np++) {
                uint32_t r0, r1, r2, r3;
                ldmx4(r0, r1, r2, r3, lm_addr(bW, wn * 32 + np * 16, kseg0));
                bw[np * 2 + 0][0] = r0; bw[np * 2 + 0][1] = r2;
                bw[np * 2 + 1][0] = r1; bw[np * 2 + 1][1] = r3;
            }
#pragma unroll
            for (int mt = 0; mt < 4; mt++)
#pragma unroll
                for (int nt = 0; nt < 4; nt++)
                    mma16816(acc[mt][nt], ax[mt], bw[nt]);
        }
        __syncthreads();
    }

    const int lid = tid & 31;
    const int grp = lid >> 2;
    const int tig = lid & 3;
#pragma unroll
    for (int mt = 0; mt < 4; mt++) {
#pragma unroll
        for (int nt = 0; nt < 4; nt++) {
            int row = bm + wm * 64 + mt * 16 + grp;
            int col = bn + wn * 32 + nt * 8 + tig * 2;
            float a0 = acc[mt][nt][0] * scale, a1 = acc[mt][nt][1] * scale;
            float a2 = acc[mt][nt][2] * scale, a3 = acc[mt][nt][3] * scale;
            if (Cf != nullptr) {
                float b0 = bias[col], b1 = bias[col + 1];
                *(float2*)(Cf + (size_t)row * Nn + col) =
                    make_float2(a0 + b0, a1 + b1);
                *(float2*)(Cf + (size_t)(row + 8) * Nn + col) =
                    make_float2(a2 + b0, a3 + b1);
            } else {
                *(uint32_t*)(Oh + (size_t)row * Nn + col) = pack2h(a0, a1);
                *(uint32_t*)(Oh + (size_t)(row + 8) * Nn + col) = pack2h(a2, a3);
            }
        }
    }
}

// ===========================================================================
// Tensor-core causal flash attention, fp16 single-product.
// q-tile 128 rows (8 warps); S = Q K^T; O = P V; exp2 softmax.
// K/V double-buffered cp.async.
// ===========================================================================
#define ALDT 144                   // smem row stride bytes
#define AQ_TILE (128 * ALDT)       // 18432
#define AKV_TILE (64 * ALDT)       // 9216
#define AOFF_Q 0
#define AOFF_ST AQ_TILE            // 18432
#define ASTAGE (2 * AKV_TILE)      // 18432
#define ASMEM (AOFF_ST + 2 * ASTAGE)  // 55296

__device__ __forceinline__ uint32_t lda(uint32_t base, int r0, int c0) {
    int L = threadIdx.x & 31;
    int mat = L >> 3;
    int r = r0 + (L & 7) + ((mat & 1) << 3);
    int c = c0 + ((mat >> 1) << 3);
    return base + (uint32_t)r * ALDT + c * 2;
}

__global__ __launch_bounds__(256) void attn_mma(
    const __half* __restrict__ Q, const __half* __restrict__ K,
    const __half* __restrict__ V, __half* __restrict__ O)
{
    extern __shared__ char dynsm[];
    const uint32_t smb = smem_u32(dynsm);
    const int tid = threadIdx.x;
    const int w = tid >> 5;
    const int lid = tid & 31;
    const int grp = lid >> 2;
    const int tig = lid & 3;
    const int iblk = (gridDim.x - 1) - blockIdx.x;   // heavy blocks first
    const int h = blockIdx.y;
    const int b = blockIdx.z;
    const int qbase = iblk * 128;
    const int jmax = 2 * iblk + 1;
    const size_t bN = (size_t)b * N_;

    auto issue_stage = [&](int s, int kbase) {
#pragma unroll
        for (int i = 0; i < 4; i++) {
            int sid = tid + 256 * i;          // 0..1023
            int tile = sid >> 9;              // 0 K, 1 V
            int r = (sid >> 3) & 63;
            int seg = sid & 7;
            const __half* gp = tile ? V : K;
            const char* ga = (const char*)(gp + (bN + kbase + r) * E_ + h * 64)
                           + seg * 16;
            cp16(smb + AOFF_ST + (uint32_t)s * ASTAGE + (uint32_t)tile * AKV_TILE
                 + (uint32_t)r * ALDT + seg * 16, ga);
        }
        cp_commit();
    };

    // prologue: Q tile (128 rows x 64 cols) + KV stage 0
    {
#pragma unroll
        for (int i = 0; i < 4; i++) {
            int sid = tid + 256 * i;          // 0..1023
            int r = sid >> 3;
            int seg = sid & 7;
            const char* ga = (const char*)(Q + (bN + qbase + r) * E_ + h * 64)
                           + seg * 16;
            cp16(smb + AOFF_Q + (uint32_t)r * ALDT + seg * 16, ga);
        }
    }
    issue_stage(0, 0);

    uint32_t qq[4][4];
    float o[8][4];
#pragma unroll
    for (int t = 0; t < 8; t++)
#pragma unroll
        for (int c = 0; c < 4; c++) o[t][c] = 0.f;
    float mr0 = -1e30f, mr1 = -1e30f, lr0 = 0.f, lr1 = 0.f;

    for (int j = 0; j <= jmax; j++) {
        cp_wait0();
        __syncthreads();
        if (j == 0) {
#pragma unroll
            for (int kc = 0; kc < 4; kc++)
                ldmx4(qq[kc][0], qq[kc][1], qq[kc][2], qq[kc][3],
                      lda(smb + AOFF_Q, w * 16, kc * 16));
        }
        if (j < jmax) issue_stage((j + 1) & 1, (j + 1) * 64);

        const uint32_t bK = smb + AOFF_ST + (uint32_t)(j & 1) * ASTAGE;
        const uint32_t bV = bK + AKV_TILE;

        // ---- S = Q K^T (1 product, hoisted K fragments) ----
        float s[8][4];
#pragma unroll
        for (int t = 0; t < 8; t++)
#pragma unroll
            for (int c = 0; c < 4; c++) s[t][c] = 0.f;
#pragma unroll
        for (int kc = 0; kc < 4; kc++) {
            uint32_t bk[8][2];
#pragma unroll
            for (int np = 0; np < 4; np++) {
                uint32_t r0, r1, r2, r3;
                ldmx4(r0, r1, r2, r3, lda(bK, np * 16, kc * 16));
                bk[np * 2 + 0][0] = r0; bk[np * 2 + 0][1] = r2;
                bk[np * 2 + 1][0] = r1; bk[np * 2 + 1][1] = r3;
            }
#pragma unroll
            for (int t = 0; t < 8; t++) mma16816(s[t], qq[kc], bk[t]);
        }

        // ---- causal mask (only kv-blocks crossing the diagonal) ----
        if (j >= 2 * iblk) {
            const int row0 = qbase + w * 16 + grp;
            const int row1 = row0 + 8;
            const int cb = j * 64;
#pragma unroll
            for (int t = 0; t < 8; t++) {
                int col = cb + t * 8 + 2 * tig;
                if (col > row0) s[t][0] = -1e30f;
                if (col + 1 > row0) s[t][1] = -1e30f;
                if (col > row1) s[t][2] = -1e30f;
                if (col + 1 > row1) s[t][3] = -1e30f;
            }
        }

        // ---- online softmax (base-2) ----
        float m0 = -1e30f, m1 = -1e30f;
#pragma unroll
        for (int t = 0; t < 8; t++) {
            m0 = fmaxf(m0, fmaxf(s[t][0], s[t][1]));
            m1 = fmaxf(m1, fmaxf(s[t][2], s[t][3]));
        }
        m0 = fmaxf(m0, __shfl_xor_sync(0xffffffffu, m0, 1));
        m0 = fmaxf(m0, __shfl_xor_sync(0xffffffffu, m0, 2));
        m1 = fmaxf(m1, __shfl_xor_sync(0xffffffffu, m1, 1));
        m1 = fmaxf(m1, __shfl_xor_sync(0xffffffffu, m1, 2));
        float mn0 = fmaxf(mr0, m0), mn1 = fmaxf(mr1, m1);
        float a0 = exp2f(mr0 - mn0), a1 = exp2f(mr1 - mn1);
        mr0 = mn0; mr1 = mn1;
        float sum0 = 0.f, sum1 = 0.f;
#pragma unroll
        for (int t = 0; t < 8; t++) {
            s[t][0] = exp2f(s[t][0] - mn0);
            s[t][1] = exp2f(s[t][1] - mn0);
            s[t][2] = exp2f(s[t][2] - mn1);
            s[t][3] = exp2f(s[t][3] - mn1);
            sum0 += s[t][0] + s[t][1];
            sum1 += s[t][2] + s[t][3];
        }
        sum0 += __shfl_xor_sync(0xffffffffu, sum0, 1);
        sum0 += __shfl_xor_sync(0xffffffffu, sum0, 2);
        sum1 += __shfl_xor_sync(0xffffffffu, sum1, 1);
        sum1 += __shfl_xor_sync(0xffffffffu, sum1, 2);
        lr0 = lr0 * a0 + sum0;
        lr1 = lr1 * a1 + sum1;
#pragma unroll
        for (int t = 0; t < 8; t++) {
            o[t][0] *= a0; o[t][1] *= a0;
            o[t][2] *= a1; o[t][3] *= a1;
        }

        // ---- P: C-frag -> A-frag, single fp16 ----
        uint32_t ph[4][4];
#pragma unroll
        for (int kc = 0; kc < 4; kc++) {
            ph[kc][0] = pack2h(s[2 * kc][0], s[2 * kc][1]);
            ph[kc][1] = pack2h(s[2 * kc][2], s[2 * kc][3]);
            ph[kc][2] = pack2h(s[2 * kc + 1][0], s[2 * kc + 1][1]);
            ph[kc][3] = pack2h(s[2 * kc + 1][2], s[2 * kc + 1][3]);
        }

        // ---- O += P V (1 product, hoisted V fragments) ----
#pragma unroll
        for (int kc = 0; kc < 4; kc++) {
            uint32_t vv[8][2];
#pragma unroll
            for (int nd = 0; nd < 4; nd++) {
                uint32_t r0, r1, r2, r3;
                ldmx4t(r0, r1, r2, r3, lda(bV, kc * 16, nd * 16));
                vv[nd * 2 + 0][0] = r0; vv[nd * 2 + 0][1] = r1;
                vv[nd * 2 + 1][0] = r2; vv[nd * 2 + 1][1] = r3;
            }
#pragma unroll
            for (int t = 0; t < 8; t++) mma16816(o[t], ph[kc], vv[t]);
        }
    }

    // ---- epilogue: normalize, single fp16, store [B,N,E] ----
    const float i0 = 1.f / lr0, i1 = 1.f / lr1;
    const int qr0 = qbase + w * 16 + grp;
    const size_t ro0 = (bN + qr0) * E_;
    const size_t ro1 = (bN + qr0 + 8) * E_;
#pragma unroll
    for (int t = 0; t < 8; t++) {
        int col = h * 64 + t * 8 + 2 * tig;
        *(uint32_t*)(O + ro0 + col) = pack2h(o[t][0] * i0, o[t][1] * i0);
        *(uint32_t*)(O + ro1 + col) = pack2h(o[t][2] * i1, o[t][3] * i1);
    }
}

// ---------------------------------------------------------------------------
extern "C" void kernel_launch(void* const* d_in, const int* in_sizes, int n_in,
                              void* d_out, int out_size)
{
    const float* xq = (const float*)d_in[0];
    const float* xk = (const float*)d_in[1];
    const float* xv = (const float*)d_in[2];
    // d_in[3] = attn_mask (causal, recomputed analytically) — unused
    const float* Wq = (const float*)d_in[4];
    const float* Wk = (const float*)d_in[5];
    const float* Wv = (const float*)d_in[6];
    const float* Wo = (const float*)d_in[7];
    const float* bo = (const float*)d_in[8];
    float* out = (float*)d_out;

    __half *xqp, *xkp, *xvp;
    __half *Qb, *Kb, *Vb, *Ab;
    __half *Wqh, *Wkh, *Wvh, *Woh;
    cudaGetSymbolAddress((void**)&xqp, g_xq);
    cudaGetSymbolAddress((void**)&xkp, g_xk);
    cudaGetSymbolAddress((void**)&xvp, g_xv);
    cudaGetSymbolAddress((void**)&Qb, g_Q);
    cudaGetSymbolAddress((void**)&Kb, g_K);
    cudaGetSymbolAddress((void**)&Vb, g_V);
    cudaGetSymbolAddress((void**)&Ab, g_A);
    cudaGetSymbolAddress((void**)&Wqh, g_Wq);
    cudaGetSymbolAddress((void**)&Wkh, g_Wk);
    cudaGetSymbolAddress((void**)&Wvh, g_Wv);
    cudaGetSymbolAddress((void**)&Woh, g_Wo);

    cudaFuncSetAttribute(gemm_tc1, cudaFuncAttributeMaxDynamicSharedMemorySize,
                         GSMEM1_SZ);
    cudaFuncSetAttribute(attn_mma, cudaFuncAttributeMaxDynamicSharedMemorySize,
                         ASMEM);

    // Prepass conversions (all single fp16)
    const int nx4 = MTOT * E_ / 4;
    const int nw4 = E_ * E_ / 4;
    convert_h<<<nx4 / 256, 256>>>(xq, xqp, nx4);
    convert_h<<<nx4 / 256, 256>>>(xk, xkp, nx4);
    convert_h<<<nx4 / 256, 256>>>(xv, xvp, nx4);
    convert_h<<<nw4 / 256, 256>>>(Wq, Wqh, nw4);
    convert_h<<<nw4 / 256, 256>>>(Wk, Wkh, nw4);
    convert_h<<<nw4 / 256, 256>>>(Wv, Wvh, nw4);
    convert_h<<<nw4 / 256, 256>>>(Wo, Woh, nw4);

    dim3 gblock(256);
    dim3 ggrid(E_ / BN, MTOT / BM);        // (8, 64)

    // Projections: all 1-product fp16 (Q pre-scaled by log2e/sqrt(D))
    gemm_tc1<<<ggrid, gblock, GSMEM1_SZ>>>(xqp, Wqh, nullptr, nullptr, Qb,
                                           SCALE_LOG2E, E_);
    gemm_tc1<<<ggrid, gblock, GSMEM1_SZ>>>(xkp, Wkh, nullptr, nullptr, Kb,
                                           1.0f, E_);
    gemm_tc1<<<ggrid, gblock, GSMEM1_SZ>>>(xvp, Wvh, nullptr, nullptr, Vb,
                                           1.0f, E_);

    dim3 agrid(N_ / 128, H_, B_);          // (16, 16, 4)
    attn_mma<<<agrid, 256, ASMEM>>>(Qb, Kb, Vb, Ab);

    // Output projection -> fp32 + bias
    gemm_tc1<<<ggrid, gblock, GSMEM1_SZ>>>(Ab, Woh, bo, out, nullptr,
                                           1.0f, E_);
}

// round 15
// speedup vs baseline: 2.8419x; 1.0787x over previous
#include <cuda_runtime.h>
#include <cuda_fp16.h>
#include <cstdint>

#define B_ 4
#define N_ 2048
#define E_ 1024
#define H_ 16
#define D_ 64
#define SCALE_LOG2E 0.18033688f  // 0.125 * log2(e)
#define MTOT (B_ * N_)           // 8192

// ---------------------------------------------------------------------------
// Scratch (allocation-free rule: __device__ globals)
// ---------------------------------------------------------------------------
__device__ __half g_xq[(size_t)MTOT * E_];
__device__ __half g_xk[(size_t)MTOT * E_];
__device__ __half g_xv[(size_t)MTOT * E_];

__device__ __half g_Q[(size_t)MTOT * E_];
__device__ __half g_K[(size_t)MTOT * E_];
__device__ __half g_V[(size_t)MTOT * E_];
__device__ __half g_A[(size_t)MTOT * E_];

__device__ __half g_Wq[(size_t)E_ * E_];
__device__ __half g_Wk[(size_t)E_ * E_];
__device__ __half g_Wv[(size_t)E_ * E_];
__device__ __half g_Wo[(size_t)E_ * E_];

// ---------------------------------------------------------------------------
// helpers
// ---------------------------------------------------------------------------
__device__ __forceinline__ uint32_t smem_u32(const void* p) {
    uint32_t a;
    asm("{ .reg .u64 t; cvta.to.shared.u64 t, %1; cvt.u32.u64 %0, t; }"
        : "=r"(a) : "l"(p));
    return a;
}
__device__ __forceinline__ void cp16(uint32_t sa, const void* ga) {
    asm volatile("cp.async.cg.shared.global [%0], [%1], 16;"
                 :: "r"(sa), "l"(ga));
}
__device__ __forceinline__ void cp_commit() {
    asm volatile("cp.async.commit_group;");
}
__device__ __forceinline__ void cp_wait1() {
    asm volatile("cp.async.wait_group 1;");
}
__device__ __forceinline__ void cp_wait0() {
    asm volatile("cp.async.wait_group 0;");
}
__device__ __forceinline__ void ldmx4(uint32_t& r0, uint32_t& r1,
                                      uint32_t& r2, uint32_t& r3, uint32_t a) {
    asm volatile("ldmatrix.sync.aligned.m8n8.x4.shared.b16 {%0,%1,%2,%3}, [%4];"
                 : "=r"(r0), "=r"(r1), "=r"(r2), "=r"(r3) : "r"(a));
}
__device__ __forceinline__ void ldmx4t(uint32_t& r0, uint32_t& r1,
                                       uint32_t& r2, uint32_t& r3, uint32_t a) {
    asm volatile("ldmatrix.sync.aligned.m8n8.x4.trans.shared.b16 {%0,%1,%2,%3}, [%4];"
                 : "=r"(r0), "=r"(r1), "=r"(r2), "=r"(r3) : "r"(a));
}
__device__ __forceinline__ void mma16816(float* d, const uint32_t* a,
                                         const uint32_t* b) {
    asm volatile(
        "mma.sync.aligned.m16n8k16.row.col.f32.f16.f16.f32 "
        "{%0,%1,%2,%3}, {%4,%5,%6,%7}, {%8,%9}, {%0,%1,%2,%3};"
        : "+f"(d[0]), "+f"(d[1]), "+f"(d[2]), "+f"(d[3])
        : "r"(a[0]), "r"(a[1]), "r"(a[2]), "r"(a[3]), "r"(b[0]), "r"(b[1]));
}
__device__ __forceinline__ uint32_t pack2h(float a, float b) {
    __half2 h = __floats2half2_rn(a, b);
    return *(uint32_t*)&h;
}

// ---------------------------------------------------------------------------
// Prepass: fp32 -> fp16, fused over multiple tensors (blockIdx.y selects).
// ---------------------------------------------------------------------------
__global__ __launch_bounds__(256) void convert_h3(
    const float* __restrict__ s0, const float* __restrict__ s1,
    const float* __restrict__ s2,
    __half* __restrict__ d0, __half* __restrict__ d1,
    __half* __restrict__ d2, int n4)
{
    int i = blockIdx.x * 256 + threadIdx.x;
    if (i >= n4) return;
    int t = blockIdx.y;
    const float* src = (t == 0) ? s0 : (t == 1) ? s1 : s2;
    __half* dst = (t == 0) ? d0 : (t == 1) ? d1 : d2;
    float4 v = ((const float4*)src)[i];
    ((uint2*)dst)[i] = make_uint2(pack2h(v.x, v.y), pack2h(v.z, v.w));
}
__global__ __launch_bounds__(256) void convert_h4(
    const float* __restrict__ s0, const float* __restrict__ s1,
    const float* __restrict__ s2, const float* __restrict__ s3,
    __half* __restrict__ d0, __half* __restrict__ d1,
    __half* __restrict__ d2, __half* __restrict__ d3, int n4)
{
    int i = blockIdx.x * 256 + threadIdx.x;
    if (i >= n4) return;
    int t = blockIdx.y;
    const float* src = (t == 0) ? s0 : (t == 1) ? s1 : (t == 2) ? s2 : s3;
    __half* dst = (t == 0) ? d0 : (t == 1) ? d1 : (t == 2) ? d2 : d3;
    float4 v = ((const float4*)src)[i];
    ((uint2*)dst)[i] = make_uint2(pack2h(v.x, v.y), pack2h(v.z, v.w));
}

// ===========================================================================
// Shared GEMM tiling constants
// ===========================================================================
#define BM 128
#define BN 128
#define BKC 32
#define KTOT 1024
#define NCHUNK (KTOT / BKC)
#define LDT 40
#define TILE_B (128 * LDT * 2)     // 10240
#define STAGE1_B (2 * TILE_B)      // 20480
#define GSMEM1_SZ (2 * STAGE1_B)   // 40960

__device__ __forceinline__ uint32_t lm_addr(uint32_t base_b, int row0, int kseg0) {
    int L = threadIdx.x & 31;
    int mat = L >> 3;
    int r = (L & 7) + ((mat & 1) << 3);
    int ks = kseg0 + (mat >> 1);
    return base_b + (uint32_t)(row0 + r) * (LDT * 2) + ks * 16;
}

// ---------------------------------------------------------------------------
// Core 1-product GEMM body (device inline): acc = X @ W^T over K=1024.
// ---------------------------------------------------------------------------
__device__ __forceinline__ void gemm_body(
    const char* tbX, const char* tbW, uint32_t smb, float acc[4][4][4])
{
    const int tid = threadIdx.x;
    const int w = tid >> 5;
    const int wm = w >> 2;
    const int wn = w & 3;

    auto issue = [&](int c, int s) {
#pragma unroll
        for (int i = 0; i < 4; i++) {
            int sid = tid + 256 * i;          // 0..1023
            int tile = sid >> 9;              // 0 X, 1 W
            int r = (sid >> 2) & 127;
            int seg = sid & 3;
            const char* base = tile ? tbW : tbX;
            uint32_t sa = smb + (uint32_t)s * STAGE1_B + (uint32_t)tile * TILE_B
                        + (uint32_t)r * (LDT * 2) + seg * 16;
            const char* ga = base + (size_t)r * (KTOT * 2) + c * (BKC * 2) + seg * 16;
            cp16(sa, ga);
        }
        cp_commit();
    };

    issue(0, 0);

    for (int c = 0; c < NCHUNK; c++) {
        const int st = c & 1;
        if (c + 1 < NCHUNK) {
            issue(c + 1, st ^ 1);
            cp_wait1();
        } else {
            cp_wait0();
        }
        __syncthreads();

        const uint32_t bX = smb + (uint32_t)st * STAGE1_B;
        const uint32_t bW = bX + TILE_B;

#pragma unroll
        for (int ks = 0; ks < 2; ks++) {
            const int kseg0 = ks * 2;
            uint32_t ax[4][4], bw[4][2];
#pragma unroll
            for (int mt = 0; mt < 4; mt++)
                ldmx4(ax[mt][0], ax[mt][1], ax[mt][2], ax[mt][3],
                      lm_addr(bX, wm * 64 + mt * 16, kseg0));
#pragma unroll
            for (int np = 0; np < 2; np++) {
                uint32_t r0, r1, r2, r3;
                ldmx4(r0, r1, r2, r3, lm_addr(bW, wn * 32 + np * 16, kseg0));
                bw[np * 2 + 0][0] = r0; bw[np * 2 + 0][1] = r2;
                bw[np * 2 + 1][0] = r1; bw[np * 2 + 1][1] = r3;
            }
#pragma unroll
            for (int mt = 0; mt < 4; mt++)
#pragma unroll
                for (int nt = 0; nt < 4; nt++)
                    mma16816(acc[mt][nt], ax[mt], bw[nt]);
        }
        __syncthreads();
    }
}

// ===========================================================================
// Fused Q/K/V projection: blockIdx.z selects (X, W, out, scale); fp16 out.
// ===========================================================================
__global__ __launch_bounds__(256, 2) void gemm_proj(
    const __half* __restrict__ xq, const __half* __restrict__ xk,
    const __half* __restrict__ xv,
    const __half* __restrict__ Wq, const __half* __restrict__ Wk,
    const __half* __restrict__ Wv,
    __half* __restrict__ Q, __half* __restrict__ K, __half* __restrict__ V)
{
    extern __shared__ char dynsm[];
    const uint32_t smb = smem_u32(dynsm);
    const int which = blockIdx.z;
    const int bm = blockIdx.y * BM;
    const int bn = blockIdx.x * BN;

    const __half* X = (which == 0) ? xq : (which == 1) ? xk : xv;
    const __half* W = (which == 0) ? Wq : (which == 1) ? Wk : Wv;
    __half* O = (which == 0) ? Q : (which == 1) ? K : V;
    const float scale = (which == 0) ? SCALE_LOG2E : 1.0f;

    float acc[4][4][4];
#pragma unroll
    for (int i = 0; i < 4; i++)
#pragma unroll
        for (int j = 0; j < 4; j++)
#pragma unroll
            for (int t = 0; t < 4; t++) acc[i][j][t] = 0.f;

    gemm_body((const char*)(X + (size_t)bm * KTOT),
              (const char*)(W + (size_t)bn * KTOT), smb, acc);

    const int tid = threadIdx.x;
    const int w = tid >> 5;
    const int wm = w >> 2;
    const int wn = w & 3;
    const int lid = tid & 31;
    const int grp = lid >> 2;
    const int tig = lid & 3;
#pragma unroll
    for (int mt = 0; mt < 4; mt++) {
#pragma unroll
        for (int nt = 0; nt < 4; nt++) {
            int row = bm + wm * 64 + mt * 16 + grp;
            int col = bn + wn * 32 + nt * 8 + tig * 2;
            *(uint32_t*)(O + (size_t)row * E_ + col) =
                pack2h(acc[mt][nt][0] * scale, acc[mt][nt][1] * scale);
            *(uint32_t*)(O + (size_t)(row + 8) * E_ + col) =
                pack2h(acc[mt][nt][2] * scale, acc[mt][nt][3] * scale);
        }
    }
}

// ===========================================================================
// Output projection: C = A @ Wo^T + bias, fp32 out.
// ===========================================================================
__global__ __launch_bounds__(256, 2) void gemm_out(
    const __half* __restrict__ X, const __half* __restrict__ W,
    const float* __restrict__ bias, float* __restrict__ Cf)
{
    extern __shared__ char dynsm[];
    const uint32_t smb = smem_u32(dynsm);
    const int bm = blockIdx.y * BM;
    const int bn = blockIdx.x * BN;

    float acc[4][4][4];
#pragma unroll
    for (int i = 0; i < 4; i++)
#pragma unroll
        for (int j = 0; j < 4; j++)
#pragma unroll
            for (int t = 0; t < 4; t++) acc[i][j][t] = 0.f;

    gemm_body((const char*)(X + (size_t)bm * KTOT),
              (const char*)(W + (size_t)bn * KTOT), smb, acc);

    const int tid = threadIdx.x;
    const int w = tid >> 5;
    const int wm = w >> 2;
    const int wn = w & 3;
    const int lid = tid & 31;
    const int grp = lid >> 2;
    const int tig = lid & 3;
#pragma unroll
    for (int mt = 0; mt < 4; mt++) {
#pragma unroll
        for (int nt = 0; nt < 4; nt++) {
            int row = bm + wm * 64 + mt * 16 + grp;
            int col = bn + wn * 32 + nt * 8 + tig * 2;
            float b0 = bias[col], b1 = bias[col + 1];
            *(float2*)(Cf + (size_t)row * E_ + col) =
                make_float2(acc[mt][nt][0] + b0, acc[mt][nt][1] + b1);
            *(float2*)(Cf + (size_t)(row + 8) * E_ + col) =
                make_float2(acc[mt][nt][2] + b0, acc[mt][nt][3] + b1);
        }
    }
}

// ===========================================================================
// Tensor-core causal flash attention, fp16 single-product.
// q-tile 128 rows (8 warps); S = Q K^T; O = P V; exp2 softmax.
// K/V double-buffered cp.async.
// ===========================================================================
#define ALDT 144                   // smem row stride bytes
#define AQ_TILE (128 * ALDT)       // 18432
#define AKV_TILE (64 * ALDT)       // 9216
#define AOFF_Q 0
#define AOFF_ST AQ_TILE            // 18432
#define ASTAGE (2 * AKV_TILE)      // 18432
#define ASMEM (AOFF_ST + 2 * ASTAGE)  // 55296

__device__ __forceinline__ uint32_t lda(uint32_t base, int r0, int c0) {
    int L = threadIdx.x & 31;
    int mat = L >> 3;
    int r = r0 + (L & 7) + ((mat & 1) << 3);
    int c = c0 + ((mat >> 1) << 3);
    return base + (uint32_t)r * ALDT + c * 2;
}

__global__ __launch_bounds__(256) void attn_mma(
    const __half* __restrict__ Q, const __half* __restrict__ K,
    const __half* __restrict__ V, __half* __restrict__ O)
{
    extern __shared__ char dynsm[];
    const uint32_t smb = smem_u32(dynsm);
    const int tid = threadIdx.x;
    const int w = tid >> 5;
    const int lid = tid & 31;
    const int grp = lid >> 2;
    const int tig = lid & 3;
    const int iblk = (gridDim.x - 1) - blockIdx.x;   // heavy blocks first
    const int h = blockIdx.y;
    const int b = blockIdx.z;
    const int qbase = iblk * 128;
    const int jmax = 2 * iblk + 1;
    const size_t bN = (size_t)b * N_;

    auto issue_stage = [&](int s, int kbase) {
#pragma unroll
        for (int i = 0; i < 4; i++) {
            int sid = tid + 256 * i;          // 0..1023
            int tile = sid >> 9;              // 0 K, 1 V
            int r = (sid >> 3) & 63;
            int seg = sid & 7;
            const __half* gp = tile ? V : K;
            const char* ga = (const char*)(gp + (bN + kbase + r) * E_ + h * 64)
                           + seg * 16;
            cp16(smb + AOFF_ST + (uint32_t)s * ASTAGE + (uint32_t)tile * AKV_TILE
                 + (uint32_t)r * ALDT + seg * 16, ga);
        }
        cp_commit();
    };

    // prologue: Q tile (128 rows x 64 cols) + KV stage 0
    {
#pragma unroll
        for (int i = 0; i < 4; i++) {
            int sid = tid + 256 * i;          // 0..1023
            int r = sid >> 3;
            int seg = sid & 7;
            const char* ga = (const char*)(Q + (bN + qbase + r) * E_ + h * 64)
                           + seg * 16;
            cp16(smb + AOFF_Q + (uint32_t)r * ALDT + seg * 16, ga);
        }
    }
    issue_stage(0, 0);

    uint32_t qq[4][4];
    float o[8][4];
#pragma unroll
    for (int t = 0; t < 8; t++)
#pragma unroll
        for (int c = 0; c < 4; c++) o[t][c] = 0.f;
    float mr0 = -1e30f, mr1 = -1e30f, lr0 = 0.f, lr1 = 0.f;

    for (int j = 0; j <= jmax; j++) {
        cp_wait0();
        __syncthreads();
        if (j == 0) {
#pragma unroll
            for (int kc = 0; kc < 4; kc++)
                ldmx4(qq[kc][0], qq[kc][1], qq[kc][2], qq[kc][3],
                      lda(smb + AOFF_Q, w * 16, kc * 16));
        }
        if (j < jmax) issue_stage((j + 1) & 1, (j + 1) * 64);

        const uint32_t bK = smb + AOFF_ST + (uint32_t)(j & 1) * ASTAGE;
        const uint32_t bV = bK + AKV_TILE;

        // ---- S = Q K^T (hoisted K fragments) ----
        float s[8][4];
#pragma unroll
        for (int t = 0; t < 8; t++)
#pragma unroll
            for (int c = 0; c < 4; c++) s[t][c] = 0.f;
#pragma unroll
        for (int kc = 0; kc < 4; kc++) {
            uint32_t bk[8][2];
#pragma unroll
            for (int np = 0; np < 4; np++) {
                uint32_t r0, r1, r2, r3;
                ldmx4(r0, r1, r2, r3, lda(bK, np * 16, kc * 16));
                bk[np * 2 + 0][0] = r0; bk[np * 2 + 0][1] = r2;
                bk[np * 2 + 1][0] = r1; bk[np * 2 + 1][1] = r3;
            }
#pragma unroll
            for (int t = 0; t < 8; t++) mma16816(s[t], qq[kc], bk[t]);
        }

        // ---- causal mask (only kv-blocks crossing the diagonal) ----
        if (j >= 2 * iblk) {
            const int row0 = qbase + w * 16 + grp;
            const int row1 = row0 + 8;
            const int cb = j * 64;
#pragma unroll
            for (int t = 0; t < 8; t++) {
                int col = cb + t * 8 + 2 * tig;
                if (col > row0) s[t][0] = -1e30f;
                if (col + 1 > row0) s[t][1] = -1e30f;
                if (col > row1) s[t][2] = -1e30f;
                if (col + 1 > row1) s[t][3] = -1e30f;
            }
        }

        // ---- online softmax (base-2) ----
        float m0 = -1e30f, m1 = -1e30f;
#pragma unroll
        for (int t = 0; t < 8; t++) {
            m0 = fmaxf(m0, fmaxf(s[t][0], s[t][1]));
            m1 = fmaxf(m1, fmaxf(s[t][2], s[t][3]));
        }
        m0 = fmaxf(m0, __shfl_xor_sync(0xffffffffu, m0, 1));
        m0 = fmaxf(m0, __shfl_xor_sync(0xffffffffu, m0, 2));
        m1 = fmaxf(m1, __shfl_xor_sync(0xffffffffu, m1, 1));
        m1 = fmaxf(m1, __shfl_xor_sync(0xffffffffu, m1, 2));
        float mn0 = fmaxf(mr0, m0), mn1 = fmaxf(mr1, m1);
        float a0 = exp2f(mr0 - mn0), a1 = exp2f(mr1 - mn1);
        mr0 = mn0; mr1 = mn1;
        float sum0 = 0.f, sum1 = 0.f;
#pragma unroll
        for (int t = 0; t < 8; t++) {
            s[t][0] = exp2f(s[t][0] - mn0);
            s[t][1] = exp2f(s[t][1] - mn0);
            s[t][2] = exp2f(s[t][2] - mn1);
            s[t][3] = exp2f(s[t][3] - mn1);
            sum0 += s[t][0] + s[t][1];
            sum1 += s[t][2] + s[t][3];
        }
        sum0 += __shfl_xor_sync(0xffffffffu, sum0, 1);
        sum0 += __shfl_xor_sync(0xffffffffu, sum0, 2);
        sum1 += __shfl_xor_sync(0xffffffffu, sum1, 1);
        sum1 += __shfl_xor_sync(0xffffffffu, sum1, 2);
        lr0 = lr0 * a0 + sum0;
        lr1 = lr1 * a1 + sum1;
#pragma unroll
        for (int t = 0; t < 8; t++) {
            o[t][0] *= a0; o[t][1] *= a0;
            o[t][2] *= a1; o[t][3] *= a1;
        }

        // ---- P: C-frag -> A-frag, single fp16 ----
        uint32_t ph[4][4];
#pragma unroll
        for (int kc = 0; kc < 4; kc++) {
            ph[kc][0] = pack2h(s[2 * kc][0], s[2 * kc][1]);
            ph[kc][1] = pack2h(s[2 * kc][2], s[2 * kc][3]);
            ph[kc][2] = pack2h(s[2 * kc + 1][0], s[2 * kc + 1][1]);
            ph[kc][3] = pack2h(s[2 * kc + 1][2], s[2 * kc + 1][3]);
        }

        // ---- O += P V (hoisted V fragments) ----
#pragma unroll
        for (int kc = 0; kc < 4; kc++) {
            uint32_t vv[8][2];
#pragma unroll
            for (int nd = 0; nd < 4; nd++) {
                uint32_t r0, r1, r2, r3;
                ldmx4t(r0, r1, r2, r3, lda(bV, kc * 16, nd * 16));
                vv[nd * 2 + 0][0] = r0; vv[nd * 2 + 0][1] = r1;
                vv[nd * 2 + 1][0] = r2; vv[nd * 2 + 1][1] = r3;
            }
#pragma unroll
            for (int t = 0; t < 8; t++) mma16816(o[t], ph[kc], vv[t]);
        }
    }

    // ---- epilogue: normalize, single fp16, store [B,N,E] ----
    const float i0 = 1.f / lr0, i1 = 1.f / lr1;
    const int qr0 = qbase + w * 16 + grp;
    const size_t ro0 = (bN + qr0) * E_;
    const size_t ro1 = (bN + qr0 + 8) * E_;
#pragma unroll
    for (int t = 0; t < 8; t++) {
        int col = h * 64 + t * 8 + 2 * tig;
        *(uint32_t*)(O + ro0 + col) = pack2h(o[t][0] * i0, o[t][1] * i0);
        *(uint32_t*)(O + ro1 + col) = pack2h(o[t][2] * i1, o[t][3] * i1);
    }
}

// ---------------------------------------------------------------------------
extern "C" void kernel_launch(void* const* d_in, const int* in_sizes, int n_in,
                              void* d_out, int out_size)
{
    const float* xq = (const float*)d_in[0];
    const float* xk = (const float*)d_in[1];
    const float* xv = (const float*)d_in[2];
    // d_in[3] = attn_mask (causal, recomputed analytically) — unused
    const float* Wq = (const float*)d_in[4];
    const float* Wk = (const float*)d_in[5];
    const float* Wv = (const float*)d_in[6];
    const float* Wo = (const float*)d_in[7];
    const float* bo = (const float*)d_in[8];
    float* out = (float*)d_out;

    __half *xqp, *xkp, *xvp;
    __half *Qb, *Kb, *Vb, *Ab;
    __half *Wqh, *Wkh, *Wvh, *Woh;
    cudaGetSymbolAddress((void**)&xqp, g_xq);
    cudaGetSymbolAddress((void**)&xkp, g_xk);
    cudaGetSymbolAddress((void**)&xvp, g_xv);
    cudaGetSymbolAddress((void**)&Qb, g_Q);
    cudaGetSymbolAddress((void**)&Kb, g_K);
    cudaGetSymbolAddress((void**)&Vb, g_V);
    cudaGetSymbolAddress((void**)&Ab, g_A);
    cudaGetSymbolAddress((void**)&Wqh, g_Wq);
    cudaGetSymbolAddress((void**)&Wkh, g_Wk);
    cudaGetSymbolAddress((void**)&Wvh, g_Wv);
    cudaGetSymbolAddress((void**)&Woh, g_Wo);

    cudaFuncSetAttribute(gemm_proj, cudaFuncAttributeMaxDynamicSharedMemorySize,
                         GSMEM1_SZ);
    cudaFuncSetAttribute(gemm_out, cudaFuncAttributeMaxDynamicSharedMemorySize,
                         GSMEM1_SZ);
    cudaFuncSetAttribute(attn_mma, cudaFuncAttributeMaxDynamicSharedMemorySize,
                         ASMEM);

    // Prepass conversions (fused: 2 launches)
    const int nx4 = MTOT * E_ / 4;
    const int nw4 = E_ * E_ / 4;
    dim3 cx(nx4 / 256, 3);
    convert_h3<<<cx, 256>>>(xq, xk, xv, xqp, xkp, xvp, nx4);
    dim3 cw(nw4 / 256, 4);
    convert_h4<<<cw, 256>>>(Wq, Wk, Wv, Wo, Wqh, Wkh, Wvh, Woh, nw4);

    // Fused Q/K/V projections (one launch, z selects which)
    dim3 gblock(256);
    dim3 pgrid(E_ / BN, MTOT / BM, 3);     // (8, 64, 3)
    gemm_proj<<<pgrid, gblock, GSMEM1_SZ>>>(xqp, xkp, xvp, Wqh, Wkh, Wvh,
                                            Qb, Kb, Vb);

    dim3 agrid(N_ / 128, H_, B_);          // (16, 16, 4)
    attn_mma<<<agrid, 256, ASMEM>>>(Qb, Kb, Vb, Ab);

    // Output projection -> fp32 + bias
    dim3 ogrid(E_ / BN, MTOT / BM);        // (8, 64)
    gemm_out<<<ogrid, gblock, GSMEM1_SZ>>>(Ab, Woh, bo, out);
}